// round 9
// baseline (speedup 1.0000x reference)
#include <cuda_runtime.h>
#include <cuda_bf16.h>
#include <cuda_fp16.h>
#include <math.h>
#include <stdint.h>

#define NNODES 100000
#define NEDGES 1600000
#define FIN 256
#define HID 128
#define COUT 64

#define H0ROWS 50048                 // 391 * 128, first half (H0); rest = H1

#define SCAN_TPB 256
#define SCAN_ELEMS 8
#define SCAN_CHUNK (SCAN_TPB * SCAN_ELEMS)                 // 2048
#define SCAN_NB ((NNODES + SCAN_CHUNK - 1) / SCAN_CHUNK)   // 49

// ---------------- scratch (static __device__, no allocation) ----------------
__device__ __half g_tmpA[NNODES * HID];         // messages, even layers
__device__ __half g_tmpB[NNODES * HID];         // messages, odd layers
__device__ __nv_bfloat16 g_ah[NNODES * HID];    // relu'd h, hi split (GEMM input)
__device__ __nv_bfloat16 g_al[NNODES * HID];    // relu'd h, lo split
__device__ __nv_bfloat16 g_ph[NNODES * HID];    // pre-relu h2, hi split (gram)
__device__ __nv_bfloat16 g_pl[NNODES * HID];    // pre-relu h2, lo split
__device__ float g_dinv[NNODES];
__device__ int   g_cnt[NNODES];
__device__ int   g_cursor[NNODES];
__device__ int   g_rowptr[NNODES + 1];
__device__ int   g_col[NEDGES];
__device__ float g_w[NEDGES];
__device__ float g_G[HID * HID];
__device__ float g_csum[HID];
__device__ int   g_bsum[SCAN_NB];

// split-bf16 transposed weights: Wt[d][k] = W[k][d]
__device__ __nv_bfloat16 g_w0h[HID * FIN],  g_w0l[HID * FIN];
__device__ __nv_bfloat16 g_w1h[HID * HID],  g_w1l[HID * HID];
__device__ __nv_bfloat16 g_w2h[HID * HID],  g_w2l[HID * HID];
__device__ __nv_bfloat16 g_w3h[COUT * HID], g_w3l[COUT * HID];

// ---------------- helpers ----------------
__device__ __forceinline__ uint32_t smem_u32(const void* p) {
    uint32_t a;
    asm("{ .reg .u64 t; cvta.to.shared.u64 t, %1; cvt.u32.u64 %0, t; }"
        : "=r"(a) : "l"(p));
    return a;
}
__device__ __forceinline__ uint32_t sw128(uint32_t off) {
    return off ^ ((off >> 3) & 0x70);
}
__device__ __forceinline__ void ldsm4(uint32_t* r, uint32_t addr) {
    asm volatile("ldmatrix.sync.aligned.m8n8.x4.shared.b16 {%0,%1,%2,%3}, [%4];"
                 : "=r"(r[0]), "=r"(r[1]), "=r"(r[2]), "=r"(r[3]) : "r"(addr));
}
__device__ __forceinline__ void mma16816(float* c, const uint32_t* a,
                                         const uint32_t* b) {
    asm volatile(
        "mma.sync.aligned.m16n8k16.row.col.f32.bf16.bf16.f32 "
        "{%0,%1,%2,%3}, {%4,%5,%6,%7}, {%8,%9}, {%0,%1,%2,%3};"
        : "+f"(c[0]), "+f"(c[1]), "+f"(c[2]), "+f"(c[3])
        : "r"(a[0]), "r"(a[1]), "r"(a[2]), "r"(a[3]), "r"(b[0]), "r"(b[1]));
}
__device__ __forceinline__ void split2(float f, __nv_bfloat16& h, __nv_bfloat16& l) {
    h = __float2bfloat16_rn(f);
    l = __float2bfloat16_rn(f - __bfloat162float(h));
}
__device__ __forceinline__ void cpa16(uint32_t dst, const void* src, int nbytes) {
    asm volatile("cp.async.cg.shared.global [%0], [%1], 16, %2;"
                 :: "r"(dst), "l"(src), "r"(nbytes) : "memory");
}
__device__ __forceinline__ void cpa_commit() {
    asm volatile("cp.async.commit_group;" ::: "memory");
}
__device__ __forceinline__ void cpa_wait1() {
    asm volatile("cp.async.wait_group 1;" ::: "memory");
}
__device__ __forceinline__ void cpa_wait0() {
    asm volatile("cp.async.wait_group 0;" ::: "memory");
}

// ---------------- preprocessing ----------------
__global__ void k_zero_init() {
    int i = blockIdx.x * blockDim.x + threadIdx.x;
    if (i < NNODES) { g_cnt[i] = 0; g_cursor[i] = 0; }
}

__global__ void k_zero_G() {
    int i = blockIdx.x * blockDim.x + threadIdx.x;
    if (i < HID * HID) g_G[i] = 0.f;
    if (i < HID) g_csum[i] = 0.f;
}

__global__ void k_count(const int* __restrict__ ei) {
    int e = blockIdx.x * blockDim.x + threadIdx.x;
    if (e < NEDGES) atomicAdd(&g_cnt[ei[e]], 1);
}

// scan pass 1 (also computes dinv)
__global__ void k_scan1() {
    __shared__ int warp_s[SCAN_TPB / 32];
    int tid = threadIdx.x, blk = blockIdx.x;
    int base = blk * SCAN_CHUNK + tid * SCAN_ELEMS;
    int s = 0;
#pragma unroll
    for (int i = 0; i < SCAN_ELEMS; i++) {
        int idx = base + i;
        if (idx < NNODES) {
            int c = g_cnt[idx];
            s += c;
            g_dinv[idx] = rsqrtf((float)(c + 1));  // +1 self loop
        }
    }
    for (int o = 16; o > 0; o >>= 1) s += __shfl_down_sync(0xffffffffu, s, o);
    if ((tid & 31) == 0) warp_s[tid >> 5] = s;
    __syncthreads();
    if (tid < SCAN_TPB / 32) {
        int w = warp_s[tid];
        for (int o = (SCAN_TPB / 64); o > 0; o >>= 1)
            w += __shfl_down_sync(0xffu, w, o);
        if (tid == 0) g_bsum[blk] = w;
    }
}

__global__ void k_scan2() {
    __shared__ int sh[64];
    int tid = threadIdx.x;
    sh[tid] = (tid < SCAN_NB) ? g_bsum[tid] : 0;
    __syncthreads();
    for (int o = 1; o < 64; o <<= 1) {
        int v = (tid >= o) ? sh[tid - o] : 0;
        __syncthreads();
        sh[tid] += v;
        __syncthreads();
    }
    if (tid < SCAN_NB) g_bsum[tid] = (tid == 0) ? 0 : sh[tid - 1];
    if (tid == 0) g_rowptr[NNODES] = sh[SCAN_NB - 1];
}

__global__ void k_scan3() {
    __shared__ int tsum[SCAN_TPB];
    int tid = threadIdx.x, blk = blockIdx.x;
    int base = blk * SCAN_CHUNK + tid * SCAN_ELEMS;
    int c[SCAN_ELEMS];
    int s = 0;
#pragma unroll
    for (int i = 0; i < SCAN_ELEMS; i++) {
        int idx = base + i;
        c[i] = (idx < NNODES) ? g_cnt[idx] : 0;
        s += c[i];
    }
    tsum[tid] = s;
    __syncthreads();
    for (int o = 1; o < SCAN_TPB; o <<= 1) {
        int v = (tid >= o) ? tsum[tid - o] : 0;
        __syncthreads();
        tsum[tid] += v;
        __syncthreads();
    }
    int run = g_bsum[blk] + ((tid == 0) ? 0 : tsum[tid - 1]);
#pragma unroll
    for (int i = 0; i < SCAN_ELEMS; i++) {
        int idx = base + i;
        if (idx < NNODES) { g_rowptr[idx] = run; run += c[i]; }
    }
}

__global__ void k_fill(const int* __restrict__ ei) {
    int e = blockIdx.x * blockDim.x + threadIdx.x;
    if (e >= NEDGES) return;
    int r = ei[e];
    int c = ei[NEDGES + e];
    int pos = g_rowptr[r] + atomicAdd(&g_cursor[r], 1);
    g_col[pos] = c;
    g_w[pos] = g_dinv[r] * g_dinv[c];
}

// ---------------- weight prep ----------------
template <int K, int D>
__global__ void k_prepW(const float* __restrict__ W,
                        __nv_bfloat16* __restrict__ Wh,
                        __nv_bfloat16* __restrict__ Wl) {
    int i = blockIdx.x * blockDim.x + threadIdx.x;
    if (i >= K * D) return;
    int n = i / K, k = i % K;
    float v = W[k * D + n];
    __nv_bfloat16 h, l;
    split2(v, h, l);
    Wh[n * K + k] = h;
    Wl[n * K + k] = l;
}

__global__ void k_prepW3x(const float* __restrict__ W1,
                          const float* __restrict__ W2,
                          const float* __restrict__ W3) {
    int i = blockIdx.x * blockDim.x + threadIdx.x;
    const int S1 = HID * HID, S2 = 2 * HID * HID, S3 = 2 * HID * HID + HID * COUT;
    __nv_bfloat16 h, l;
    if (i < S1) {
        int n = i / HID, k = i % HID;
        split2(W1[k * HID + n], h, l);
        g_w1h[n * HID + k] = h; g_w1l[n * HID + k] = l;
    } else if (i < S2) {
        int j = i - S1;
        int n = j / HID, k = j % HID;
        split2(W2[k * HID + n], h, l);
        g_w2h[n * HID + k] = h; g_w2l[n * HID + k] = l;
    } else if (i < S3) {
        int j = i - S2;
        int n = j / HID, k = j % HID;
        split2(W3[k * COUT + n], h, l);
        g_w3h[n * HID + k] = h; g_w3l[n * HID + k] = l;
    }
}

// ---------------- pipelined tensor-core split-bf16 GEMM --------------------
// rowbase: first row handled by blockIdx 0 (for split-half launches)
template <int K, int D, bool CONVERT>
__global__ __launch_bounds__(512) void k_tgemm512(const float* __restrict__ Af,
                                                  const __nv_bfloat16* __restrict__ Ah,
                                                  const __nv_bfloat16* __restrict__ Al,
                                                  const __nv_bfloat16* __restrict__ Bh,
                                                  const __nv_bfloat16* __restrict__ Bl,
                                                  __half* __restrict__ C,
                                                  int rowbase) {
    extern __shared__ __align__(1024) uint8_t smem[];
    const int CK = 64;
    const int NCH = K / CK;
    const int WN = D / 4;
    const int NT = WN / 8;
    const int STA = 128 * 128;
    const int SBB = D * 128;
    const int OFF_B = 4 * STA;

    uint32_t sb = smem_u32(smem);
    int tid = threadIdx.x, wid = tid >> 5, lane = tid & 31;
    int wm = wid & 3, wn = wid >> 2;
    int row0 = wm * 32;
    int col0 = wn * WN;
    int grow = rowbase + blockIdx.x * 128;

    float acc[2][NT][4];
#pragma unroll
    for (int i = 0; i < 2; i++)
#pragma unroll
        for (int j = 0; j < NT; j++)
#pragma unroll
            for (int q = 0; q < 4; q++) acc[i][j][q] = 0.f;

    float4 pf[4];

    auto a_async = [&](int s, int ch) {
        int kk = ch * CK;
#pragma unroll
        for (int i = 0; i < 2; i++) {
            int u = tid + i * 512;
            int m = u >> 3, g = u & 7;
            int r = grow + m;
            int rc = (r < NNODES) ? r : 0;
            int nb = (r < NNODES) ? 16 : 0;
            uint32_t so = sw128((uint32_t)(m * 128 + g * 16));
            cpa16(sb + (2 * s) * STA + so, &Ah[(size_t)rc * K + kk + g * 8], nb);
            cpa16(sb + (2 * s + 1) * STA + so, &Al[(size_t)rc * K + kk + g * 8], nb);
        }
    };
    auto b_async = [&](int s, int ch) {
        int kk = ch * CK;
#pragma unroll
        for (int i = 0; i < (D * 8 + 511) / 512; i++) {
            int u = tid + i * 512;
            if (u < D * 8) {
                int n = u >> 3, g = u & 7;
                uint32_t so = sw128((uint32_t)(n * 128 + g * 16));
                cpa16(sb + OFF_B + (2 * s) * SBB + so, &Bh[n * K + kk + g * 8], 16);
                cpa16(sb + OFF_B + (2 * s + 1) * SBB + so, &Bl[n * K + kk + g * 8], 16);
            }
        }
    };
    auto a_ldregs = [&](int ch) {
        int kk = ch * CK;
#pragma unroll
        for (int i = 0; i < 2; i++) {
            int u = tid + i * 512;
            int m = u >> 3, g = u & 7;
            int r = grow + m;
            pf[2 * i] = make_float4(0.f, 0.f, 0.f, 0.f);
            pf[2 * i + 1] = pf[2 * i];
            if (r < NNODES) {
                const float* p = &Af[(size_t)r * K + kk + g * 8];
                pf[2 * i] = *(const float4*)p;
                pf[2 * i + 1] = *(const float4*)(p + 4);
            }
        }
    };
    auto a_cvtsts = [&](int s) {
#pragma unroll
        for (int i = 0; i < 2; i++) {
            int u = tid + i * 512;
            int m = u >> 3, g = u & 7;
            float f[8] = {pf[2 * i].x, pf[2 * i].y, pf[2 * i].z, pf[2 * i].w,
                          pf[2 * i + 1].x, pf[2 * i + 1].y, pf[2 * i + 1].z, pf[2 * i + 1].w};
            uint32_t hp[4], lp[4];
#pragma unroll
            for (int j = 0; j < 4; j++) {
                __nv_bfloat16 h0, l0, h1, l1;
                split2(f[2 * j], h0, l0);
                split2(f[2 * j + 1], h1, l1);
                hp[j] = (uint32_t)__bfloat16_as_ushort(h0)
                      | ((uint32_t)__bfloat16_as_ushort(h1) << 16);
                lp[j] = (uint32_t)__bfloat16_as_ushort(l0)
                      | ((uint32_t)__bfloat16_as_ushort(l1) << 16);
            }
            uint32_t so = sw128((uint32_t)(m * 128 + g * 16));
            *(uint4*)(smem + (2 * s) * STA + so) = make_uint4(hp[0], hp[1], hp[2], hp[3]);
            *(uint4*)(smem + (2 * s + 1) * STA + so) = make_uint4(lp[0], lp[1], lp[2], lp[3]);
        }
    };

    if (CONVERT) { a_ldregs(0); a_cvtsts(0); }
    else a_async(0, 0);
    b_async(0, 0);
    cpa_commit();

    for (int ch = 0; ch < NCH; ch++) {
        int cur = ch & 1, nxt = cur ^ 1;
        bool more = (ch + 1 < NCH);
        if (more) {
            if (CONVERT) a_ldregs(ch + 1);
            else a_async(nxt, ch + 1);
            b_async(nxt, ch + 1);
            cpa_commit();
        }
        if (more) cpa_wait1(); else cpa_wait0();
        __syncthreads();
        {
            uint32_t aB0 = sb + (2 * cur) * STA;
            uint32_t aB1 = sb + (2 * cur + 1) * STA;
            uint32_t bB0 = sb + OFF_B + (2 * cur) * SBB;
            uint32_t bB1 = sb + OFF_B + (2 * cur + 1) * SBB;
#pragma unroll
            for (int k16 = 0; k16 < CK / 16; k16++) {
                int kb = k16 * 32;
                uint32_t ah[2][4], al[2][4];
#pragma unroll
                for (int mt = 0; mt < 2; mt++) {
                    int r = row0 + mt * 16 + (lane & 15);
                    int cb = kb + ((lane & 16) ? 16 : 0);
                    uint32_t so = sw128((uint32_t)(r * 128 + cb));
                    ldsm4(ah[mt], aB0 + so);
                    ldsm4(al[mt], aB1 + so);
                }
#pragma unroll
                for (int bt = 0; bt < NT / 2; bt++) {
                    int n = col0 + bt * 16 + (lane & 7) + ((lane & 16) ? 8 : 0);
                    int cb = kb + ((lane & 8) ? 16 : 0);
                    uint32_t so = sw128((uint32_t)(n * 128 + cb));
                    uint32_t bh[4], bl[4];
                    ldsm4(bh, bB0 + so);
                    ldsm4(bl, bB1 + so);
#pragma unroll
                    for (int h = 0; h < 2; h++) {
                        int nt = bt * 2 + h;
#pragma unroll
                        for (int mt = 0; mt < 2; mt++) {
                            mma16816(acc[mt][nt], ah[mt], &bh[h * 2]);
                            mma16816(acc[mt][nt], ah[mt], &bl[h * 2]);
                            mma16816(acc[mt][nt], al[mt], &bh[h * 2]);
                        }
                    }
                }
            }
        }
        if (more && CONVERT) a_cvtsts(nxt);
        __syncthreads();
    }

#pragma unroll
    for (int mt = 0; mt < 2; mt++) {
        int r0 = grow + row0 + mt * 16 + (lane >> 2);
        int r1 = r0 + 8;
#pragma unroll
        for (int nt = 0; nt < NT; nt++) {
            int cc = col0 + nt * 8 + (lane & 3) * 2;
            if (r0 < NNODES)
                *(__half2*)&C[(size_t)r0 * D + cc] =
                    __floats2half2_rn(acc[mt][nt][0], acc[mt][nt][1]);
            if (r1 < NNODES)
                *(__half2*)&C[(size_t)r1 * D + cc] =
                    __floats2half2_rn(acc[mt][nt][2], acc[mt][nt][3]);
        }
    }
}

// ---------------- sparse aggregation (fp16 gather, fp32 accumulate) --------
// processes nodes [base, limit)
template <bool PRE>
__global__ void k_agg128s(const __half* __restrict__ tmp,
                          __nv_bfloat16* __restrict__ ah,
                          __nv_bfloat16* __restrict__ al,
                          __nv_bfloat16* __restrict__ ph,
                          __nv_bfloat16* __restrict__ pl,
                          int base, int limit) {
    int gw = base + ((blockIdx.x * blockDim.x + threadIdx.x) >> 5);
    int lane = threadIdx.x & 31;
    if (gw >= limit) return;
    const uint2* __restrict__ t = (const uint2*)tmp;
    float di = g_dinv[gw];
    float s = di * di;
    uint2 u = t[gw * 32 + lane];
    float2 p0 = __half22float2(*(__half2*)&u.x);
    float2 p1 = __half22float2(*(__half2*)&u.y);
    float4 acc = make_float4(p0.x * s, p0.y * s, p1.x * s, p1.y * s);
    float4 acc2 = make_float4(0.f, 0.f, 0.f, 0.f);
    int e = g_rowptr[gw], en = g_rowptr[gw + 1];
    for (; e + 3 < en; e += 4) {
        int c0 = g_col[e], c1 = g_col[e + 1], c2 = g_col[e + 2], c3 = g_col[e + 3];
        float w0 = g_w[e], w1 = g_w[e + 1], w2 = g_w[e + 2], w3 = g_w[e + 3];
        uint2 a = t[c0 * 32 + lane];
        uint2 b = t[c1 * 32 + lane];
        uint2 cc = t[c2 * 32 + lane];
        uint2 d = t[c3 * 32 + lane];
        float2 a0 = __half22float2(*(__half2*)&a.x), a1 = __half22float2(*(__half2*)&a.y);
        float2 b0 = __half22float2(*(__half2*)&b.x), b1 = __half22float2(*(__half2*)&b.y);
        float2 c0f = __half22float2(*(__half2*)&cc.x), c1f = __half22float2(*(__half2*)&cc.y);
        float2 d0 = __half22float2(*(__half2*)&d.x), d1 = __half22float2(*(__half2*)&d.y);
        acc.x = fmaf(w0, a0.x, acc.x);   acc.y = fmaf(w0, a0.y, acc.y);
        acc.z = fmaf(w0, a1.x, acc.z);   acc.w = fmaf(w0, a1.y, acc.w);
        acc2.x = fmaf(w1, b0.x, acc2.x); acc2.y = fmaf(w1, b0.y, acc2.y);
        acc2.z = fmaf(w1, b1.x, acc2.z); acc2.w = fmaf(w1, b1.y, acc2.w);
        acc.x = fmaf(w2, c0f.x, acc.x);  acc.y = fmaf(w2, c0f.y, acc.y);
        acc.z = fmaf(w2, c1f.x, acc.z);  acc.w = fmaf(w2, c1f.y, acc.w);
        acc2.x = fmaf(w3, d0.x, acc2.x); acc2.y = fmaf(w3, d0.y, acc2.y);
        acc2.z = fmaf(w3, d1.x, acc2.z); acc2.w = fmaf(w3, d1.y, acc2.w);
    }
    for (; e < en; e++) {
        int c0 = g_col[e];
        float w0 = g_w[e];
        uint2 a = t[c0 * 32 + lane];
        float2 a0 = __half22float2(*(__half2*)&a.x);
        float2 a1 = __half22float2(*(__half2*)&a.y);
        acc.x = fmaf(w0, a0.x, acc.x); acc.y = fmaf(w0, a0.y, acc.y);
        acc.z = fmaf(w0, a1.x, acc.z); acc.w = fmaf(w0, a1.y, acc.w);
    }
    acc.x += acc2.x; acc.y += acc2.y; acc.z += acc2.z; acc.w += acc2.w;

    float f[4] = {acc.x, acc.y, acc.z, acc.w};
    size_t bidx = (size_t)gw * HID + lane * 4;
    if (PRE) {
        ushort hh[4], ll[4];
#pragma unroll
        for (int j = 0; j < 4; j++) {
            __nv_bfloat16 h, l;
            split2(f[j], h, l);
            hh[j] = __bfloat16_as_ushort(h);
            ll[j] = __bfloat16_as_ushort(l);
        }
        *(uint2*)&ph[bidx] = make_uint2((uint32_t)hh[0] | ((uint32_t)hh[1] << 16),
                                        (uint32_t)hh[2] | ((uint32_t)hh[3] << 16));
        *(uint2*)&pl[bidx] = make_uint2((uint32_t)ll[0] | ((uint32_t)ll[1] << 16),
                                        (uint32_t)ll[2] | ((uint32_t)ll[3] << 16));
    }
    ushort rh[4], rl[4];
#pragma unroll
    for (int j = 0; j < 4; j++) {
        float v = fmaxf(f[j], 0.f);
        __nv_bfloat16 h, l;
        split2(v, h, l);
        rh[j] = __bfloat16_as_ushort(h);
        rl[j] = __bfloat16_as_ushort(l);
    }
    *(uint2*)&ah[bidx] = make_uint2((uint32_t)rh[0] | ((uint32_t)rh[1] << 16),
                                    (uint32_t)rh[2] | ((uint32_t)rh[3] << 16));
    *(uint2*)&al[bidx] = make_uint2((uint32_t)rl[0] | ((uint32_t)rl[1] << 16),
                                    (uint32_t)rl[2] | ((uint32_t)rl[3] << 16));
}

__global__ void k_agg64h(const __half* __restrict__ tmp, float* __restrict__ out) {
    int gw = (blockIdx.x * blockDim.x + threadIdx.x) >> 5;
    int lane = threadIdx.x & 31;
    if (gw >= NNODES) return;
    const uint32_t* __restrict__ t = (const uint32_t*)tmp;
    float di = g_dinv[gw];
    float s = di * di;
    uint32_t u = t[gw * 32 + lane];
    float2 p = __half22float2(*(__half2*)&u);
    float2 acc = make_float2(p.x * s, p.y * s);
    float2 acc2 = make_float2(0.f, 0.f);
    int e = g_rowptr[gw], en = g_rowptr[gw + 1];
    for (; e + 3 < en; e += 4) {
        int c0 = g_col[e], c1 = g_col[e + 1], c2 = g_col[e + 2], c3 = g_col[e + 3];
        float w0 = g_w[e], w1 = g_w[e + 1], w2 = g_w[e + 2], w3 = g_w[e + 3];
        uint32_t a = t[c0 * 32 + lane];
        uint32_t b = t[c1 * 32 + lane];
        uint32_t c = t[c2 * 32 + lane];
        uint32_t d = t[c3 * 32 + lane];
        float2 af = __half22float2(*(__half2*)&a);
        float2 bf = __half22float2(*(__half2*)&b);
        float2 cf = __half22float2(*(__half2*)&c);
        float2 df = __half22float2(*(__half2*)&d);
        acc.x = fmaf(w0, af.x, acc.x);   acc.y = fmaf(w0, af.y, acc.y);
        acc2.x = fmaf(w1, bf.x, acc2.x); acc2.y = fmaf(w1, bf.y, acc2.y);
        acc.x = fmaf(w2, cf.x, acc.x);   acc.y = fmaf(w2, cf.y, acc.y);
        acc2.x = fmaf(w3, df.x, acc2.x); acc2.y = fmaf(w3, df.y, acc2.y);
    }
    for (; e < en; e++) {
        int c0 = g_col[e];
        float w0 = g_w[e];
        uint32_t a = t[c0 * 32 + lane];
        float2 af = __half22float2(*(__half2*)&a);
        acc.x = fmaf(w0, af.x, acc.x); acc.y = fmaf(w0, af.y, acc.y);
    }
    acc.x += acc2.x; acc.y += acc2.y;
    ((float2*)out)[gw * 32 + lane] = acc;
}

// ---------------- Gram via mma from pre-split bf16 h2 (D=128) ---------------
__global__ __launch_bounds__(256) void k_gram_split(const __nv_bfloat16* __restrict__ ph,
                                                    const __nv_bfloat16* __restrict__ pl) {
    const int D = HID;
    __shared__ __align__(1024) uint8_t sm[2 * D * 128];
    const int OFF_L = D * 128;
    const int FG = D / 4;
    const int PAIRS = 256 / FG;
    const int NT = D / 8;
    const int MW = D / 16;
    uint32_t sb = smem_u32(sm);
    int tid = threadIdx.x, wid = tid >> 5, lane = tid & 31;
    int f4 = tid % FG;
    int rp0 = tid / FG;

    float acc[NT][4];
#pragma unroll
    for (int j = 0; j < NT; j++)
#pragma unroll
        for (int q = 0; q < 4; q++) acc[j][q] = 0.f;
    float cs0 = 0.f, cs1 = 0.f, cs2 = 0.f, cs3 = 0.f;

    const int NCHUNK = (NNODES + 63) / 64;
    for (int ch = blockIdx.x; ch < NCHUNK; ch += gridDim.x) {
        int rbase = ch * 64;
#pragma unroll
        for (int it = 0; it < 32 / PAIRS; it++) {
            int pr = rp0 + it * PAIRS;
            int r0 = rbase + pr * 2, r1 = r0 + 1;
            uint2 h0v = make_uint2(0, 0), h1v = h0v, l0v = h0v, l1v = h0v;
            if (r0 < NNODES) {
                h0v = *(const uint2*)&ph[(size_t)r0 * D + f4 * 4];
                l0v = *(const uint2*)&pl[(size_t)r0 * D + f4 * 4];
            }
            if (r1 < NNODES) {
                h1v = *(const uint2*)&ph[(size_t)r1 * D + f4 * 4];
                l1v = *(const uint2*)&pl[(size_t)r1 * D + f4 * 4];
            }
            const ushort* h0s = (const ushort*)&h0v;
            const ushort* h1s = (const ushort*)&h1v;
            const ushort* l0s = (const ushort*)&l0v;
            const ushort* l1s = (const ushort*)&l1v;
            float fs[4];
#pragma unroll
            for (int j = 0; j < 4; j++) {
                fs[j] = __bfloat162float(__ushort_as_bfloat16(h0s[j]))
                      + __bfloat162float(__ushort_as_bfloat16(l0s[j]))
                      + __bfloat162float(__ushort_as_bfloat16(h1s[j]))
                      + __bfloat162float(__ushort_as_bfloat16(l1s[j]));
                int feat = f4 * 4 + j;
                uint32_t hp = (uint32_t)h0s[j] | ((uint32_t)h1s[j] << 16);
                uint32_t lp = (uint32_t)l0s[j] | ((uint32_t)l1s[j] << 16);
                uint32_t so = sw128((uint32_t)(feat * 128 + pr * 4));
                *(uint32_t*)(sm + so) = hp;
                *(uint32_t*)(sm + OFF_L + so) = lp;
            }
            cs0 += fs[0]; cs1 += fs[1]; cs2 += fs[2]; cs3 += fs[3];
        }
        __syncthreads();
        if (wid < MW) {
#pragma unroll
            for (int k16 = 0; k16 < 4; k16++) {
                int kb = k16 * 32;
                uint32_t ah[4], al[4];
                {
                    int r = wid * 16 + (lane & 15);
                    int cb = kb + ((lane & 16) ? 16 : 0);
                    uint32_t so = sw128((uint32_t)(r * 128 + cb));
                    ldsm4(ah, sb + so);
                    ldsm4(al, sb + OFF_L + so);
                }
#pragma unroll
                for (int bt = 0; bt < NT / 2; bt++) {
                    int n = bt * 16 + (lane & 7) + ((lane & 16) ? 8 : 0);
                    int cb = kb + ((lane & 8) ? 16 : 0);
                    uint32_t so = sw128((uint32_t)(n * 128 + cb));
                    uint32_t bh[4], bl[4];
                    ldsm4(bh, sb + so);
                    ldsm4(bl, sb + OFF_L + so);
#pragma unroll
                    for (int hh = 0; hh < 2; hh++) {
                        int nt = bt * 2 + hh;
                        mma16816(acc[nt], ah, &bh[hh * 2]);
                        mma16816(acc[nt], ah, &bl[hh * 2]);
                        mma16816(acc[nt], al, &bh[hh * 2]);
                    }
                }
            }
        }
        __syncthreads();
    }
    if (wid < MW) {
        int mrow = wid * 16 + (lane >> 2);
#pragma unroll
        for (int nt = 0; nt < NT; nt++) {
            int c = nt * 8 + (lane & 3) * 2;
            atomicAdd(&g_G[mrow * D + c], acc[nt][0]);
            atomicAdd(&g_G[mrow * D + c + 1], acc[nt][1]);
            atomicAdd(&g_G[(mrow + 8) * D + c], acc[nt][2]);
            atomicAdd(&g_G[(mrow + 8) * D + c + 1], acc[nt][3]);
        }
    }
    atomicAdd(&g_csum[f4 * 4 + 0], cs0);
    atomicAdd(&g_csum[f4 * 4 + 1], cs1);
    atomicAdd(&g_csum[f4 * 4 + 2], cs2);
    atomicAdd(&g_csum[f4 * 4 + 3], cs3);
}

// ---------------- Gram via mma from fp32 (D=64, for h3/out) -----------------
template <int D>
__global__ __launch_bounds__(256) void k_gram_mma(const float* __restrict__ h) {
    __shared__ __align__(1024) uint8_t sm[2 * D * 128];
    const int OFF_L = D * 128;
    const int FG = D / 4;
    const int PAIRS = 256 / FG;
    const int NT = D / 8;
    const int MW = D / 16;
    uint32_t sb = smem_u32(sm);
    int tid = threadIdx.x, wid = tid >> 5, lane = tid & 31;
    int f4 = tid % FG;
    int rp0 = tid / FG;

    float acc[NT][4];
#pragma unroll
    for (int j = 0; j < NT; j++)
#pragma unroll
        for (int q = 0; q < 4; q++) acc[j][q] = 0.f;
    float cs0 = 0.f, cs1 = 0.f, cs2 = 0.f, cs3 = 0.f;

    const int NCHUNK = (NNODES + 63) / 64;
    for (int ch = blockIdx.x; ch < NCHUNK; ch += gridDim.x) {
        int rbase = ch * 64;
#pragma unroll
        for (int it = 0; it < 32 / PAIRS; it++) {
            int pr = rp0 + it * PAIRS;
            int r0 = rbase + pr * 2, r1 = r0 + 1;
            float4 v0 = make_float4(0.f, 0.f, 0.f, 0.f), v1 = v0;
            if (r0 < NNODES) v0 = *(const float4*)&h[(size_t)r0 * D + f4 * 4];
            if (r1 < NNODES) v1 = *(const float4*)&h[(size_t)r1 * D + f4 * 4];
            cs0 += v0.x + v1.x; cs1 += v0.y + v1.y;
            cs2 += v0.z + v1.z; cs3 += v0.w + v1.w;
            float a0[4] = {v0.x, v0.y, v0.z, v0.w};
            float a1[4] = {v1.x, v1.y, v1.z, v1.w};
#pragma unroll
            for (int j = 0; j < 4; j++) {
                int feat = f4 * 4 + j;
                __nv_bfloat16 h0, l0, h1, l1;
                split2(a0[j], h0, l0);
                split2(a1[j], h1, l1);
                uint32_t hp = (uint32_t)__bfloat16_as_ushort(h0)
                            | ((uint32_t)__bfloat16_as_ushort(h1) << 16);
                uint32_t lp = (uint32_t)__bfloat16_as_ushort(l0)
                            | ((uint32_t)__bfloat16_as_ushort(l1) << 16);
                uint32_t so = sw128((uint32_t)(feat * 128 + pr * 4));
                *(uint32_t*)(sm + so) = hp;
                *(uint32_t*)(sm + OFF_L + so) = lp;
            }
        }
        __syncthreads();
        if (wid < MW) {
#pragma unroll
            for (int k16 = 0; k16 < 4; k16++) {
                int kb = k16 * 32;
                uint32_t ah[4], al[4];
                {
                    int r = wid * 16 + (lane & 15);
                    int cb = kb + ((lane & 16) ? 16 : 0);
                    uint32_t so = sw128((uint32_t)(r * 128 + cb));
                    ldsm4(ah, sb + so);
                    ldsm4(al, sb + OFF_L + so);
                }
#pragma unroll
                for (int bt = 0; bt < NT / 2; bt++) {
                    int n = bt * 16 + (lane & 7) + ((lane & 16) ? 8 : 0);
                    int cb = kb + ((lane & 8) ? 16 : 0);
                    uint32_t so = sw128((uint32_t)(n * 128 + cb));
                    uint32_t bh[4], bl[4];
                    ldsm4(bh, sb + so);
                    ldsm4(bl, sb + OFF_L + so);
#pragma unroll
                    for (int hh = 0; hh < 2; hh++) {
                        int nt = bt * 2 + hh;
                        mma16816(acc[nt], ah, &bh[hh * 2]);
                        mma16816(acc[nt], ah, &bl[hh * 2]);
                        mma16816(acc[nt], al, &bh[hh * 2]);
                    }
                }
            }
        }
        __syncthreads();
    }
    if (wid < MW) {
        int mrow = wid * 16 + (lane >> 2);
#pragma unroll
        for (int nt = 0; nt < NT; nt++) {
            int c = nt * 8 + (lane & 3) * 2;
            atomicAdd(&g_G[mrow * D + c], acc[nt][0]);
            atomicAdd(&g_G[mrow * D + c + 1], acc[nt][1]);
            atomicAdd(&g_G[(mrow + 8) * D + c], acc[nt][2]);
            atomicAdd(&g_G[(mrow + 8) * D + c + 1], acc[nt][3]);
        }
    }
    atomicAdd(&g_csum[f4 * 4 + 0], cs0);
    atomicAdd(&g_csum[f4 * 4 + 1], cs1);
    atomicAdd(&g_csum[f4 * 4 + 2], cs2);
    atomicAdd(&g_csum[f4 * 4 + 3], cs3);
}

// ---------------- correlation metric finalize (single block) ----------------
template <int D>
__global__ void k_finalize(float* __restrict__ dst) {
    __shared__ float sd[D];
    __shared__ float red[256];
    int tid = threadIdx.x;
    const float invN = 1.0f / (float)NNODES;
    if (tid < D) {
        float cjj = g_G[tid * D + tid] - g_csum[tid] * g_csum[tid] * invN;
        sd[tid] = sqrtf(fmaxf(cjj, 1e-12f));
    }
    __syncthreads();
    float sum = 0.f;
    for (int idx = tid; idx < D * D; idx += 256) {
        int j = idx / D, k = idx % D;
        if (k > j) {
            float cov = g_G[idx] - g_csum[j] * g_csum[k] * invN;
            sum += fabsf(cov / (sd[j] * sd[k]));
        }
    }
    red[tid] = sum;
    __syncthreads();
    for (int off = 128; off > 0; off >>= 1) {
        if (tid < off) red[tid] += red[tid + off];
        __syncthreads();
    }
    if (tid == 0) *dst = red[0] / (float)(D * (D - 1) / 2);
}

// ---------------- launch ----------------
extern "C" void kernel_launch(void* const* d_in, const int* in_sizes, int n_in,
                              void* d_out, int out_size) {
    const float* x  = (const float*)d_in[0];
    const int*   ei = (const int*)d_in[1];
    const float* W0 = (const float*)d_in[2];
    const float* W1 = (const float*)d_in[3];
    const float* W2 = (const float*)d_in[4];
    const float* W3 = (const float*)d_in[5];
    float* out = (float*)d_out;

    __half *tmpA, *tmpB;
    __nv_bfloat16 *ah, *al, *ph, *pl;
    cudaGetSymbolAddress((void**)&tmpA, g_tmpA);
    cudaGetSymbolAddress((void**)&tmpB, g_tmpB);
    cudaGetSymbolAddress((void**)&ah, g_ah);
    cudaGetSymbolAddress((void**)&al, g_al);
    cudaGetSymbolAddress((void**)&ph, g_ph);
    cudaGetSymbolAddress((void**)&pl, g_pl);
    __nv_bfloat16 *w0h, *w0l, *w1h, *w1l, *w2h, *w2l, *w3h, *w3l;
    cudaGetSymbolAddress((void**)&w0h, g_w0h); cudaGetSymbolAddress((void**)&w0l, g_w0l);
    cudaGetSymbolAddress((void**)&w1h, g_w1h); cudaGetSymbolAddress((void**)&w1l, g_w1l);
    cudaGetSymbolAddress((void**)&w2h, g_w2h); cudaGetSymbolAddress((void**)&w2l, g_w2l);
    cudaGetSymbolAddress((void**)&w3h, g_w3h); cudaGetSymbolAddress((void**)&w3l, g_w3l);

    const int SM_BIG = 4 * 128 * 128 + 4 * HID * 128;   // 131072 (2 stages)
    const int SM_SML = 4 * 128 * 128 + 4 * COUT * 128;  // 98304
    cudaFuncSetAttribute(k_tgemm512<FIN, HID, true>,
                         cudaFuncAttributeMaxDynamicSharedMemorySize, SM_BIG);
    cudaFuncSetAttribute(k_tgemm512<HID, HID, false>,
                         cudaFuncAttributeMaxDynamicSharedMemorySize, SM_BIG);
    cudaFuncSetAttribute(k_tgemm512<HID, COUT, false>,
                         cudaFuncAttributeMaxDynamicSharedMemorySize, SM_SML);

    // side stream + events for fork/join inside graph capture (leaked, bounded)
    cudaStream_t s1;
    cudaStreamCreateWithFlags(&s1, cudaStreamNonBlocking);
    cudaEvent_t eFork1, ePre, eG0, eA0, eG1, eA1, eG2, eA2h0, eA2, eCorr;
    cudaEventCreateWithFlags(&eFork1, cudaEventDisableTiming);
    cudaEventCreateWithFlags(&ePre,  cudaEventDisableTiming);
    cudaEventCreateWithFlags(&eG0, cudaEventDisableTiming);
    cudaEventCreateWithFlags(&eA0, cudaEventDisableTiming);
    cudaEventCreateWithFlags(&eG1, cudaEventDisableTiming);
    cudaEventCreateWithFlags(&eA1, cudaEventDisableTiming);
    cudaEventCreateWithFlags(&eG2, cudaEventDisableTiming);
    cudaEventCreateWithFlags(&eA2h0, cudaEventDisableTiming);
    cudaEventCreateWithFlags(&eA2, cudaEventDisableTiming);
    cudaEventCreateWithFlags(&eCorr, cudaEventDisableTiming);

    const int TB = 256;
    const int nbN = (NNODES + TB - 1) / TB;
    const int nbE = (NEDGES + TB - 1) / TB;
    const int nbM  = (NNODES + 127) / 128;       // 782 (full)
    const int nbM0 = H0ROWS / 128;               // 391
    const int nbM1 = nbM - nbM0;                 // 391
    const int nbA  = (NNODES + 7) / 8;
    const int nbA0 = (H0ROWS + 7) / 8;
    const int nbA1 = (NNODES - H0ROWS + 7) / 8;
    const int P3N = 2 * HID * HID + HID * COUT;

    // ---- fork: preprocessing on s1, L0 GEMM on capture stream ----
    cudaEventRecord(eFork1, 0);
    cudaStreamWaitEvent(s1, eFork1, 0);

    k_prepW<FIN, HID><<<(FIN * HID + TB - 1) / TB, TB>>>(W0, w0h, w0l);      // idx0
    k_zero_init<<<nbN, TB, 0, s1>>>();                                        // idx1
    k_count<<<nbE, TB, 0, s1>>>(ei);                                          // idx2
    k_tgemm512<FIN, HID, true><<<nbM, 512, SM_BIG>>>(x, nullptr, nullptr,
                                                     w0h, w0l, tmpA, 0);      // idx3 (profiled)
    cudaEventRecord(eG0, 0);
    k_scan1<<<SCAN_NB, SCAN_TPB, 0, s1>>>();
    k_scan2<<<1, 64, 0, s1>>>();
    k_scan3<<<SCAN_NB, SCAN_TPB, 0, s1>>>();
    k_fill<<<nbE, TB, 0, s1>>>(ei);
    k_prepW3x<<<(P3N + TB - 1) / TB, TB, 0, s1>>>(W1, W2, W3);
    cudaEventRecord(ePre, s1);
    cudaStreamWaitEvent(0, ePre, 0);

    // ---- layer 0 agg, split: H0 on s0, H1 on s1 (overlaps GEMM1(H0)) ----
    k_agg128s<false><<<nbA0, TB>>>(tmpA, ah, al, ph, pl, 0, H0ROWS);
    cudaStreamWaitEvent(s1, eG0, 0);
    k_agg128s<false><<<nbA1, TB, 0, s1>>>(tmpA, ah, al, ph, pl, H0ROWS, NNODES);
    cudaEventRecord(eA0, s1);
    // ---- layer 1 GEMM -> tmpB ----
    k_tgemm512<HID, HID, false><<<nbM0, 512, SM_BIG>>>(nullptr, ah, al, w1h, w1l, tmpB, 0);
    cudaStreamWaitEvent(0, eA0, 0);
    k_tgemm512<HID, HID, false><<<nbM1, 512, SM_BIG>>>(nullptr, ah, al, w1h, w1l, tmpB, H0ROWS);
    cudaEventRecord(eG1, 0);
    // ---- layer 1 agg, split ----
    k_agg128s<false><<<nbA0, TB>>>(tmpB, ah, al, ph, pl, 0, H0ROWS);
    cudaStreamWaitEvent(s1, eG1, 0);
    k_agg128s<false><<<nbA1, TB, 0, s1>>>(tmpB, ah, al, ph, pl, H0ROWS, NNODES);
    cudaEventRecord(eA1, s1);
    // ---- layer 2 GEMM -> tmpA ----
    k_tgemm512<HID, HID, false><<<nbM0, 512, SM_BIG>>>(nullptr, ah, al, w2h, w2l, tmpA, 0);
    cudaStreamWaitEvent(0, eA1, 0);
    k_tgemm512<HID, HID, false><<<nbM1, 512, SM_BIG>>>(nullptr, ah, al, w2h, w2l, tmpA, H0ROWS);
    cudaEventRecord(eG2, 0);
    // ---- layer 2 agg (PRE: keeps pre-relu h2), split ----
    k_agg128s<true><<<nbA0, TB>>>(tmpA, ah, al, ph, pl, 0, H0ROWS);
    cudaEventRecord(eA2h0, 0);
    cudaStreamWaitEvent(s1, eG2, 0);
    k_agg128s<true><<<nbA1, TB, 0, s1>>>(tmpA, ah, al, ph, pl, H0ROWS, NNODES);
    cudaEventRecord(eA2, s1);

    // ---- corr_2 on s1 (needs both agg2 halves: H1 natural, H0 via eA2h0) ----
    cudaStreamWaitEvent(s1, eA2h0, 0);
    k_zero_G<<<(HID * HID + TB - 1) / TB, TB, 0, s1>>>();
    k_gram_split<<<296, 256, 0, s1>>>(ph, pl);
    k_finalize<HID><<<1, 256, 0, s1>>>(out + NNODES * COUT);
    cudaEventRecord(eCorr, s1);

    // ---- layer 3 GEMM -> tmpB (H0 after agg2(H0) natural; H1 waits eA2) ----
    k_tgemm512<HID, COUT, false><<<nbM0, 512, SM_SML>>>(nullptr, ah, al, w3h, w3l, tmpB, 0);
    cudaStreamWaitEvent(0, eA2, 0);
    k_tgemm512<HID, COUT, false><<<nbM1, 512, SM_SML>>>(nullptr, ah, al, w3h, w3l, tmpB, H0ROWS);
    k_agg64h<<<nbA, TB>>>(tmpB, out);

    // ---- final corr on h3 (g_G free after finalize<HID> via eCorr) ----
    cudaStreamWaitEvent(0, eCorr, 0);
    k_zero_G<<<(HID * HID + TB - 1) / TB, TB>>>();
    k_gram_mma<COUT><<<296, 256>>>(out);
    k_finalize<COUT><<<1, 256>>>(out + NNODES * COUT + 1);
}

// round 10
// speedup vs baseline: 1.1155x; 1.1155x over previous
#include <cuda_runtime.h>
#include <cuda_bf16.h>
#include <cuda_fp16.h>
#include <math.h>
#include <stdint.h>

#define NNODES 100000
#define NEDGES 1600000
#define FIN 256
#define HID 128
#define COUT 64

#define SCAN_TPB 256
#define SCAN_ELEMS 8
#define SCAN_CHUNK (SCAN_TPB * SCAN_ELEMS)                 // 2048
#define SCAN_NB ((NNODES + SCAN_CHUNK - 1) / SCAN_CHUNK)   // 49

// ---------------- scratch (static __device__, no allocation) ----------------
__device__ __half g_tmp[NNODES * HID];          // messages (GEMM out), fp16
__device__ __half g_hf[NNODES * HID];           // relu'd h, fp16 (GEMM A input)
__device__ __nv_bfloat16 g_ph[NNODES * HID];    // pre-relu h2, hi split (gram)
__device__ __nv_bfloat16 g_pl[NNODES * HID];    // pre-relu h2, lo split
__device__ float g_dinv[NNODES];
__device__ int   g_cnt[NNODES];
__device__ int   g_cursor[NNODES];
__device__ int   g_rowptr[NNODES + 1];
__device__ int   g_col[NEDGES];
__device__ float g_w[NEDGES];
__device__ float g_G[HID * HID];
__device__ float g_csum[HID];
__device__ int   g_bsum[SCAN_NB];

// split-fp16 transposed weights: Wt[d][k] = W[k][d]
__device__ __half g_w0h[HID * FIN],  g_w0l[HID * FIN];
__device__ __half g_w1h[HID * HID],  g_w1l[HID * HID];
__device__ __half g_w2h[HID * HID],  g_w2l[HID * HID];
__device__ __half g_w3h[COUT * HID], g_w3l[COUT * HID];

// ---------------- helpers ----------------
__device__ __forceinline__ uint32_t smem_u32(const void* p) {
    uint32_t a;
    asm("{ .reg .u64 t; cvta.to.shared.u64 t, %1; cvt.u32.u64 %0, t; }"
        : "=r"(a) : "l"(p));
    return a;
}
__device__ __forceinline__ uint32_t sw128(uint32_t off) {
    return off ^ ((off >> 3) & 0x70);
}
__device__ __forceinline__ void ldsm4(uint32_t* r, uint32_t addr) {
    asm volatile("ldmatrix.sync.aligned.m8n8.x4.shared.b16 {%0,%1,%2,%3}, [%4];"
                 : "=r"(r[0]), "=r"(r[1]), "=r"(r[2]), "=r"(r[3]) : "r"(addr));
}
// fp16 mma: D(f32) += A(f16) * B(f16)
__device__ __forceinline__ void mma_h(float* c, const uint32_t* a,
                                      const uint32_t* b) {
    asm volatile(
        "mma.sync.aligned.m16n8k16.row.col.f32.f16.f16.f32 "
        "{%0,%1,%2,%3}, {%4,%5,%6,%7}, {%8,%9}, {%0,%1,%2,%3};"
        : "+f"(c[0]), "+f"(c[1]), "+f"(c[2]), "+f"(c[3])
        : "r"(a[0]), "r"(a[1]), "r"(a[2]), "r"(a[3]), "r"(b[0]), "r"(b[1]));
}
__device__ __forceinline__ void split2b(float f, __nv_bfloat16& h, __nv_bfloat16& l) {
    h = __float2bfloat16_rn(f);
    l = __float2bfloat16_rn(f - __bfloat162float(h));
}
__device__ __forceinline__ void split2h(float f, __half& h, __half& l) {
    h = __float2half_rn(f);
    l = __float2half_rn(f - __half2float(h));
}
__device__ __forceinline__ void cpa16(uint32_t dst, const void* src, int nbytes) {
    asm volatile("cp.async.cg.shared.global [%0], [%1], 16, %2;"
                 :: "r"(dst), "l"(src), "r"(nbytes) : "memory");
}
__device__ __forceinline__ void cpa_commit() {
    asm volatile("cp.async.commit_group;" ::: "memory");
}
__device__ __forceinline__ void cpa_wait1() {
    asm volatile("cp.async.wait_group 1;" ::: "memory");
}
__device__ __forceinline__ void cpa_wait0() {
    asm volatile("cp.async.wait_group 0;" ::: "memory");
}

// ---------------- preprocessing ----------------
__global__ void k_zero_init() {
    int i = blockIdx.x * blockDim.x + threadIdx.x;
    if (i < NNODES) { g_cnt[i] = 0; g_cursor[i] = 0; }
}

__global__ void k_zero_G() {
    int i = blockIdx.x * blockDim.x + threadIdx.x;
    if (i < HID * HID) g_G[i] = 0.f;
    if (i < HID) g_csum[i] = 0.f;
}

__global__ void k_count(const int* __restrict__ ei) {
    int e = blockIdx.x * blockDim.x + threadIdx.x;
    if (e < NEDGES) atomicAdd(&g_cnt[ei[e]], 1);
}

__global__ void k_scan1() {
    __shared__ int warp_s[SCAN_TPB / 32];
    int tid = threadIdx.x, blk = blockIdx.x;
    int base = blk * SCAN_CHUNK + tid * SCAN_ELEMS;
    int s = 0;
#pragma unroll
    for (int i = 0; i < SCAN_ELEMS; i++) {
        int idx = base + i;
        if (idx < NNODES) {
            int c = g_cnt[idx];
            s += c;
            g_dinv[idx] = rsqrtf((float)(c + 1));  // +1 self loop
        }
    }
    for (int o = 16; o > 0; o >>= 1) s += __shfl_down_sync(0xffffffffu, s, o);
    if ((tid & 31) == 0) warp_s[tid >> 5] = s;
    __syncthreads();
    if (tid < SCAN_TPB / 32) {
        int w = warp_s[tid];
        for (int o = (SCAN_TPB / 64); o > 0; o >>= 1)
            w += __shfl_down_sync(0xffu, w, o);
        if (tid == 0) g_bsum[blk] = w;
    }
}

__global__ void k_scan2() {
    __shared__ int sh[64];
    int tid = threadIdx.x;
    sh[tid] = (tid < SCAN_NB) ? g_bsum[tid] : 0;
    __syncthreads();
    for (int o = 1; o < 64; o <<= 1) {
        int v = (tid >= o) ? sh[tid - o] : 0;
        __syncthreads();
        sh[tid] += v;
        __syncthreads();
    }
    if (tid < SCAN_NB) g_bsum[tid] = (tid == 0) ? 0 : sh[tid - 1];
    if (tid == 0) g_rowptr[NNODES] = sh[SCAN_NB - 1];
}

__global__ void k_scan3() {
    __shared__ int tsum[SCAN_TPB];
    int tid = threadIdx.x, blk = blockIdx.x;
    int base = blk * SCAN_CHUNK + tid * SCAN_ELEMS;
    int c[SCAN_ELEMS];
    int s = 0;
#pragma unroll
    for (int i = 0; i < SCAN_ELEMS; i++) {
        int idx = base + i;
        c[i] = (idx < NNODES) ? g_cnt[idx] : 0;
        s += c[i];
    }
    tsum[tid] = s;
    __syncthreads();
    for (int o = 1; o < SCAN_TPB; o <<= 1) {
        int v = (tid >= o) ? tsum[tid - o] : 0;
        __syncthreads();
        tsum[tid] += v;
        __syncthreads();
    }
    int run = g_bsum[blk] + ((tid == 0) ? 0 : tsum[tid - 1]);
#pragma unroll
    for (int i = 0; i < SCAN_ELEMS; i++) {
        int idx = base + i;
        if (idx < NNODES) { g_rowptr[idx] = run; run += c[i]; }
    }
}

__global__ void k_fill(const int* __restrict__ ei) {
    int e = blockIdx.x * blockDim.x + threadIdx.x;
    if (e >= NEDGES) return;
    int r = ei[e];
    int c = ei[NEDGES + e];
    int pos = g_rowptr[r] + atomicAdd(&g_cursor[r], 1);
    g_col[pos] = c;
    g_w[pos] = g_dinv[r] * g_dinv[c];
}

// ---------------- weight prep: W[K,D] fp32 -> Wt hi/lo fp16 [D][K] ----------
template <int K, int D>
__global__ void k_prepW(const float* __restrict__ W,
                        __half* __restrict__ Wh, __half* __restrict__ Wl) {
    int i = blockIdx.x * blockDim.x + threadIdx.x;
    if (i >= K * D) return;
    int n = i / K, k = i % K;
    __half h, l;
    split2h(W[k * D + n], h, l);
    Wh[n * K + k] = h;
    Wl[n * K + k] = l;
}

__global__ void k_prepW3x(const float* __restrict__ W1,
                          const float* __restrict__ W2,
                          const float* __restrict__ W3) {
    int i = blockIdx.x * blockDim.x + threadIdx.x;
    const int S1 = HID * HID, S2 = 2 * HID * HID, S3 = 2 * HID * HID + HID * COUT;
    __half h, l;
    if (i < S1) {
        int n = i / HID, k = i % HID;
        split2h(W1[k * HID + n], h, l);
        g_w1h[n * HID + k] = h; g_w1l[n * HID + k] = l;
    } else if (i < S2) {
        int j = i - S1;
        int n = j / HID, k = j % HID;
        split2h(W2[k * HID + n], h, l);
        g_w2h[n * HID + k] = h; g_w2l[n * HID + k] = l;
    } else if (i < S3) {
        int j = i - S2;
        int n = j / HID, k = j % HID;
        split2h(W3[k * COUT + n], h, l);
        g_w3h[n * HID + k] = h; g_w3l[n * HID + k] = l;
    }
}

// ---------------- pipelined fp16-A / split-fp16-B GEMM ---------------------
// C[N,D] = A[N,K] @ W[K,D]; 512 threads (16 warps, 4x4); 2-stage ping-pong.
// 2 MMAs per (mt,nt,k16): A*Bh + A*Bl.
template <int K, int D, bool CONVERT>
__global__ __launch_bounds__(512) void k_tgemm512(const float* __restrict__ Af,
                                                  const __half* __restrict__ Ah,
                                                  const __half* __restrict__ Bh,
                                                  const __half* __restrict__ Bl,
                                                  __half* __restrict__ C) {
    extern __shared__ __align__(1024) uint8_t smem[];
    const int CK = 64;
    const int NCH = K / CK;
    const int WN = D / 4;                // 32 or 16
    const int NT = WN / 8;               // 4 or 2
    const int STA = 128 * 128;           // 16KB A stage (single operand)
    const int SBB = D * 128;
    const int OFF_B = 2 * STA;

    uint32_t sb = smem_u32(smem);
    int tid = threadIdx.x, wid = tid >> 5, lane = tid & 31;
    int wm = wid & 3, wn = wid >> 2;
    int row0 = wm * 32;
    int col0 = wn * WN;
    int grow = blockIdx.x * 128;

    float acc[2][NT][4];
#pragma unroll
    for (int i = 0; i < 2; i++)
#pragma unroll
        for (int j = 0; j < NT; j++)
#pragma unroll
            for (int q = 0; q < 4; q++) acc[i][j][q] = 0.f;

    float4 pf[4];

    auto a_async = [&](int s, int ch) {
        int kk = ch * CK;
#pragma unroll
        for (int i = 0; i < 2; i++) {
            int u = tid + i * 512;
            int m = u >> 3, g = u & 7;
            int r = grow + m;
            int rc = (r < NNODES) ? r : 0;
            int nb = (r < NNODES) ? 16 : 0;
            uint32_t so = sw128((uint32_t)(m * 128 + g * 16));
            cpa16(sb + s * STA + so, &Ah[(size_t)rc * K + kk + g * 8], nb);
        }
    };
    auto b_async = [&](int s, int ch) {
        int kk = ch * CK;
#pragma unroll
        for (int i = 0; i < (D * 8 + 511) / 512; i++) {
            int u = tid + i * 512;
            if (u < D * 8) {
                int n = u >> 3, g = u & 7;
                uint32_t so = sw128((uint32_t)(n * 128 + g * 16));
                cpa16(sb + OFF_B + (2 * s) * SBB + so, &Bh[n * K + kk + g * 8], 16);
                cpa16(sb + OFF_B + (2 * s + 1) * SBB + so, &Bl[n * K + kk + g * 8], 16);
            }
        }
    };
    auto a_ldregs = [&](int ch) {
        int kk = ch * CK;
#pragma unroll
        for (int i = 0; i < 2; i++) {
            int u = tid + i * 512;
            int m = u >> 3, g = u & 7;
            int r = grow + m;
            pf[2 * i] = make_float4(0.f, 0.f, 0.f, 0.f);
            pf[2 * i + 1] = pf[2 * i];
            if (r < NNODES) {
                const float* p = &Af[(size_t)r * K + kk + g * 8];
                pf[2 * i] = *(const float4*)p;
                pf[2 * i + 1] = *(const float4*)(p + 4);
            }
        }
    };
    auto a_cvtsts = [&](int s) {
#pragma unroll
        for (int i = 0; i < 2; i++) {
            int u = tid + i * 512;
            int m = u >> 3, g = u & 7;
            uint32_t hp[4];
            __half2 h0 = __floats2half2_rn(pf[2 * i].x, pf[2 * i].y);
            __half2 h1 = __floats2half2_rn(pf[2 * i].z, pf[2 * i].w);
            __half2 h2 = __floats2half2_rn(pf[2 * i + 1].x, pf[2 * i + 1].y);
            __half2 h3 = __floats2half2_rn(pf[2 * i + 1].z, pf[2 * i + 1].w);
            hp[0] = *(uint32_t*)&h0; hp[1] = *(uint32_t*)&h1;
            hp[2] = *(uint32_t*)&h2; hp[3] = *(uint32_t*)&h3;
            uint32_t so = sw128((uint32_t)(m * 128 + g * 16));
            *(uint4*)(smem + s * STA + so) = make_uint4(hp[0], hp[1], hp[2], hp[3]);
        }
    };

    if (CONVERT) { a_ldregs(0); a_cvtsts(0); }
    else a_async(0, 0);
    b_async(0, 0);
    cpa_commit();

    for (int ch = 0; ch < NCH; ch++) {
        int cur = ch & 1, nxt = cur ^ 1;
        bool more = (ch + 1 < NCH);
        if (more) {
            if (CONVERT) a_ldregs(ch + 1);
            else a_async(nxt, ch + 1);
            b_async(nxt, ch + 1);
            cpa_commit();
        }
        if (more) cpa_wait1(); else cpa_wait0();
        __syncthreads();
        {
            uint32_t aB = sb + cur * STA;
            uint32_t bB0 = sb + OFF_B + (2 * cur) * SBB;
            uint32_t bB1 = sb + OFF_B + (2 * cur + 1) * SBB;
#pragma unroll
            for (int k16 = 0; k16 < CK / 16; k16++) {
                int kb = k16 * 32;
                uint32_t ah[2][4];
#pragma unroll
                for (int mt = 0; mt < 2; mt++) {
                    int r = row0 + mt * 16 + (lane & 15);
                    int cb = kb + ((lane & 16) ? 16 : 0);
                    uint32_t so = sw128((uint32_t)(r * 128 + cb));
                    ldsm4(ah[mt], aB + so);
                }
#pragma unroll
                for (int bt = 0; bt < NT / 2; bt++) {
                    int n = col0 + bt * 16 + (lane & 7) + ((lane & 16) ? 8 : 0);
                    int cb = kb + ((lane & 8) ? 16 : 0);
                    uint32_t so = sw128((uint32_t)(n * 128 + cb));
                    uint32_t bh[4], bl[4];
                    ldsm4(bh, bB0 + so);
                    ldsm4(bl, bB1 + so);
#pragma unroll
                    for (int h = 0; h < 2; h++) {
                        int nt = bt * 2 + h;
#pragma unroll
                        for (int mt = 0; mt < 2; mt++) {
                            mma_h(acc[mt][nt], ah[mt], &bh[h * 2]);
                            mma_h(acc[mt][nt], ah[mt], &bl[h * 2]);
                        }
                    }
                }
            }
        }
        if (more && CONVERT) a_cvtsts(nxt);
        __syncthreads();
    }

#pragma unroll
    for (int mt = 0; mt < 2; mt++) {
        int r0 = grow + row0 + mt * 16 + (lane >> 2);
        int r1 = r0 + 8;
#pragma unroll
        for (int nt = 0; nt < NT; nt++) {
            int cc = col0 + nt * 8 + (lane & 3) * 2;
            if (r0 < NNODES)
                *(__half2*)&C[(size_t)r0 * D + cc] =
                    __floats2half2_rn(acc[mt][nt][0], acc[mt][nt][1]);
            if (r1 < NNODES)
                *(__half2*)&C[(size_t)r1 * D + cc] =
                    __floats2half2_rn(acc[mt][nt][2], acc[mt][nt][3]);
        }
    }
}

// ---------------- sparse aggregation (fp16 gather, fp32 accumulate) --------
// h[i] = dinv[i]^2*tmp[i] + sum_e w_e*tmp[col_e]; writes relu(h) as fp16 hf;
// PRE also stores pre-relu split-bf16 (gram operand).
template <bool PRE>
__global__ void k_agg128s(const __half* __restrict__ tmp,
                          __half* __restrict__ hf,
                          __nv_bfloat16* __restrict__ ph,
                          __nv_bfloat16* __restrict__ pl) {
    int gw = (blockIdx.x * blockDim.x + threadIdx.x) >> 5;
    int lane = threadIdx.x & 31;
    if (gw >= NNODES) return;
    const uint2* __restrict__ t = (const uint2*)tmp;
    float di = g_dinv[gw];
    float s = di * di;
    uint2 u = t[gw * 32 + lane];
    float2 p0 = __half22float2(*(__half2*)&u.x);
    float2 p1 = __half22float2(*(__half2*)&u.y);
    float4 acc = make_float4(p0.x * s, p0.y * s, p1.x * s, p1.y * s);
    float4 acc2 = make_float4(0.f, 0.f, 0.f, 0.f);
    int e = g_rowptr[gw], en = g_rowptr[gw + 1];
    for (; e + 3 < en; e += 4) {
        int c0 = g_col[e], c1 = g_col[e + 1], c2 = g_col[e + 2], c3 = g_col[e + 3];
        float w0 = g_w[e], w1 = g_w[e + 1], w2 = g_w[e + 2], w3 = g_w[e + 3];
        uint2 a = t[c0 * 32 + lane];
        uint2 b = t[c1 * 32 + lane];
        uint2 cc = t[c2 * 32 + lane];
        uint2 d = t[c3 * 32 + lane];
        float2 a0 = __half22float2(*(__half2*)&a.x), a1 = __half22float2(*(__half2*)&a.y);
        float2 b0 = __half22float2(*(__half2*)&b.x), b1 = __half22float2(*(__half2*)&b.y);
        float2 c0f = __half22float2(*(__half2*)&cc.x), c1f = __half22float2(*(__half2*)&cc.y);
        float2 d0 = __half22float2(*(__half2*)&d.x), d1 = __half22float2(*(__half2*)&d.y);
        acc.x = fmaf(w0, a0.x, acc.x);   acc.y = fmaf(w0, a0.y, acc.y);
        acc.z = fmaf(w0, a1.x, acc.z);   acc.w = fmaf(w0, a1.y, acc.w);
        acc2.x = fmaf(w1, b0.x, acc2.x); acc2.y = fmaf(w1, b0.y, acc2.y);
        acc2.z = fmaf(w1, b1.x, acc2.z); acc2.w = fmaf(w1, b1.y, acc2.w);
        acc.x = fmaf(w2, c0f.x, acc.x);  acc.y = fmaf(w2, c0f.y, acc.y);
        acc.z = fmaf(w2, c1f.x, acc.z);  acc.w = fmaf(w2, c1f.y, acc.w);
        acc2.x = fmaf(w3, d0.x, acc2.x); acc2.y = fmaf(w3, d0.y, acc2.y);
        acc2.z = fmaf(w3, d1.x, acc2.z); acc2.w = fmaf(w3, d1.y, acc2.w);
    }
    for (; e < en; e++) {
        int c0 = g_col[e];
        float w0 = g_w[e];
        uint2 a = t[c0 * 32 + lane];
        float2 a0 = __half22float2(*(__half2*)&a.x);
        float2 a1 = __half22float2(*(__half2*)&a.y);
        acc.x = fmaf(w0, a0.x, acc.x); acc.y = fmaf(w0, a0.y, acc.y);
        acc.z = fmaf(w0, a1.x, acc.z); acc.w = fmaf(w0, a1.y, acc.w);
    }
    acc.x += acc2.x; acc.y += acc2.y; acc.z += acc2.z; acc.w += acc2.w;

    size_t base = (size_t)gw * HID + lane * 4;
    if (PRE) {
        float f[4] = {acc.x, acc.y, acc.z, acc.w};
        ushort hh[4], ll[4];
#pragma unroll
        for (int j = 0; j < 4; j++) {
            __nv_bfloat16 h, l;
            split2b(f[j], h, l);
            hh[j] = __bfloat16_as_ushort(h);
            ll[j] = __bfloat16_as_ushort(l);
        }
        *(uint2*)&ph[base] = make_uint2((uint32_t)hh[0] | ((uint32_t)hh[1] << 16),
                                        (uint32_t)hh[2] | ((uint32_t)hh[3] << 16));
        *(uint2*)&pl[base] = make_uint2((uint32_t)ll[0] | ((uint32_t)ll[1] << 16),
                                        (uint32_t)ll[2] | ((uint32_t)ll[3] << 16));
    }
    // relu + fp16 store (GEMM A operand)
    __half2 r0 = __floats2half2_rn(fmaxf(acc.x, 0.f), fmaxf(acc.y, 0.f));
    __half2 r1 = __floats2half2_rn(fmaxf(acc.z, 0.f), fmaxf(acc.w, 0.f));
    *(uint2*)&hf[base] = make_uint2(*(uint32_t*)&r0, *(uint32_t*)&r1);
}

__global__ void k_agg64h(const __half* __restrict__ tmp, float* __restrict__ out) {
    int gw = (blockIdx.x * blockDim.x + threadIdx.x) >> 5;
    int lane = threadIdx.x & 31;
    if (gw >= NNODES) return;
    const uint32_t* __restrict__ t = (const uint32_t*)tmp;
    float di = g_dinv[gw];
    float s = di * di;
    uint32_t u = t[gw * 32 + lane];
    float2 p = __half22float2(*(__half2*)&u);
    float2 acc = make_float2(p.x * s, p.y * s);
    float2 acc2 = make_float2(0.f, 0.f);
    int e = g_rowptr[gw], en = g_rowptr[gw + 1];
    for (; e + 3 < en; e += 4) {
        int c0 = g_col[e], c1 = g_col[e + 1], c2 = g_col[e + 2], c3 = g_col[e + 3];
        float w0 = g_w[e], w1 = g_w[e + 1], w2 = g_w[e + 2], w3 = g_w[e + 3];
        uint32_t a = t[c0 * 32 + lane];
        uint32_t b = t[c1 * 32 + lane];
        uint32_t c = t[c2 * 32 + lane];
        uint32_t d = t[c3 * 32 + lane];
        float2 af = __half22float2(*(__half2*)&a);
        float2 bf = __half22float2(*(__half2*)&b);
        float2 cf = __half22float2(*(__half2*)&c);
        float2 df = __half22float2(*(__half2*)&d);
        acc.x = fmaf(w0, af.x, acc.x);   acc.y = fmaf(w0, af.y, acc.y);
        acc2.x = fmaf(w1, bf.x, acc2.x); acc2.y = fmaf(w1, bf.y, acc2.y);
        acc.x = fmaf(w2, cf.x, acc.x);   acc.y = fmaf(w2, cf.y, acc.y);
        acc2.x = fmaf(w3, df.x, acc2.x); acc2.y = fmaf(w3, df.y, acc2.y);
    }
    for (; e < en; e++) {
        int c0 = g_col[e];
        float w0 = g_w[e];
        uint32_t a = t[c0 * 32 + lane];
        float2 af = __half22float2(*(__half2*)&a);
        acc.x = fmaf(w0, af.x, acc.x); acc.y = fmaf(w0, af.y, acc.y);
    }
    acc.x += acc2.x; acc.y += acc2.y;
    ((float2*)out)[gw * 32 + lane] = acc;
}

// ---------------- Gram via mma from pre-split bf16 h2 (D=128) ---------------
__device__ __forceinline__ void mma_bf(float* c, const uint32_t* a,
                                       const uint32_t* b) {
    asm volatile(
        "mma.sync.aligned.m16n8k16.row.col.f32.bf16.bf16.f32 "
        "{%0,%1,%2,%3}, {%4,%5,%6,%7}, {%8,%9}, {%0,%1,%2,%3};"
        : "+f"(c[0]), "+f"(c[1]), "+f"(c[2]), "+f"(c[3])
        : "r"(a[0]), "r"(a[1]), "r"(a[2]), "r"(a[3]), "r"(b[0]), "r"(b[1]));
}

__global__ __launch_bounds__(256) void k_gram_split(const __nv_bfloat16* __restrict__ ph,
                                                    const __nv_bfloat16* __restrict__ pl) {
    const int D = HID;
    __shared__ __align__(1024) uint8_t sm[2 * D * 128];
    const int OFF_L = D * 128;
    const int FG = D / 4;
    const int PAIRS = 256 / FG;
    const int NT = D / 8;
    const int MW = D / 16;
    uint32_t sb = smem_u32(sm);
    int tid = threadIdx.x, wid = tid >> 5, lane = tid & 31;
    int f4 = tid % FG;
    int rp0 = tid / FG;

    float acc[NT][4];
#pragma unroll
    for (int j = 0; j < NT; j++)
#pragma unroll
        for (int q = 0; q < 4; q++) acc[j][q] = 0.f;
    float cs0 = 0.f, cs1 = 0.f, cs2 = 0.f, cs3 = 0.f;

    const int NCHUNK = (NNODES + 63) / 64;
    for (int ch = blockIdx.x; ch < NCHUNK; ch += gridDim.x) {
        int rbase = ch * 64;
#pragma unroll
        for (int it = 0; it < 32 / PAIRS; it++) {
            int pr = rp0 + it * PAIRS;
            int r0 = rbase + pr * 2, r1 = r0 + 1;
            uint2 h0v = make_uint2(0, 0), h1v = h0v, l0v = h0v, l1v = h0v;
            if (r0 < NNODES) {
                h0v = *(const uint2*)&ph[(size_t)r0 * D + f4 * 4];
                l0v = *(const uint2*)&pl[(size_t)r0 * D + f4 * 4];
            }
            if (r1 < NNODES) {
                h1v = *(const uint2*)&ph[(size_t)r1 * D + f4 * 4];
                l1v = *(const uint2*)&pl[(size_t)r1 * D + f4 * 4];
            }
            const ushort* h0s = (const ushort*)&h0v;
            const ushort* h1s = (const ushort*)&h1v;
            const ushort* l0s = (const ushort*)&l0v;
            const ushort* l1s = (const ushort*)&l1v;
            float fs[4];
#pragma unroll
            for (int j = 0; j < 4; j++) {
                fs[j] = __bfloat162float(__ushort_as_bfloat16(h0s[j]))
                      + __bfloat162float(__ushort_as_bfloat16(l0s[j]))
                      + __bfloat162float(__ushort_as_bfloat16(h1s[j]))
                      + __bfloat162float(__ushort_as_bfloat16(l1s[j]));
                int feat = f4 * 4 + j;
                uint32_t hp = (uint32_t)h0s[j] | ((uint32_t)h1s[j] << 16);
                uint32_t lp = (uint32_t)l0s[j] | ((uint32_t)l1s[j] << 16);
                uint32_t so = sw128((uint32_t)(feat * 128 + pr * 4));
                *(uint32_t*)(sm + so) = hp;
                *(uint32_t*)(sm + OFF_L + so) = lp;
            }
            cs0 += fs[0]; cs1 += fs[1]; cs2 += fs[2]; cs3 += fs[3];
        }
        __syncthreads();
        if (wid < MW) {
#pragma unroll
            for (int k16 = 0; k16 < 4; k16++) {
                int kb = k16 * 32;
                uint32_t ah[4], al[4];
                {
                    int r = wid * 16 + (lane & 15);
                    int cb = kb + ((lane & 16) ? 16 : 0);
                    uint32_t so = sw128((uint32_t)(r * 128 + cb));
                    ldsm4(ah, sb + so);
                    ldsm4(al, sb + OFF_L + so);
                }
#pragma unroll
                for (int bt = 0; bt < NT / 2; bt++) {
                    int n = bt * 16 + (lane & 7) + ((lane & 16) ? 8 : 0);
                    int cb = kb + ((lane & 8) ? 16 : 0);
                    uint32_t so = sw128((uint32_t)(n * 128 + cb));
                    uint32_t bh[4], bl[4];
                    ldsm4(bh, sb + so);
                    ldsm4(bl, sb + OFF_L + so);
#pragma unroll
                    for (int hh = 0; hh < 2; hh++) {
                        int nt = bt * 2 + hh;
                        mma_bf(acc[nt], ah, &bh[hh * 2]);
                        mma_bf(acc[nt], ah, &bl[hh * 2]);
                        mma_bf(acc[nt], al, &bh[hh * 2]);
                    }
                }
            }
        }
        __syncthreads();
    }
    if (wid < MW) {
        int mrow = wid * 16 + (lane >> 2);
#pragma unroll
        for (int nt = 0; nt < NT; nt++) {
            int c = nt * 8 + (lane & 3) * 2;
            atomicAdd(&g_G[mrow * D + c], acc[nt][0]);
            atomicAdd(&g_G[mrow * D + c + 1], acc[nt][1]);
            atomicAdd(&g_G[(mrow + 8) * D + c], acc[nt][2]);
            atomicAdd(&g_G[(mrow + 8) * D + c + 1], acc[nt][3]);
        }
    }
    atomicAdd(&g_csum[f4 * 4 + 0], cs0);
    atomicAdd(&g_csum[f4 * 4 + 1], cs1);
    atomicAdd(&g_csum[f4 * 4 + 2], cs2);
    atomicAdd(&g_csum[f4 * 4 + 3], cs3);
}

// ---------------- Gram via mma from fp32 (D=64, for h3/out) -----------------
template <int D>
__global__ __launch_bounds__(256) void k_gram_mma(const float* __restrict__ h) {
    __shared__ __align__(1024) uint8_t sm[2 * D * 128];
    const int OFF_L = D * 128;
    const int FG = D / 4;
    const int PAIRS = 256 / FG;
    const int NT = D / 8;
    const int MW = D / 16;
    uint32_t sb = smem_u32(sm);
    int tid = threadIdx.x, wid = tid >> 5, lane = tid & 31;
    int f4 = tid % FG;
    int rp0 = tid / FG;

    float acc[NT][4];
#pragma unroll
    for (int j = 0; j < NT; j++)
#pragma unroll
        for (int q = 0; q < 4; q++) acc[j][q] = 0.f;
    float cs0 = 0.f, cs1 = 0.f, cs2 = 0.f, cs3 = 0.f;

    const int NCHUNK = (NNODES + 63) / 64;
    for (int ch = blockIdx.x; ch < NCHUNK; ch += gridDim.x) {
        int rbase = ch * 64;
#pragma unroll
        for (int it = 0; it < 32 / PAIRS; it++) {
            int pr = rp0 + it * PAIRS;
            int r0 = rbase + pr * 2, r1 = r0 + 1;
            float4 v0 = make_float4(0.f, 0.f, 0.f, 0.f), v1 = v0;
            if (r0 < NNODES) v0 = *(const float4*)&h[(size_t)r0 * D + f4 * 4];
            if (r1 < NNODES) v1 = *(const float4*)&h[(size_t)r1 * D + f4 * 4];
            cs0 += v0.x + v1.x; cs1 += v0.y + v1.y;
            cs2 += v0.z + v1.z; cs3 += v0.w + v1.w;
            float a0[4] = {v0.x, v0.y, v0.z, v0.w};
            float a1[4] = {v1.x, v1.y, v1.z, v1.w};
#pragma unroll
            for (int j = 0; j < 4; j++) {
                int feat = f4 * 4 + j;
                __nv_bfloat16 h0, l0, h1, l1;
                split2b(a0[j], h0, l0);
                split2b(a1[j], h1, l1);
                uint32_t hp = (uint32_t)__bfloat16_as_ushort(h0)
                            | ((uint32_t)__bfloat16_as_ushort(h1) << 16);
                uint32_t lp = (uint32_t)__bfloat16_as_ushort(l0)
                            | ((uint32_t)__bfloat16_as_ushort(l1) << 16);
                uint32_t so = sw128((uint32_t)(feat * 128 + pr * 4));
                *(uint32_t*)(sm + so) = hp;
                *(uint32_t*)(sm + OFF_L + so) = lp;
            }
        }
        __syncthreads();
        if (wid < MW) {
#pragma unroll
            for (int k16 = 0; k16 < 4; k16++) {
                int kb = k16 * 32;
                uint32_t ah[4], al[4];
                {
                    int r = wid * 16 + (lane & 15);
                    int cb = kb + ((lane & 16) ? 16 : 0);
                    uint32_t so = sw128((uint32_t)(r * 128 + cb));
                    ldsm4(ah, sb + so);
                    ldsm4(al, sb + OFF_L + so);
                }
#pragma unroll
                for (int bt = 0; bt < NT / 2; bt++) {
                    int n = bt * 16 + (lane & 7) + ((lane & 16) ? 8 : 0);
                    int cb = kb + ((lane & 8) ? 16 : 0);
                    uint32_t so = sw128((uint32_t)(n * 128 + cb));
                    uint32_t bh[4], bl[4];
                    ldsm4(bh, sb + so);
                    ldsm4(bl, sb + OFF_L + so);
#pragma unroll
                    for (int hh = 0; hh < 2; hh++) {
                        int nt = bt * 2 + hh;
                        mma_bf(acc[nt], ah, &bh[hh * 2]);
                        mma_bf(acc[nt], ah, &bl[hh * 2]);
                        mma_bf(acc[nt], al, &bh[hh * 2]);
                    }
                }
            }
        }
        __syncthreads();
    }
    if (wid < MW) {
        int mrow = wid * 16 + (lane >> 2);
#pragma unroll
        for (int nt = 0; nt < NT; nt++) {
            int c = nt * 8 + (lane & 3) * 2;
            atomicAdd(&g_G[mrow * D + c], acc[nt][0]);
            atomicAdd(&g_G[mrow * D + c + 1], acc[nt][1]);
            atomicAdd(&g_G[(mrow + 8) * D + c], acc[nt][2]);
            atomicAdd(&g_G[(mrow + 8) * D + c + 1], acc[nt][3]);
        }
    }
    atomicAdd(&g_csum[f4 * 4 + 0], cs0);
    atomicAdd(&g_csum[f4 * 4 + 1], cs1);
    atomicAdd(&g_csum[f4 * 4 + 2], cs2);
    atomicAdd(&g_csum[f4 * 4 + 3], cs3);
}

// ---------------- correlation metric finalize (single block) ----------------
template <int D>
__global__ void k_finalize(float* __restrict__ dst) {
    __shared__ float sd[D];
    __shared__ float red[256];
    int tid = threadIdx.x;
    const float invN = 1.0f / (float)NNODES;
    if (tid < D) {
        float cjj = g_G[tid * D + tid] - g_csum[tid] * g_csum[tid] * invN;
        sd[tid] = sqrtf(fmaxf(cjj, 1e-12f));
    }
    __syncthreads();
    float sum = 0.f;
    for (int idx = tid; idx < D * D; idx += 256) {
        int j = idx / D, k = idx % D;
        if (k > j) {
            float cov = g_G[idx] - g_csum[j] * g_csum[k] * invN;
            sum += fabsf(cov / (sd[j] * sd[k]));
        }
    }
    red[tid] = sum;
    __syncthreads();
    for (int off = 128; off > 0; off >>= 1) {
        if (tid < off) red[tid] += red[tid + off];
        __syncthreads();
    }
    if (tid == 0) *dst = red[0] / (float)(D * (D - 1) / 2);
}

// ---------------- launch (round-8 graph structure) --------------------------
extern "C" void kernel_launch(void* const* d_in, const int* in_sizes, int n_in,
                              void* d_out, int out_size) {
    const float* x  = (const float*)d_in[0];
    const int*   ei = (const int*)d_in[1];
    const float* W0 = (const float*)d_in[2];
    const float* W1 = (const float*)d_in[3];
    const float* W2 = (const float*)d_in[4];
    const float* W3 = (const float*)d_in[5];
    float* out = (float*)d_out;

    __half *tmp, *hf;
    __nv_bfloat16 *ph, *pl;
    cudaGetSymbolAddress((void**)&tmp, g_tmp);
    cudaGetSymbolAddress((void**)&hf, g_hf);
    cudaGetSymbolAddress((void**)&ph, g_ph);
    cudaGetSymbolAddress((void**)&pl, g_pl);
    __half *w0h, *w0l, *w1h, *w1l, *w2h, *w2l, *w3h, *w3l;
    cudaGetSymbolAddress((void**)&w0h, g_w0h); cudaGetSymbolAddress((void**)&w0l, g_w0l);
    cudaGetSymbolAddress((void**)&w1h, g_w1h); cudaGetSymbolAddress((void**)&w1l, g_w1l);
    cudaGetSymbolAddress((void**)&w2h, g_w2h); cudaGetSymbolAddress((void**)&w2l, g_w2l);
    cudaGetSymbolAddress((void**)&w3h, g_w3h); cudaGetSymbolAddress((void**)&w3l, g_w3l);

    const int SM_BIG = 2 * 128 * 128 + 4 * HID * 128;   // 98304
    const int SM_SML = 2 * 128 * 128 + 4 * COUT * 128;  // 65536
    cudaFuncSetAttribute(k_tgemm512<FIN, HID, true>,
                         cudaFuncAttributeMaxDynamicSharedMemorySize, SM_BIG);
    cudaFuncSetAttribute(k_tgemm512<HID, HID, false>,
                         cudaFuncAttributeMaxDynamicSharedMemorySize, SM_BIG);
    cudaFuncSetAttribute(k_tgemm512<HID, COUT, false>,
                         cudaFuncAttributeMaxDynamicSharedMemorySize, SM_SML);

    // side stream + events for fork/join inside graph capture (leaked, bounded)
    cudaStream_t s1;
    cudaStreamCreateWithFlags(&s1, cudaStreamNonBlocking);
    cudaEvent_t eFork1, ePre, eFork2, eCorr;
    cudaEventCreateWithFlags(&eFork1, cudaEventDisableTiming);
    cudaEventCreateWithFlags(&ePre,  cudaEventDisableTiming);
    cudaEventCreateWithFlags(&eFork2, cudaEventDisableTiming);
    cudaEventCreateWithFlags(&eCorr, cudaEventDisableTiming);

    const int TB = 256;
    const int nbN = (NNODES + TB - 1) / TB;
    const int nbE = (NEDGES + TB - 1) / TB;
    const int nbM = (NNODES + 127) / 128;
    const int nbA = (NNODES + 7) / 8;
    const int P3N = 2 * HID * HID + HID * COUT;

    // ---- fork: preprocessing on s1, L0 GEMM path on capture stream ----
    cudaEventRecord(eFork1, 0);
    cudaStreamWaitEvent(s1, eFork1, 0);

    k_prepW<FIN, HID><<<(FIN * HID + TB - 1) / TB, TB>>>(W0, w0h, w0l);      // idx0
    k_zero_init<<<nbN, TB, 0, s1>>>();                                        // idx1
    k_count<<<nbE, TB, 0, s1>>>(ei);                                          // idx2
    k_tgemm512<FIN, HID, true><<<nbM, 512, SM_BIG>>>(x, nullptr,
                                                     w0h, w0l, tmp);          // idx3 (profiled)
    k_scan1<<<SCAN_NB, SCAN_TPB, 0, s1>>>();
    k_scan2<<<1, 64, 0, s1>>>();
    k_scan3<<<SCAN_NB, SCAN_TPB, 0, s1>>>();
    k_fill<<<nbE, TB, 0, s1>>>(ei);
    k_prepW3x<<<(P3N + TB - 1) / TB, TB, 0, s1>>>(W1, W2, W3);
    cudaEventRecord(ePre, s1);
    cudaStreamWaitEvent(0, ePre, 0);

    // layer 0 aggregation -> relu'd fp16 h0
    k_agg128s<false><<<nbA, TB>>>(tmp, hf, ph, pl);
    // layer 1
    k_tgemm512<HID, HID, false><<<nbM, 512, SM_BIG>>>(nullptr, hf, w1h, w1l, tmp);
    k_agg128s<false><<<nbA, TB>>>(tmp, hf, ph, pl);
    // layer 2 (pre-relu h2 kept for corr_2)
    k_tgemm512<HID, HID, false><<<nbM, 512, SM_BIG>>>(nullptr, hf, w2h, w2l, tmp);
    k_agg128s<true><<<nbA, TB>>>(tmp, hf, ph, pl);

    // ---- fork: corr_2 metric (s1) concurrent with layer-3 chain (s0) ----
    cudaEventRecord(eFork2, 0);
    cudaStreamWaitEvent(s1, eFork2, 0);
    k_zero_G<<<(HID * HID + TB - 1) / TB, TB, 0, s1>>>();
    k_gram_split<<<296, 256, 0, s1>>>(ph, pl);
    k_finalize<HID><<<1, 256, 0, s1>>>(out + NNODES * COUT);
    cudaEventRecord(eCorr, s1);

    // layer 3: relu(h2) @ W3 -> agg directly into d_out
    k_tgemm512<HID, COUT, false><<<nbM, 512, SM_SML>>>(nullptr, hf, w3h, w3l, tmp);
    k_agg64h<<<nbA, TB>>>(tmp, out);

    // final corr on h3
    cudaStreamWaitEvent(0, eCorr, 0);
    k_zero_G<<<(HID * HID + TB - 1) / TB, TB>>>();
    k_gram_mma<COUT><<<296, 256>>>(out);
    k_finalize<COUT><<<1, 256>>>(out + NNODES * COUT + 1);
}

// round 11
// speedup vs baseline: 1.1280x; 1.0112x over previous
#include <cuda_runtime.h>
#include <cuda_bf16.h>
#include <cuda_fp16.h>
#include <math.h>
#include <stdint.h>

#define NNODES 100000
#define NEDGES 1600000
#define FIN 256
#define HID 128
#define COUT 64

#define SCAN_TPB 256
#define SCAN_ELEMS 8
#define SCAN_CHUNK (SCAN_TPB * SCAN_ELEMS)                 // 2048
#define SCAN_NB ((NNODES + SCAN_CHUNK - 1) / SCAN_CHUNK)   // 49

// ---------------- scratch (static __device__, no allocation) ----------------
__device__ __half g_tmp[NNODES * HID];          // messages (GEMM out), fp16
__device__ __half g_hf[NNODES * HID];           // relu'd h, fp16 (GEMM A input)
__device__ __nv_bfloat16 g_ph[NNODES * HID];    // pre-relu h2, hi split (gram)
__device__ __nv_bfloat16 g_pl[NNODES * HID];    // pre-relu h2, lo split
__device__ float g_dinv[NNODES];
__device__ int   g_cnt[NNODES];
__device__ int   g_cursor[NNODES];
__device__ int   g_rowptr[NNODES + 1];
__device__ int   g_col[NEDGES];
__device__ float g_w[NEDGES];
__device__ float g_G[HID * HID];
__device__ float g_csum[HID];
__device__ int   g_bsum[SCAN_NB];

// split-fp16 transposed weights: Wt[d][k] = W[k][d]
__device__ __half g_w0h[HID * FIN],  g_w0l[HID * FIN];
__device__ __half g_w1h[HID * HID],  g_w1l[HID * HID];
__device__ __half g_w2h[HID * HID],  g_w2l[HID * HID];
__device__ __half g_w3h[COUT * HID], g_w3l[COUT * HID];

// ---------------- helpers ----------------
__device__ __forceinline__ uint32_t smem_u32(const void* p) {
    uint32_t a;
    asm("{ .reg .u64 t; cvta.to.shared.u64 t, %1; cvt.u32.u64 %0, t; }"
        : "=r"(a) : "l"(p));
    return a;
}
__device__ __forceinline__ uint32_t sw128(uint32_t off) {
    return off ^ ((off >> 3) & 0x70);
}
__device__ __forceinline__ void ldsm4(uint32_t* r, uint32_t addr) {
    asm volatile("ldmatrix.sync.aligned.m8n8.x4.shared.b16 {%0,%1,%2,%3}, [%4];"
                 : "=r"(r[0]), "=r"(r[1]), "=r"(r[2]), "=r"(r[3]) : "r"(addr));
}
// fp16 mma: D(f32) += A(f16) * B(f16)
__device__ __forceinline__ void mma_h(float* c, const uint32_t* a,
                                      const uint32_t* b) {
    asm volatile(
        "mma.sync.aligned.m16n8k16.row.col.f32.f16.f16.f32 "
        "{%0,%1,%2,%3}, {%4,%5,%6,%7}, {%8,%9}, {%0,%1,%2,%3};"
        : "+f"(c[0]), "+f"(c[1]), "+f"(c[2]), "+f"(c[3])
        : "r"(a[0]), "r"(a[1]), "r"(a[2]), "r"(a[3]), "r"(b[0]), "r"(b[1]));
}
__device__ __forceinline__ void mma_bf(float* c, const uint32_t* a,
                                       const uint32_t* b) {
    asm volatile(
        "mma.sync.aligned.m16n8k16.row.col.f32.bf16.bf16.f32 "
        "{%0,%1,%2,%3}, {%4,%5,%6,%7}, {%8,%9}, {%0,%1,%2,%3};"
        : "+f"(c[0]), "+f"(c[1]), "+f"(c[2]), "+f"(c[3])
        : "r"(a[0]), "r"(a[1]), "r"(a[2]), "r"(a[3]), "r"(b[0]), "r"(b[1]));
}
__device__ __forceinline__ void split2b(float f, __nv_bfloat16& h, __nv_bfloat16& l) {
    h = __float2bfloat16_rn(f);
    l = __float2bfloat16_rn(f - __bfloat162float(h));
}
__device__ __forceinline__ void split2h(float f, __half& h, __half& l) {
    h = __float2half_rn(f);
    l = __float2half_rn(f - __half2float(h));
}
__device__ __forceinline__ void cpa16(uint32_t dst, const void* src, int nbytes) {
    asm volatile("cp.async.cg.shared.global [%0], [%1], 16, %2;"
                 :: "r"(dst), "l"(src), "r"(nbytes) : "memory");
}
__device__ __forceinline__ void cpa_commit() {
    asm volatile("cp.async.commit_group;" ::: "memory");
}
__device__ __forceinline__ void cpa_wait1() {
    asm volatile("cp.async.wait_group 1;" ::: "memory");
}
__device__ __forceinline__ void cpa_wait0() {
    asm volatile("cp.async.wait_group 0;" ::: "memory");
}

// ---------------- preprocessing ----------------
__global__ void k_zero_init() {
    int i = blockIdx.x * blockDim.x + threadIdx.x;
    if (i < NNODES) { g_cnt[i] = 0; g_cursor[i] = 0; }
}

__global__ void k_zero_G() {
    int i = blockIdx.x * blockDim.x + threadIdx.x;
    if (i < HID * HID) g_G[i] = 0.f;
    if (i < HID) g_csum[i] = 0.f;
}

__global__ void k_count(const int* __restrict__ ei) {
    int e = blockIdx.x * blockDim.x + threadIdx.x;
    if (e < NEDGES) atomicAdd(&g_cnt[ei[e]], 1);
}

__global__ void k_scan1() {
    __shared__ int warp_s[SCAN_TPB / 32];
    int tid = threadIdx.x, blk = blockIdx.x;
    int base = blk * SCAN_CHUNK + tid * SCAN_ELEMS;
    int s = 0;
#pragma unroll
    for (int i = 0; i < SCAN_ELEMS; i++) {
        int idx = base + i;
        if (idx < NNODES) {
            int c = g_cnt[idx];
            s += c;
            g_dinv[idx] = rsqrtf((float)(c + 1));  // +1 self loop
        }
    }
    for (int o = 16; o > 0; o >>= 1) s += __shfl_down_sync(0xffffffffu, s, o);
    if ((tid & 31) == 0) warp_s[tid >> 5] = s;
    __syncthreads();
    if (tid < SCAN_TPB / 32) {
        int w = warp_s[tid];
        for (int o = (SCAN_TPB / 64); o > 0; o >>= 1)
            w += __shfl_down_sync(0xffu, w, o);
        if (tid == 0) g_bsum[blk] = w;
    }
}

__global__ void k_scan2() {
    __shared__ int sh[64];
    int tid = threadIdx.x;
    sh[tid] = (tid < SCAN_NB) ? g_bsum[tid] : 0;
    __syncthreads();
    for (int o = 1; o < 64; o <<= 1) {
        int v = (tid >= o) ? sh[tid - o] : 0;
        __syncthreads();
        sh[tid] += v;
        __syncthreads();
    }
    if (tid < SCAN_NB) g_bsum[tid] = (tid == 0) ? 0 : sh[tid - 1];
    if (tid == 0) g_rowptr[NNODES] = sh[SCAN_NB - 1];
}

__global__ void k_scan3() {
    __shared__ int tsum[SCAN_TPB];
    int tid = threadIdx.x, blk = blockIdx.x;
    int base = blk * SCAN_CHUNK + tid * SCAN_ELEMS;
    int c[SCAN_ELEMS];
    int s = 0;
#pragma unroll
    for (int i = 0; i < SCAN_ELEMS; i++) {
        int idx = base + i;
        c[i] = (idx < NNODES) ? g_cnt[idx] : 0;
        s += c[i];
    }
    tsum[tid] = s;
    __syncthreads();
    for (int o = 1; o < SCAN_TPB; o <<= 1) {
        int v = (tid >= o) ? tsum[tid - o] : 0;
        __syncthreads();
        tsum[tid] += v;
        __syncthreads();
    }
    int run = g_bsum[blk] + ((tid == 0) ? 0 : tsum[tid - 1]);
#pragma unroll
    for (int i = 0; i < SCAN_ELEMS; i++) {
        int idx = base + i;
        if (idx < NNODES) { g_rowptr[idx] = run; run += c[i]; }
    }
}

__global__ void k_fill(const int* __restrict__ ei) {
    int e = blockIdx.x * blockDim.x + threadIdx.x;
    if (e >= NEDGES) return;
    int r = ei[e];
    int c = ei[NEDGES + e];
    int pos = g_rowptr[r] + atomicAdd(&g_cursor[r], 1);
    g_col[pos] = c;
    g_w[pos] = g_dinv[r] * g_dinv[c];
}

// ---------------- weight prep: W[K,D] fp32 -> Wt hi/lo fp16 [D][K] ----------
template <int K, int D>
__global__ void k_prepW(const float* __restrict__ W,
                        __half* __restrict__ Wh, __half* __restrict__ Wl) {
    int i = blockIdx.x * blockDim.x + threadIdx.x;
    if (i >= K * D) return;
    int n = i / K, k = i % K;
    __half h, l;
    split2h(W[k * D + n], h, l);
    Wh[n * K + k] = h;
    Wl[n * K + k] = l;
}

__global__ void k_prepW3x(const float* __restrict__ W1,
                          const float* __restrict__ W2,
                          const float* __restrict__ W3) {
    int i = blockIdx.x * blockDim.x + threadIdx.x;
    const int S1 = HID * HID, S2 = 2 * HID * HID, S3 = 2 * HID * HID + HID * COUT;
    __half h, l;
    if (i < S1) {
        int n = i / HID, k = i % HID;
        split2h(W1[k * HID + n], h, l);
        g_w1h[n * HID + k] = h; g_w1l[n * HID + k] = l;
    } else if (i < S2) {
        int j = i - S1;
        int n = j / HID, k = j % HID;
        split2h(W2[k * HID + n], h, l);
        g_w2h[n * HID + k] = h; g_w2l[n * HID + k] = l;
    } else if (i < S3) {
        int j = i - S2;
        int n = j / HID, k = j % HID;
        split2h(W3[k * COUT + n], h, l);
        g_w3h[n * HID + k] = h; g_w3l[n * HID + k] = l;
    }
}

// ---------------- pipelined fp16-A / split-fp16-B GEMM ---------------------
// C[N,D] = A[N,K] @ W[K,D]; 512 threads (16 warps, 4x4); 2-stage ping-pong.
// MINB: min CTAs per SM (2 for steady-state layers -> 64-reg budget).
template <int K, int D, bool CONVERT, int MINB>
__global__ __launch_bounds__(512, MINB) void k_tgemm512(const float* __restrict__ Af,
                                                        const __half* __restrict__ Ah,
                                                        const __half* __restrict__ Bh,
                                                        const __half* __restrict__ Bl,
                                                        __half* __restrict__ C) {
    extern __shared__ __align__(1024) uint8_t smem[];
    const int CK = 64;
    const int NCH = K / CK;
    const int WN = D / 4;                // 32 or 16
    const int NT = WN / 8;               // 4 or 2
    const int STA = 128 * 128;           // 16KB A stage (single operand)
    const int SBB = D * 128;
    const int OFF_B = 2 * STA;

    uint32_t sb = smem_u32(smem);
    int tid = threadIdx.x, wid = tid >> 5, lane = tid & 31;
    int wm = wid & 3, wn = wid >> 2;
    int row0 = wm * 32;
    int col0 = wn * WN;
    int grow = blockIdx.x * 128;

    float acc[2][NT][4];
#pragma unroll
    for (int i = 0; i < 2; i++)
#pragma unroll
        for (int j = 0; j < NT; j++)
#pragma unroll
            for (int q = 0; q < 4; q++) acc[i][j][q] = 0.f;

    float4 pf[4];

    auto a_async = [&](int s, int ch) {
        int kk = ch * CK;
#pragma unroll
        for (int i = 0; i < 2; i++) {
            int u = tid + i * 512;
            int m = u >> 3, g = u & 7;
            int r = grow + m;
            int rc = (r < NNODES) ? r : 0;
            int nb = (r < NNODES) ? 16 : 0;
            uint32_t so = sw128((uint32_t)(m * 128 + g * 16));
            cpa16(sb + s * STA + so, &Ah[(size_t)rc * K + kk + g * 8], nb);
        }
    };
    auto b_async = [&](int s, int ch) {
        int kk = ch * CK;
#pragma unroll
        for (int i = 0; i < (D * 8 + 511) / 512; i++) {
            int u = tid + i * 512;
            if (u < D * 8) {
                int n = u >> 3, g = u & 7;
                uint32_t so = sw128((uint32_t)(n * 128 + g * 16));
                cpa16(sb + OFF_B + (2 * s) * SBB + so, &Bh[n * K + kk + g * 8], 16);
                cpa16(sb + OFF_B + (2 * s + 1) * SBB + so, &Bl[n * K + kk + g * 8], 16);
            }
        }
    };
    auto a_ldregs = [&](int ch) {
        int kk = ch * CK;
#pragma unroll
        for (int i = 0; i < 2; i++) {
            int u = tid + i * 512;
            int m = u >> 3, g = u & 7;
            int r = grow + m;
            pf[2 * i] = make_float4(0.f, 0.f, 0.f, 0.f);
            pf[2 * i + 1] = pf[2 * i];
            if (r < NNODES) {
                const float* p = &Af[(size_t)r * K + kk + g * 8];
                pf[2 * i] = *(const float4*)p;
                pf[2 * i + 1] = *(const float4*)(p + 4);
            }
        }
    };
    auto a_cvtsts = [&](int s) {
#pragma unroll
        for (int i = 0; i < 2; i++) {
            int u = tid + i * 512;
            int m = u >> 3, g = u & 7;
            uint32_t hp[4];
            __half2 h0 = __floats2half2_rn(pf[2 * i].x, pf[2 * i].y);
            __half2 h1 = __floats2half2_rn(pf[2 * i].z, pf[2 * i].w);
            __half2 h2 = __floats2half2_rn(pf[2 * i + 1].x, pf[2 * i + 1].y);
            __half2 h3 = __floats2half2_rn(pf[2 * i + 1].z, pf[2 * i + 1].w);
            hp[0] = *(uint32_t*)&h0; hp[1] = *(uint32_t*)&h1;
            hp[2] = *(uint32_t*)&h2; hp[3] = *(uint32_t*)&h3;
            uint32_t so = sw128((uint32_t)(m * 128 + g * 16));
            *(uint4*)(smem + s * STA + so) = make_uint4(hp[0], hp[1], hp[2], hp[3]);
        }
    };

    if (CONVERT) { a_ldregs(0); a_cvtsts(0); }
    else a_async(0, 0);
    b_async(0, 0);
    cpa_commit();

    for (int ch = 0; ch < NCH; ch++) {
        int cur = ch & 1, nxt = cur ^ 1;
        bool more = (ch + 1 < NCH);
        if (more) {
            if (CONVERT) a_ldregs(ch + 1);
            else a_async(nxt, ch + 1);
            b_async(nxt, ch + 1);
            cpa_commit();
        }
        if (more) cpa_wait1(); else cpa_wait0();
        __syncthreads();
        {
            uint32_t aB = sb + cur * STA;
            uint32_t bB0 = sb + OFF_B + (2 * cur) * SBB;
            uint32_t bB1 = sb + OFF_B + (2 * cur + 1) * SBB;
#pragma unroll
            for (int k16 = 0; k16 < CK / 16; k16++) {
                int kb = k16 * 32;
                uint32_t ah[2][4];
#pragma unroll
                for (int mt = 0; mt < 2; mt++) {
                    int r = row0 + mt * 16 + (lane & 15);
                    int cb = kb + ((lane & 16) ? 16 : 0);
                    uint32_t so = sw128((uint32_t)(r * 128 + cb));
                    ldsm4(ah[mt], aB + so);
                }
#pragma unroll
                for (int bt = 0; bt < NT / 2; bt++) {
                    int n = col0 + bt * 16 + (lane & 7) + ((lane & 16) ? 8 : 0);
                    int cb = kb + ((lane & 8) ? 16 : 0);
                    uint32_t so = sw128((uint32_t)(n * 128 + cb));
                    uint32_t bh[4], bl[4];
                    ldsm4(bh, bB0 + so);
                    ldsm4(bl, bB1 + so);
#pragma unroll
                    for (int h = 0; h < 2; h++) {
                        int nt = bt * 2 + h;
#pragma unroll
                        for (int mt = 0; mt < 2; mt++) {
                            mma_h(acc[mt][nt], ah[mt], &bh[h * 2]);
                            mma_h(acc[mt][nt], ah[mt], &bl[h * 2]);
                        }
                    }
                }
            }
        }
        if (more && CONVERT) a_cvtsts(nxt);
        __syncthreads();
    }

#pragma unroll
    for (int mt = 0; mt < 2; mt++) {
        int r0 = grow + row0 + mt * 16 + (lane >> 2);
        int r1 = r0 + 8;
#pragma unroll
        for (int nt = 0; nt < NT; nt++) {
            int cc = col0 + nt * 8 + (lane & 3) * 2;
            if (r0 < NNODES)
                *(__half2*)&C[(size_t)r0 * D + cc] =
                    __floats2half2_rn(acc[mt][nt][0], acc[mt][nt][1]);
            if (r1 < NNODES)
                *(__half2*)&C[(size_t)r1 * D + cc] =
                    __floats2half2_rn(acc[mt][nt][2], acc[mt][nt][3]);
        }
    }
}

// ---------------- sparse aggregation (fp16 gather, fp32 accumulate) --------
// h[i] = dinv[i]^2*tmp[i] + sum_e w_e*tmp[col_e]; writes relu(h) as fp16 hf;
// PRE also stores pre-relu split-bf16 (gram operand). 8-wide edge unroll.
template <bool PRE>
__global__ void k_agg128s(const __half* __restrict__ tmp,
                          __half* __restrict__ hf,
                          __nv_bfloat16* __restrict__ ph,
                          __nv_bfloat16* __restrict__ pl) {
    int gw = (blockIdx.x * blockDim.x + threadIdx.x) >> 5;
    int lane = threadIdx.x & 31;
    if (gw >= NNODES) return;
    const uint2* __restrict__ t = (const uint2*)tmp;
    float di = g_dinv[gw];
    float s = di * di;
    uint2 u = t[gw * 32 + lane];
    float2 p0 = __half22float2(*(__half2*)&u.x);
    float2 p1 = __half22float2(*(__half2*)&u.y);
    float4 acc = make_float4(p0.x * s, p0.y * s, p1.x * s, p1.y * s);
    float4 acc2 = make_float4(0.f, 0.f, 0.f, 0.f);
    int e = g_rowptr[gw], en = g_rowptr[gw + 1];
    for (; e + 7 < en; e += 8) {
        int cidx[8];
        float wv[8];
        uint2 v[8];
#pragma unroll
        for (int j = 0; j < 8; j++) { cidx[j] = g_col[e + j]; wv[j] = g_w[e + j]; }
#pragma unroll
        for (int j = 0; j < 8; j++) v[j] = t[cidx[j] * 32 + lane];
#pragma unroll
        for (int j = 0; j < 8; j++) {
            float2 f0 = __half22float2(*(__half2*)&v[j].x);
            float2 f1 = __half22float2(*(__half2*)&v[j].y);
            if (j & 1) {
                acc2.x = fmaf(wv[j], f0.x, acc2.x); acc2.y = fmaf(wv[j], f0.y, acc2.y);
                acc2.z = fmaf(wv[j], f1.x, acc2.z); acc2.w = fmaf(wv[j], f1.y, acc2.w);
            } else {
                acc.x = fmaf(wv[j], f0.x, acc.x); acc.y = fmaf(wv[j], f0.y, acc.y);
                acc.z = fmaf(wv[j], f1.x, acc.z); acc.w = fmaf(wv[j], f1.y, acc.w);
            }
        }
    }
    for (; e + 1 < en; e += 2) {
        int c0 = g_col[e], c1 = g_col[e + 1];
        float w0 = g_w[e], w1 = g_w[e + 1];
        uint2 a = t[c0 * 32 + lane];
        uint2 b = t[c1 * 32 + lane];
        float2 a0 = __half22float2(*(__half2*)&a.x), a1 = __half22float2(*(__half2*)&a.y);
        float2 b0 = __half22float2(*(__half2*)&b.x), b1 = __half22float2(*(__half2*)&b.y);
        acc.x = fmaf(w0, a0.x, acc.x);   acc.y = fmaf(w0, a0.y, acc.y);
        acc.z = fmaf(w0, a1.x, acc.z);   acc.w = fmaf(w0, a1.y, acc.w);
        acc2.x = fmaf(w1, b0.x, acc2.x); acc2.y = fmaf(w1, b0.y, acc2.y);
        acc2.z = fmaf(w1, b1.x, acc2.z); acc2.w = fmaf(w1, b1.y, acc2.w);
    }
    if (e < en) {
        int c0 = g_col[e];
        float w0 = g_w[e];
        uint2 a = t[c0 * 32 + lane];
        float2 a0 = __half22float2(*(__half2*)&a.x);
        float2 a1 = __half22float2(*(__half2*)&a.y);
        acc.x = fmaf(w0, a0.x, acc.x); acc.y = fmaf(w0, a0.y, acc.y);
        acc.z = fmaf(w0, a1.x, acc.z); acc.w = fmaf(w0, a1.y, acc.w);
    }
    acc.x += acc2.x; acc.y += acc2.y; acc.z += acc2.z; acc.w += acc2.w;

    size_t base = (size_t)gw * HID + lane * 4;
    if (PRE) {
        float f[4] = {acc.x, acc.y, acc.z, acc.w};
        ushort hh[4], ll[4];
#pragma unroll
        for (int j = 0; j < 4; j++) {
            __nv_bfloat16 h, l;
            split2b(f[j], h, l);
            hh[j] = __bfloat16_as_ushort(h);
            ll[j] = __bfloat16_as_ushort(l);
        }
        *(uint2*)&ph[base] = make_uint2((uint32_t)hh[0] | ((uint32_t)hh[1] << 16),
                                        (uint32_t)hh[2] | ((uint32_t)hh[3] << 16));
        *(uint2*)&pl[base] = make_uint2((uint32_t)ll[0] | ((uint32_t)ll[1] << 16),
                                        (uint32_t)ll[2] | ((uint32_t)ll[3] << 16));
    }
    __half2 r0 = __floats2half2_rn(fmaxf(acc.x, 0.f), fmaxf(acc.y, 0.f));
    __half2 r1 = __floats2half2_rn(fmaxf(acc.z, 0.f), fmaxf(acc.w, 0.f));
    *(uint2*)&hf[base] = make_uint2(*(uint32_t*)&r0, *(uint32_t*)&r1);
}

__global__ void k_agg64h(const __half* __restrict__ tmp, float* __restrict__ out) {
    int gw = (blockIdx.x * blockDim.x + threadIdx.x) >> 5;
    int lane = threadIdx.x & 31;
    if (gw >= NNODES) return;
    const uint32_t* __restrict__ t = (const uint32_t*)tmp;
    float di = g_dinv[gw];
    float s = di * di;
    uint32_t u = t[gw * 32 + lane];
    float2 p = __half22float2(*(__half2*)&u);
    float2 acc = make_float2(p.x * s, p.y * s);
    float2 acc2 = make_float2(0.f, 0.f);
    int e = g_rowptr[gw], en = g_rowptr[gw + 1];
    for (; e + 7 < en; e += 8) {
        int cidx[8];
        float wv[8];
        uint32_t v[8];
#pragma unroll
        for (int j = 0; j < 8; j++) { cidx[j] = g_col[e + j]; wv[j] = g_w[e + j]; }
#pragma unroll
        for (int j = 0; j < 8; j++) v[j] = t[cidx[j] * 32 + lane];
#pragma unroll
        for (int j = 0; j < 8; j++) {
            float2 f = __half22float2(*(__half2*)&v[j]);
            if (j & 1) {
                acc2.x = fmaf(wv[j], f.x, acc2.x); acc2.y = fmaf(wv[j], f.y, acc2.y);
            } else {
                acc.x = fmaf(wv[j], f.x, acc.x); acc.y = fmaf(wv[j], f.y, acc.y);
            }
        }
    }
    for (; e < en; e++) {
        int c0 = g_col[e];
        float w0 = g_w[e];
        uint32_t a = t[c0 * 32 + lane];
        float2 af = __half22float2(*(__half2*)&a);
        acc.x = fmaf(w0, af.x, acc.x); acc.y = fmaf(w0, af.y, acc.y);
    }
    acc.x += acc2.x; acc.y += acc2.y;
    ((float2*)out)[gw * 32 + lane] = acc;
}

// ---------------- Gram via mma from pre-split bf16 h2 (D=128) ---------------
__global__ __launch_bounds__(256) void k_gram_split(const __nv_bfloat16* __restrict__ ph,
                                                    const __nv_bfloat16* __restrict__ pl) {
    const int D = HID;
    __shared__ __align__(1024) uint8_t sm[2 * D * 128];
    const int OFF_L = D * 128;
    const int FG = D / 4;
    const int PAIRS = 256 / FG;
    const int NT = D / 8;
    const int MW = D / 16;
    uint32_t sb = smem_u32(sm);
    int tid = threadIdx.x, wid = tid >> 5, lane = tid & 31;
    int f4 = tid % FG;
    int rp0 = tid / FG;

    float acc[NT][4];
#pragma unroll
    for (int j = 0; j < NT; j++)
#pragma unroll
        for (int q = 0; q < 4; q++) acc[j][q] = 0.f;
    float cs0 = 0.f, cs1 = 0.f, cs2 = 0.f, cs3 = 0.f;

    const int NCHUNK = (NNODES + 63) / 64;
    for (int ch = blockIdx.x; ch < NCHUNK; ch += gridDim.x) {
        int rbase = ch * 64;
#pragma unroll
        for (int it = 0; it < 32 / PAIRS; it++) {
            int pr = rp0 + it * PAIRS;
            int r0 = rbase + pr * 2, r1 = r0 + 1;
            uint2 h0v = make_uint2(0, 0), h1v = h0v, l0v = h0v, l1v = h0v;
            if (r0 < NNODES) {
                h0v = *(const uint2*)&ph[(size_t)r0 * D + f4 * 4];
                l0v = *(const uint2*)&pl[(size_t)r0 * D + f4 * 4];
            }
            if (r1 < NNODES) {
                h1v = *(const uint2*)&ph[(size_t)r1 * D + f4 * 4];
                l1v = *(const uint2*)&pl[(size_t)r1 * D + f4 * 4];
            }
            const ushort* h0s = (const ushort*)&h0v;
            const ushort* h1s = (const ushort*)&h1v;
            const ushort* l0s = (const ushort*)&l0v;
            const ushort* l1s = (const ushort*)&l1v;
            float fs[4];
#pragma unroll
            for (int j = 0; j < 4; j++) {
                fs[j] = __bfloat162float(__ushort_as_bfloat16(h0s[j]))
                      + __bfloat162float(__ushort_as_bfloat16(l0s[j]))
                      + __bfloat162float(__ushort_as_bfloat16(h1s[j]))
                      + __bfloat162float(__ushort_as_bfloat16(l1s[j]));
                int feat = f4 * 4 + j;
                uint32_t hp = (uint32_t)h0s[j] | ((uint32_t)h1s[j] << 16);
                uint32_t lp = (uint32_t)l0s[j] | ((uint32_t)l1s[j] << 16);
                uint32_t so = sw128((uint32_t)(feat * 128 + pr * 4));
                *(uint32_t*)(sm + so) = hp;
                *(uint32_t*)(sm + OFF_L + so) = lp;
            }
            cs0 += fs[0]; cs1 += fs[1]; cs2 += fs[2]; cs3 += fs[3];
        }
        __syncthreads();
        if (wid < MW) {
#pragma unroll
            for (int k16 = 0; k16 < 4; k16++) {
                int kb = k16 * 32;
                uint32_t ah[4], al[4];
                {
                    int r = wid * 16 + (lane & 15);
                    int cb = kb + ((lane & 16) ? 16 : 0);
                    uint32_t so = sw128((uint32_t)(r * 128 + cb));
                    ldsm4(ah, sb + so);
                    ldsm4(al, sb + OFF_L + so);
                }
#pragma unroll
                for (int bt = 0; bt < NT / 2; bt++) {
                    int n = bt * 16 + (lane & 7) + ((lane & 16) ? 8 : 0);
                    int cb = kb + ((lane & 8) ? 16 : 0);
                    uint32_t so = sw128((uint32_t)(n * 128 + cb));
                    uint32_t bh[4], bl[4];
                    ldsm4(bh, sb + so);
                    ldsm4(bl, sb + OFF_L + so);
#pragma unroll
                    for (int hh = 0; hh < 2; hh++) {
                        int nt = bt * 2 + hh;
                        mma_bf(acc[nt], ah, &bh[hh * 2]);
                        mma_bf(acc[nt], ah, &bl[hh * 2]);
                        mma_bf(acc[nt], al, &bh[hh * 2]);
                    }
                }
            }
        }
        __syncthreads();
    }
    if (wid < MW) {
        int mrow = wid * 16 + (lane >> 2);
#pragma unroll
        for (int nt = 0; nt < NT; nt++) {
            int c = nt * 8 + (lane & 3) * 2;
            atomicAdd(&g_G[mrow * D + c], acc[nt][0]);
            atomicAdd(&g_G[mrow * D + c + 1], acc[nt][1]);
            atomicAdd(&g_G[(mrow + 8) * D + c], acc[nt][2]);
            atomicAdd(&g_G[(mrow + 8) * D + c + 1], acc[nt][3]);
        }
    }
    atomicAdd(&g_csum[f4 * 4 + 0], cs0);
    atomicAdd(&g_csum[f4 * 4 + 1], cs1);
    atomicAdd(&g_csum[f4 * 4 + 2], cs2);
    atomicAdd(&g_csum[f4 * 4 + 3], cs3);
}

// ---------------- Gram via mma from fp32 (D=64, for h3/out) -----------------
template <int D>
__global__ __launch_bounds__(256) void k_gram_mma(const float* __restrict__ h) {
    __shared__ __align__(1024) uint8_t sm[2 * D * 128];
    const int OFF_L = D * 128;
    const int FG = D / 4;
    const int PAIRS = 256 / FG;
    const int NT = D / 8;
    const int MW = D / 16;
    uint32_t sb = smem_u32(sm);
    int tid = threadIdx.x, wid = tid >> 5, lane = tid & 31;
    int f4 = tid % FG;
    int rp0 = tid / FG;

    float acc[NT][4];
#pragma unroll
    for (int j = 0; j < NT; j++)
#pragma unroll
        for (int q = 0; q < 4; q++) acc[j][q] = 0.f;
    float cs0 = 0.f, cs1 = 0.f, cs2 = 0.f, cs3 = 0.f;

    const int NCHUNK = (NNODES + 63) / 64;
    for (int ch = blockIdx.x; ch < NCHUNK; ch += gridDim.x) {
        int rbase = ch * 64;
#pragma unroll
        for (int it = 0; it < 32 / PAIRS; it++) {
            int pr = rp0 + it * PAIRS;
            int r0 = rbase + pr * 2, r1 = r0 + 1;
            float4 v0 = make_float4(0.f, 0.f, 0.f, 0.f), v1 = v0;
            if (r0 < NNODES) v0 = *(const float4*)&h[(size_t)r0 * D + f4 * 4];
            if (r1 < NNODES) v1 = *(const float4*)&h[(size_t)r1 * D + f4 * 4];
            cs0 += v0.x + v1.x; cs1 += v0.y + v1.y;
            cs2 += v0.z + v1.z; cs3 += v0.w + v1.w;
            float a0[4] = {v0.x, v0.y, v0.z, v0.w};
            float a1[4] = {v1.x, v1.y, v1.z, v1.w};
#pragma unroll
            for (int j = 0; j < 4; j++) {
                int feat = f4 * 4 + j;
                __nv_bfloat16 h0, l0, h1, l1;
                split2b(a0[j], h0, l0);
                split2b(a1[j], h1, l1);
                uint32_t hp = (uint32_t)__bfloat16_as_ushort(h0)
                            | ((uint32_t)__bfloat16_as_ushort(h1) << 16);
                uint32_t lp = (uint32_t)__bfloat16_as_ushort(l0)
                            | ((uint32_t)__bfloat16_as_ushort(l1) << 16);
                uint32_t so = sw128((uint32_t)(feat * 128 + pr * 4));
                *(uint32_t*)(sm + so) = hp;
                *(uint32_t*)(sm + OFF_L + so) = lp;
            }
        }
        __syncthreads();
        if (wid < MW) {
#pragma unroll
            for (int k16 = 0; k16 < 4; k16++) {
                int kb = k16 * 32;
                uint32_t ah[4], al[4];
                {
                    int r = wid * 16 + (lane & 15);
                    int cb = kb + ((lane & 16) ? 16 : 0);
                    uint32_t so = sw128((uint32_t)(r * 128 + cb));
                    ldsm4(ah, sb + so);
                    ldsm4(al, sb + OFF_L + so);
                }
#pragma unroll
                for (int bt = 0; bt < NT / 2; bt++) {
                    int n = bt * 16 + (lane & 7) + ((lane & 16) ? 8 : 0);
                    int cb = kb + ((lane & 8) ? 16 : 0);
                    uint32_t so = sw128((uint32_t)(n * 128 + cb));
                    uint32_t bh[4], bl[4];
                    ldsm4(bh, sb + so);
                    ldsm4(bl, sb + OFF_L + so);
#pragma unroll
                    for (int hh = 0; hh < 2; hh++) {
                        int nt = bt * 2 + hh;
                        mma_bf(acc[nt], ah, &bh[hh * 2]);
                        mma_bf(acc[nt], ah, &bl[hh * 2]);
                        mma_bf(acc[nt], al, &bh[hh * 2]);
                    }
                }
            }
        }
        __syncthreads();
    }
    if (wid < MW) {
        int mrow = wid * 16 + (lane >> 2);
#pragma unroll
        for (int nt = 0; nt < NT; nt++) {
            int c = nt * 8 + (lane & 3) * 2;
            atomicAdd(&g_G[mrow * D + c], acc[nt][0]);
            atomicAdd(&g_G[mrow * D + c + 1], acc[nt][1]);
            atomicAdd(&g_G[(mrow + 8) * D + c], acc[nt][2]);
            atomicAdd(&g_G[(mrow + 8) * D + c + 1], acc[nt][3]);
        }
    }
    atomicAdd(&g_csum[f4 * 4 + 0], cs0);
    atomicAdd(&g_csum[f4 * 4 + 1], cs1);
    atomicAdd(&g_csum[f4 * 4 + 2], cs2);
    atomicAdd(&g_csum[f4 * 4 + 3], cs3);
}

// ---------------- correlation metric finalize (single block) ----------------
template <int D>
__global__ void k_finalize(float* __restrict__ dst) {
    __shared__ float sd[D];
    __shared__ float red[256];
    int tid = threadIdx.x;
    const float invN = 1.0f / (float)NNODES;
    if (tid < D) {
        float cjj = g_G[tid * D + tid] - g_csum[tid] * g_csum[tid] * invN;
        sd[tid] = sqrtf(fmaxf(cjj, 1e-12f));
    }
    __syncthreads();
    float sum = 0.f;
    for (int idx = tid; idx < D * D; idx += 256) {
        int j = idx / D, k = idx % D;
        if (k > j) {
            float cov = g_G[idx] - g_csum[j] * g_csum[k] * invN;
            sum += fabsf(cov / (sd[j] * sd[k]));
        }
    }
    red[tid] = sum;
    __syncthreads();
    for (int off = 128; off > 0; off >>= 1) {
        if (tid < off) red[tid] += red[tid + off];
        __syncthreads();
    }
    if (tid == 0) *dst = red[0] / (float)(D * (D - 1) / 2);
}

// ---------------- launch ----------------
extern "C" void kernel_launch(void* const* d_in, const int* in_sizes, int n_in,
                              void* d_out, int out_size) {
    const float* x  = (const float*)d_in[0];
    const int*   ei = (const int*)d_in[1];
    const float* W0 = (const float*)d_in[2];
    const float* W1 = (const float*)d_in[3];
    const float* W2 = (const float*)d_in[4];
    const float* W3 = (const float*)d_in[5];
    float* out = (float*)d_out;

    __half *tmp, *hf;
    __nv_bfloat16 *ph, *pl;
    cudaGetSymbolAddress((void**)&tmp, g_tmp);
    cudaGetSymbolAddress((void**)&hf, g_hf);
    cudaGetSymbolAddress((void**)&ph, g_ph);
    cudaGetSymbolAddress((void**)&pl, g_pl);
    __half *w0h, *w0l, *w1h, *w1l, *w2h, *w2l, *w3h, *w3l;
    cudaGetSymbolAddress((void**)&w0h, g_w0h); cudaGetSymbolAddress((void**)&w0l, g_w0l);
    cudaGetSymbolAddress((void**)&w1h, g_w1h); cudaGetSymbolAddress((void**)&w1l, g_w1l);
    cudaGetSymbolAddress((void**)&w2h, g_w2h); cudaGetSymbolAddress((void**)&w2l, g_w2l);
    cudaGetSymbolAddress((void**)&w3h, g_w3h); cudaGetSymbolAddress((void**)&w3l, g_w3l);

    const int SM_BIG = 2 * 128 * 128 + 4 * HID * 128;   // 98304
    const int SM_SML = 2 * 128 * 128 + 4 * COUT * 128;  // 65536
    cudaFuncSetAttribute((const void*)k_tgemm512<FIN, HID, true, 1>,
                         cudaFuncAttributeMaxDynamicSharedMemorySize, SM_BIG);
    cudaFuncSetAttribute((const void*)k_tgemm512<HID, HID, false, 2>,
                         cudaFuncAttributeMaxDynamicSharedMemorySize, SM_BIG);
    cudaFuncSetAttribute((const void*)k_tgemm512<HID, COUT, false, 2>,
                         cudaFuncAttributeMaxDynamicSharedMemorySize, SM_SML);

    // side stream + events for fork/join inside graph capture (leaked, bounded)
    cudaStream_t s1;
    cudaStreamCreateWithFlags(&s1, cudaStreamNonBlocking);
    cudaEvent_t eFork1, ePre, eFork2, eCorr;
    cudaEventCreateWithFlags(&eFork1, cudaEventDisableTiming);
    cudaEventCreateWithFlags(&ePre,  cudaEventDisableTiming);
    cudaEventCreateWithFlags(&eFork2, cudaEventDisableTiming);
    cudaEventCreateWithFlags(&eCorr, cudaEventDisableTiming);

    const int TB = 256;
    const int nbN = (NNODES + TB - 1) / TB;
    const int nbE = (NEDGES + TB - 1) / TB;
    const int nbM = (NNODES + 127) / 128;
    const int nbA = (NNODES + 7) / 8;
    const int P3N = 2 * HID * HID + HID * COUT;

    // ---- fork: preprocessing on s1, L0 GEMM path on capture stream ----
    cudaEventRecord(eFork1, 0);
    cudaStreamWaitEvent(s1, eFork1, 0);

    k_prepW<FIN, HID><<<(FIN * HID + TB - 1) / TB, TB>>>(W0, w0h, w0l);      // idx0
    k_zero_init<<<nbN, TB, 0, s1>>>();                                        // idx1
    k_count<<<nbE, TB, 0, s1>>>(ei);                                          // idx2
    k_tgemm512<FIN, HID, true, 1><<<nbM, 512, SM_BIG>>>(x, nullptr,
                                                        w0h, w0l, tmp);       // idx3 (profiled)
    k_scan1<<<SCAN_NB, SCAN_TPB, 0, s1>>>();
    k_scan2<<<1, 64, 0, s1>>>();
    k_scan3<<<SCAN_NB, SCAN_TPB, 0, s1>>>();
    k_fill<<<nbE, TB, 0, s1>>>(ei);
    k_prepW3x<<<(P3N + TB - 1) / TB, TB, 0, s1>>>(W1, W2, W3);
    cudaEventRecord(ePre, s1);
    cudaStreamWaitEvent(0, ePre, 0);

    // layer 0 aggregation -> relu'd fp16 h0
    k_agg128s<false><<<nbA, TB>>>(tmp, hf, ph, pl);
    // layer 1
    k_tgemm512<HID, HID, false, 2><<<nbM, 512, SM_BIG>>>(nullptr, hf, w1h, w1l, tmp);
    k_agg128s<false><<<nbA, TB>>>(tmp, hf, ph, pl);
    // layer 2 (pre-relu h2 kept for corr_2)
    k_tgemm512<HID, HID, false, 2><<<nbM, 512, SM_BIG>>>(nullptr, hf, w2h, w2l, tmp);
    k_agg128s<true><<<nbA, TB>>>(tmp, hf, ph, pl);

    // ---- fork: corr_2 metric (s1) concurrent with layer-3 chain (s0) ----
    cudaEventRecord(eFork2, 0);
    cudaStreamWaitEvent(s1, eFork2, 0);
    k_zero_G<<<(HID * HID + TB - 1) / TB, TB, 0, s1>>>();
    k_gram_split<<<296, 256, 0, s1>>>(ph, pl);
    k_finalize<HID><<<1, 256, 0, s1>>>(out + NNODES * COUT);
    cudaEventRecord(eCorr, s1);

    // layer 3: relu(h2) @ W3 -> agg directly into d_out
    k_tgemm512<HID, COUT, false, 2><<<nbM, 512, SM_SML>>>(nullptr, hf, w3h, w3l, tmp);
    k_agg64h<<<nbA, TB>>>(tmp, out);

    // final corr on h3
    cudaStreamWaitEvent(0, eCorr, 0);
    k_zero_G<<<(HID * HID + TB - 1) / TB, TB>>>();
    k_gram_mma<COUT><<<296, 256>>>(out);
    k_finalize<COUT><<<1, 256>>>(out + NNODES * COUT + 1);
}

// round 12
// speedup vs baseline: 1.1327x; 1.0041x over previous
#include <cuda_runtime.h>
#include <cuda_bf16.h>
#include <cuda_fp16.h>
#include <math.h>
#include <stdint.h>

#define NNODES 100000
#define NEDGES 1600000
#define FIN 256
#define HID 128
#define COUT 64

#define SCAN_TPB 256
#define SCAN_ELEMS 8
#define SCAN_CHUNK (SCAN_TPB * SCAN_ELEMS)                 // 2048
#define SCAN_NB ((NNODES + SCAN_CHUNK - 1) / SCAN_CHUNK)   // 49

// ---------------- scratch (static __device__, no allocation) ----------------
__device__ __half g_tmp[NNODES * HID];          // messages (GEMM out), fp16
__device__ __half g_hf[NNODES * HID];           // relu'd h, fp16 (GEMM A input)
__device__ __nv_bfloat16 g_ph[NNODES * HID];    // pre-relu h2, hi split (gram)
__device__ __nv_bfloat16 g_pl[NNODES * HID];    // pre-relu h2, lo split
__device__ float g_dinv[NNODES];
__device__ int   g_cnt[NNODES];
__device__ int   g_cursor[NNODES];
__device__ int   g_rowptr[NNODES + 1];
__device__ int   g_col[NEDGES];
__device__ float g_w[NEDGES];
__device__ float g_G[HID * HID];
__device__ float g_csum[HID];
__device__ int   g_bsum[SCAN_NB];

// split-fp16 transposed weights: Wt[d][k] = W[k][d]
__device__ __half g_w0h[HID * FIN],  g_w0l[HID * FIN];
__device__ __half g_w1h[HID * HID],  g_w1l[HID * HID];
__device__ __half g_w2h[HID * HID],  g_w2l[HID * HID];
__device__ __half g_w3h[COUT * HID], g_w3l[COUT * HID];

// ---------------- helpers ----------------
__device__ __forceinline__ uint32_t smem_u32(const void* p) {
    uint32_t a;
    asm("{ .reg .u64 t; cvta.to.shared.u64 t, %1; cvt.u32.u64 %0, t; }"
        : "=r"(a) : "l"(p));
    return a;
}
__device__ __forceinline__ uint32_t sw128(uint32_t off) {
    return off ^ ((off >> 3) & 0x70);
}
__device__ __forceinline__ void ldsm4(uint32_t* r, uint32_t addr) {
    asm volatile("ldmatrix.sync.aligned.m8n8.x4.shared.b16 {%0,%1,%2,%3}, [%4];"
                 : "=r"(r[0]), "=r"(r[1]), "=r"(r[2]), "=r"(r[3]) : "r"(addr));
}
__device__ __forceinline__ void mma_h(float* c, const uint32_t* a,
                                      const uint32_t* b) {
    asm volatile(
        "mma.sync.aligned.m16n8k16.row.col.f32.f16.f16.f32 "
        "{%0,%1,%2,%3}, {%4,%5,%6,%7}, {%8,%9}, {%0,%1,%2,%3};"
        : "+f"(c[0]), "+f"(c[1]), "+f"(c[2]), "+f"(c[3])
        : "r"(a[0]), "r"(a[1]), "r"(a[2]), "r"(a[3]), "r"(b[0]), "r"(b[1]));
}
__device__ __forceinline__ void mma_bf(float* c, const uint32_t* a,
                                       const uint32_t* b) {
    asm volatile(
        "mma.sync.aligned.m16n8k16.row.col.f32.bf16.bf16.f32 "
        "{%0,%1,%2,%3}, {%4,%5,%6,%7}, {%8,%9}, {%0,%1,%2,%3};"
        : "+f"(c[0]), "+f"(c[1]), "+f"(c[2]), "+f"(c[3])
        : "r"(a[0]), "r"(a[1]), "r"(a[2]), "r"(a[3]), "r"(b[0]), "r"(b[1]));
}
__device__ __forceinline__ void split2b(float f, __nv_bfloat16& h, __nv_bfloat16& l) {
    h = __float2bfloat16_rn(f);
    l = __float2bfloat16_rn(f - __bfloat162float(h));
}
__device__ __forceinline__ void split2h(float f, __half& h, __half& l) {
    h = __float2half_rn(f);
    l = __float2half_rn(f - __half2float(h));
}
__device__ __forceinline__ void cpa16(uint32_t dst, const void* src, int nbytes) {
    asm volatile("cp.async.cg.shared.global [%0], [%1], 16, %2;"
                 :: "r"(dst), "l"(src), "r"(nbytes) : "memory");
}
__device__ __forceinline__ void cpa_commit() {
    asm volatile("cp.async.commit_group;" ::: "memory");
}
__device__ __forceinline__ void cpa_wait1() {
    asm volatile("cp.async.wait_group 1;" ::: "memory");
}
__device__ __forceinline__ void cpa_wait0() {
    asm volatile("cp.async.wait_group 0;" ::: "memory");
}

// ---------------- preprocessing ----------------
__global__ void k_count(const int* __restrict__ ei) {
    int e = blockIdx.x * blockDim.x + threadIdx.x;
    if (e < NEDGES) atomicAdd(&g_cnt[ei[e]], 1);
}

__global__ void k_scan1() {
    __shared__ int warp_s[SCAN_TPB / 32];
    int tid = threadIdx.x, blk = blockIdx.x;
    int base = blk * SCAN_CHUNK + tid * SCAN_ELEMS;
    int s = 0;
#pragma unroll
    for (int i = 0; i < SCAN_ELEMS; i++) {
        int idx = base + i;
        if (idx < NNODES) {
            int c = g_cnt[idx];
            s += c;
            g_dinv[idx] = rsqrtf((float)(c + 1));  // +1 self loop
        }
    }
    for (int o = 16; o > 0; o >>= 1) s += __shfl_down_sync(0xffffffffu, s, o);
    if ((tid & 31) == 0) warp_s[tid >> 5] = s;
    __syncthreads();
    if (tid < SCAN_TPB / 32) {
        int w = warp_s[tid];
        for (int o = (SCAN_TPB / 64); o > 0; o >>= 1)
            w += __shfl_down_sync(0xffu, w, o);
        if (tid == 0) g_bsum[blk] = w;
    }
}

__global__ void k_scan2() {
    __shared__ int sh[64];
    int tid = threadIdx.x;
    sh[tid] = (tid < SCAN_NB) ? g_bsum[tid] : 0;
    __syncthreads();
    for (int o = 1; o < 64; o <<= 1) {
        int v = (tid >= o) ? sh[tid - o] : 0;
        __syncthreads();
        sh[tid] += v;
        __syncthreads();
    }
    if (tid < SCAN_NB) g_bsum[tid] = (tid == 0) ? 0 : sh[tid - 1];
    if (tid == 0) g_rowptr[NNODES] = sh[SCAN_NB - 1];
}

__global__ void k_scan3() {
    __shared__ int tsum[SCAN_TPB];
    int tid = threadIdx.x, blk = blockIdx.x;
    int base = blk * SCAN_CHUNK + tid * SCAN_ELEMS;
    int c[SCAN_ELEMS];
    int s = 0;
#pragma unroll
    for (int i = 0; i < SCAN_ELEMS; i++) {
        int idx = base + i;
        c[i] = (idx < NNODES) ? g_cnt[idx] : 0;
        s += c[i];
    }
    tsum[tid] = s;
    __syncthreads();
    for (int o = 1; o < SCAN_TPB; o <<= 1) {
        int v = (tid >= o) ? tsum[tid - o] : 0;
        __syncthreads();
        tsum[tid] += v;
        __syncthreads();
    }
    int run = g_bsum[blk] + ((tid == 0) ? 0 : tsum[tid - 1]);
#pragma unroll
    for (int i = 0; i < SCAN_ELEMS; i++) {
        int idx = base + i;
        if (idx < NNODES) { g_rowptr[idx] = run; run += c[i]; }
    }
}

__global__ void k_fill(const int* __restrict__ ei) {
    int e = blockIdx.x * blockDim.x + threadIdx.x;
    if (e >= NEDGES) return;
    int r = ei[e];
    int c = ei[NEDGES + e];
    int pos = g_rowptr[r] + atomicAdd(&g_cursor[r], 1);
    g_col[pos] = c;
    g_w[pos] = g_dinv[r] * g_dinv[c];
}

// ---------------- weight prep: W[K,D] fp32 -> Wt hi/lo fp16 [D][K] ----------
template <int K, int D>
__global__ void k_prepW(const float* __restrict__ W,
                        __half* __restrict__ Wh, __half* __restrict__ Wl) {
    int i = blockIdx.x * blockDim.x + threadIdx.x;
    if (i >= K * D) return;
    int n = i / K, k = i % K;
    __half h, l;
    split2h(W[k * D + n], h, l);
    Wh[n * K + k] = h;
    Wl[n * K + k] = l;
}

__global__ void k_prepW3x(const float* __restrict__ W1,
                          const float* __restrict__ W2,
                          const float* __restrict__ W3) {
    int i = blockIdx.x * blockDim.x + threadIdx.x;
    const int S1 = HID * HID, S2 = 2 * HID * HID, S3 = 2 * HID * HID + HID * COUT;
    __half h, l;
    if (i < S1) {
        int n = i / HID, k = i % HID;
        split2h(W1[k * HID + n], h, l);
        g_w1h[n * HID + k] = h; g_w1l[n * HID + k] = l;
    } else if (i < S2) {
        int j = i - S1;
        int n = j / HID, k = j % HID;
        split2h(W2[k * HID + n], h, l);
        g_w2h[n * HID + k] = h; g_w2l[n * HID + k] = l;
    } else if (i < S3) {
        int j = i - S2;
        int n = j / HID, k = j % HID;
        split2h(W3[k * COUT + n], h, l);
        g_w3h[n * HID + k] = h; g_w3l[n * HID + k] = l;
    }
}

// ---------------- fp16-A / split-fp16-B GEMM --------------------------------
// C[N,D] = A[N,K] @ W[K,D]; 512 threads (16 warps, 4x4).
// K<=128 non-convert: SINGLE-SHOT (all tiles loaded once, no mid-loop syncs).
// K=256 convert (layer 0): 2-stage ping-pong with register prefetch.
template <int K, int D, bool CONVERT, int MINB>
__global__ __launch_bounds__(512, MINB) void k_tgemm512(const float* __restrict__ Af,
                                                        const __half* __restrict__ Ah,
                                                        const __half* __restrict__ Bh,
                                                        const __half* __restrict__ Bl,
                                                        __half* __restrict__ C) {
    extern __shared__ __align__(1024) uint8_t smem[];
    const int CK = 64;
    const int NCH = K / CK;
    const int WN = D / 4;                // 32 or 16
    const int NT = WN / 8;               // 4 or 2
    const int STA = 128 * 128;           // 16KB A stage per chunk
    const int SBB = D * 128;
    const bool SINGLE = (!CONVERT) && (NCH <= 2);
    const int NSTA = SINGLE ? NCH : 2;   // A stages resident
    const int OFF_B = NSTA * STA;

    uint32_t sb = smem_u32(smem);
    int tid = threadIdx.x, wid = tid >> 5, lane = tid & 31;
    int wm = wid & 3, wn = wid >> 2;
    int row0 = wm * 32;
    int col0 = wn * WN;
    int grow = blockIdx.x * 128;

    float acc[2][NT][4];
#pragma unroll
    for (int i = 0; i < 2; i++)
#pragma unroll
        for (int j = 0; j < NT; j++)
#pragma unroll
            for (int q = 0; q < 4; q++) acc[i][j][q] = 0.f;

    float4 pf[4];

    auto a_async = [&](int s, int ch) {
        int kk = ch * CK;
#pragma unroll
        for (int i = 0; i < 2; i++) {
            int u = tid + i * 512;
            int m = u >> 3, g = u & 7;
            int r = grow + m;
            int rc = (r < NNODES) ? r : 0;
            int nb = (r < NNODES) ? 16 : 0;
            uint32_t so = sw128((uint32_t)(m * 128 + g * 16));
            cpa16(sb + s * STA + so, &Ah[(size_t)rc * K + kk + g * 8], nb);
        }
    };
    auto b_async = [&](int s, int ch) {
        int kk = ch * CK;
#pragma unroll
        for (int i = 0; i < (D * 8 + 511) / 512; i++) {
            int u = tid + i * 512;
            if (u < D * 8) {
                int n = u >> 3, g = u & 7;
                uint32_t so = sw128((uint32_t)(n * 128 + g * 16));
                cpa16(sb + OFF_B + (2 * s) * SBB + so, &Bh[n * K + kk + g * 8], 16);
                cpa16(sb + OFF_B + (2 * s + 1) * SBB + so, &Bl[n * K + kk + g * 8], 16);
            }
        }
    };
    auto a_ldregs = [&](int ch) {
        int kk = ch * CK;
#pragma unroll
        for (int i = 0; i < 2; i++) {
            int u = tid + i * 512;
            int m = u >> 3, g = u & 7;
            int r = grow + m;
            pf[2 * i] = make_float4(0.f, 0.f, 0.f, 0.f);
            pf[2 * i + 1] = pf[2 * i];
            if (r < NNODES) {
                const float* p = &Af[(size_t)r * K + kk + g * 8];
                pf[2 * i] = *(const float4*)p;
                pf[2 * i + 1] = *(const float4*)(p + 4);
            }
        }
    };
    auto a_cvtsts = [&](int s) {
#pragma unroll
        for (int i = 0; i < 2; i++) {
            int u = tid + i * 512;
            int m = u >> 3, g = u & 7;
            uint32_t hp[4];
            __half2 h0 = __floats2half2_rn(pf[2 * i].x, pf[2 * i].y);
            __half2 h1 = __floats2half2_rn(pf[2 * i].z, pf[2 * i].w);
            __half2 h2 = __floats2half2_rn(pf[2 * i + 1].x, pf[2 * i + 1].y);
            __half2 h3 = __floats2half2_rn(pf[2 * i + 1].z, pf[2 * i + 1].w);
            hp[0] = *(uint32_t*)&h0; hp[1] = *(uint32_t*)&h1;
            hp[2] = *(uint32_t*)&h2; hp[3] = *(uint32_t*)&h3;
            uint32_t so = sw128((uint32_t)(m * 128 + g * 16));
            *(uint4*)(smem + s * STA + so) = make_uint4(hp[0], hp[1], hp[2], hp[3]);
        }
    };
    auto mma_stage = [&](int stA, int stB) {
        uint32_t aB = sb + stA * STA;
        uint32_t bB0 = sb + OFF_B + (2 * stB) * SBB;
        uint32_t bB1 = sb + OFF_B + (2 * stB + 1) * SBB;
#pragma unroll
        for (int k16 = 0; k16 < CK / 16; k16++) {
            int kb = k16 * 32;
            uint32_t ah[2][4];
#pragma unroll
            for (int mt = 0; mt < 2; mt++) {
                int r = row0 + mt * 16 + (lane & 15);
                int cb = kb + ((lane & 16) ? 16 : 0);
                uint32_t so = sw128((uint32_t)(r * 128 + cb));
                ldsm4(ah[mt], aB + so);
            }
#pragma unroll
            for (int bt = 0; bt < NT / 2; bt++) {
                int n = col0 + bt * 16 + (lane & 7) + ((lane & 16) ? 8 : 0);
                int cb = kb + ((lane & 8) ? 16 : 0);
                uint32_t so = sw128((uint32_t)(n * 128 + cb));
                uint32_t bh[4], bl[4];
                ldsm4(bh, bB0 + so);
                ldsm4(bl, bB1 + so);
#pragma unroll
                for (int h = 0; h < 2; h++) {
                    int nt = bt * 2 + h;
#pragma unroll
                    for (int mt = 0; mt < 2; mt++) {
                        mma_h(acc[mt][nt], ah[mt], &bh[h * 2]);
                        mma_h(acc[mt][nt], ah[mt], &bl[h * 2]);
                    }
                }
            }
        }
    };

    if (SINGLE) {
        // ---- single-shot: everything resident, one wait, one sync ----
#pragma unroll
        for (int s = 0; s < NCH; s++) { a_async(s, s); b_async(s, s); }
        cpa_commit();
        cpa_wait0();
        __syncthreads();
#pragma unroll
        for (int ch = 0; ch < NCH; ch++) mma_stage(ch, ch);
    } else {
        // ---- 2-stage ping-pong (layer 0: fp32 convert path) ----
        if (CONVERT) { a_ldregs(0); a_cvtsts(0); }
        else a_async(0, 0);
        b_async(0, 0);
        cpa_commit();
        for (int ch = 0; ch < NCH; ch++) {
            int cur = ch & 1, nxt = cur ^ 1;
            bool more = (ch + 1 < NCH);
            if (more) {
                if (CONVERT) a_ldregs(ch + 1);
                else a_async(nxt, ch + 1);
                b_async(nxt, ch + 1);
                cpa_commit();
            }
            if (more) cpa_wait1(); else cpa_wait0();
            __syncthreads();
            mma_stage(cur, cur);
            if (more && CONVERT) a_cvtsts(nxt);
            __syncthreads();
        }
    }

#pragma unroll
    for (int mt = 0; mt < 2; mt++) {
        int r0 = grow + row0 + mt * 16 + (lane >> 2);
        int r1 = r0 + 8;
#pragma unroll
        for (int nt = 0; nt < NT; nt++) {
            int cc = col0 + nt * 8 + (lane & 3) * 2;
            if (r0 < NNODES)
                *(__half2*)&C[(size_t)r0 * D + cc] =
                    __floats2half2_rn(acc[mt][nt][0], acc[mt][nt][1]);
            if (r1 < NNODES)
                *(__half2*)&C[(size_t)r1 * D + cc] =
                    __floats2half2_rn(acc[mt][nt][2], acc[mt][nt][3]);
        }
    }
}

// ---------------- sparse aggregation (fp16 gather, fp32 accumulate) --------
template <bool PRE>
__global__ void k_agg128s(const __half* __restrict__ tmp,
                          __half* __restrict__ hf,
                          __nv_bfloat16* __restrict__ ph,
                          __nv_bfloat16* __restrict__ pl) {
    int gw = (blockIdx.x * blockDim.x + threadIdx.x) >> 5;
    int lane = threadIdx.x & 31;
    if (gw >= NNODES) return;
    const uint2* __restrict__ t = (const uint2*)tmp;
    float di = g_dinv[gw];
    float s = di * di;
    uint2 u = t[gw * 32 + lane];
    float2 p0 = __half22float2(*(__half2*)&u.x);
    float2 p1 = __half22float2(*(__half2*)&u.y);
    float4 acc = make_float4(p0.x * s, p0.y * s, p1.x * s, p1.y * s);
    float4 acc2 = make_float4(0.f, 0.f, 0.f, 0.f);
    int e = g_rowptr[gw], en = g_rowptr[gw + 1];
    for (; e + 7 < en; e += 8) {
        int cidx[8];
        float wv[8];
        uint2 v[8];
#pragma unroll
        for (int j = 0; j < 8; j++) { cidx[j] = g_col[e + j]; wv[j] = g_w[e + j]; }
#pragma unroll
        for (int j = 0; j < 8; j++) v[j] = t[cidx[j] * 32 + lane];
#pragma unroll
        for (int j = 0; j < 8; j++) {
            float2 f0 = __half22float2(*(__half2*)&v[j].x);
            float2 f1 = __half22float2(*(__half2*)&v[j].y);
            if (j & 1) {
                acc2.x = fmaf(wv[j], f0.x, acc2.x); acc2.y = fmaf(wv[j], f0.y, acc2.y);
                acc2.z = fmaf(wv[j], f1.x, acc2.z); acc2.w = fmaf(wv[j], f1.y, acc2.w);
            } else {
                acc.x = fmaf(wv[j], f0.x, acc.x); acc.y = fmaf(wv[j], f0.y, acc.y);
                acc.z = fmaf(wv[j], f1.x, acc.z); acc.w = fmaf(wv[j], f1.y, acc.w);
            }
        }
    }
    for (; e + 1 < en; e += 2) {
        int c0 = g_col[e], c1 = g_col[e + 1];
        float w0 = g_w[e], w1 = g_w[e + 1];
        uint2 a = t[c0 * 32 + lane];
        uint2 b = t[c1 * 32 + lane];
        float2 a0 = __half22float2(*(__half2*)&a.x), a1 = __half22float2(*(__half2*)&a.y);
        float2 b0 = __half22float2(*(__half2*)&b.x), b1 = __half22float2(*(__half2*)&b.y);
        acc.x = fmaf(w0, a0.x, acc.x);   acc.y = fmaf(w0, a0.y, acc.y);
        acc.z = fmaf(w0, a1.x, acc.z);   acc.w = fmaf(w0, a1.y, acc.w);
        acc2.x = fmaf(w1, b0.x, acc2.x); acc2.y = fmaf(w1, b0.y, acc2.y);
        acc2.z = fmaf(w1, b1.x, acc2.z); acc2.w = fmaf(w1, b1.y, acc2.w);
    }
    if (e < en) {
        int c0 = g_col[e];
        float w0 = g_w[e];
        uint2 a = t[c0 * 32 + lane];
        float2 a0 = __half22float2(*(__half2*)&a.x);
        float2 a1 = __half22float2(*(__half2*)&a.y);
        acc.x = fmaf(w0, a0.x, acc.x); acc.y = fmaf(w0, a0.y, acc.y);
        acc.z = fmaf(w0, a1.x, acc.z); acc.w = fmaf(w0, a1.y, acc.w);
    }
    acc.x += acc2.x; acc.y += acc2.y; acc.z += acc2.z; acc.w += acc2.w;

    size_t base = (size_t)gw * HID + lane * 4;
    if (PRE) {
        float f[4] = {acc.x, acc.y, acc.z, acc.w};
        ushort hh[4], ll[4];
#pragma unroll
        for (int j = 0; j < 4; j++) {
            __nv_bfloat16 h, l;
            split2b(f[j], h, l);
            hh[j] = __bfloat16_as_ushort(h);
            ll[j] = __bfloat16_as_ushort(l);
        }
        *(uint2*)&ph[base] = make_uint2((uint32_t)hh[0] | ((uint32_t)hh[1] << 16),
                                        (uint32_t)hh[2] | ((uint32_t)hh[3] << 16));
        *(uint2*)&pl[base] = make_uint2((uint32_t)ll[0] | ((uint32_t)ll[1] << 16),
                                        (uint32_t)ll[2] | ((uint32_t)ll[3] << 16));
    }
    __half2 r0 = __floats2half2_rn(fmaxf(acc.x, 0.f), fmaxf(acc.y, 0.f));
    __half2 r1 = __floats2half2_rn(fmaxf(acc.z, 0.f), fmaxf(acc.w, 0.f));
    *(uint2*)&hf[base] = make_uint2(*(uint32_t*)&r0, *(uint32_t*)&r1);
}

__global__ void k_agg64h(const __half* __restrict__ tmp, float* __restrict__ out) {
    int gw = (blockIdx.x * blockDim.x + threadIdx.x) >> 5;
    int lane = threadIdx.x & 31;
    if (gw >= NNODES) return;
    const uint32_t* __restrict__ t = (const uint32_t*)tmp;
    float di = g_dinv[gw];
    float s = di * di;
    uint32_t u = t[gw * 32 + lane];
    float2 p = __half22float2(*(__half2*)&u);
    float2 acc = make_float2(p.x * s, p.y * s);
    float2 acc2 = make_float2(0.f, 0.f);
    int e = g_rowptr[gw], en = g_rowptr[gw + 1];
    for (; e + 7 < en; e += 8) {
        int cidx[8];
        float wv[8];
        uint32_t v[8];
#pragma unroll
        for (int j = 0; j < 8; j++) { cidx[j] = g_col[e + j]; wv[j] = g_w[e + j]; }
#pragma unroll
        for (int j = 0; j < 8; j++) v[j] = t[cidx[j] * 32 + lane];
#pragma unroll
        for (int j = 0; j < 8; j++) {
            float2 f = __half22float2(*(__half2*)&v[j]);
            if (j & 1) {
                acc2.x = fmaf(wv[j], f.x, acc2.x); acc2.y = fmaf(wv[j], f.y, acc2.y);
            } else {
                acc.x = fmaf(wv[j], f.x, acc.x); acc.y = fmaf(wv[j], f.y, acc.y);
            }
        }
    }
    for (; e < en; e++) {
        int c0 = g_col[e];
        float w0 = g_w[e];
        uint32_t a = t[c0 * 32 + lane];
        float2 af = __half22float2(*(__half2*)&a);
        acc.x = fmaf(w0, af.x, acc.x); acc.y = fmaf(w0, af.y, acc.y);
    }
    acc.x += acc2.x; acc.y += acc2.y;
    ((float2*)out)[gw * 32 + lane] = acc;
}

// ---------------- Gram via mma from pre-split bf16 h2 (D=128) ---------------
__global__ __launch_bounds__(256) void k_gram_split(const __nv_bfloat16* __restrict__ ph,
                                                    const __nv_bfloat16* __restrict__ pl) {
    const int D = HID;
    __shared__ __align__(1024) uint8_t sm[2 * D * 128];
    const int OFF_L = D * 128;
    const int FG = D / 4;
    const int PAIRS = 256 / FG;
    const int NT = D / 8;
    const int MW = D / 16;
    uint32_t sb = smem_u32(sm);
    int tid = threadIdx.x, wid = tid >> 5, lane = tid & 31;
    int f4 = tid % FG;
    int rp0 = tid / FG;

    float acc[NT][4];
#pragma unroll
    for (int j = 0; j < NT; j++)
#pragma unroll
        for (int q = 0; q < 4; q++) acc[j][q] = 0.f;
    float cs0 = 0.f, cs1 = 0.f, cs2 = 0.f, cs3 = 0.f;

    const int NCHUNK = (NNODES + 63) / 64;
    for (int ch = blockIdx.x; ch < NCHUNK; ch += gridDim.x) {
        int rbase = ch * 64;
#pragma unroll
        for (int it = 0; it < 32 / PAIRS; it++) {
            int pr = rp0 + it * PAIRS;
            int r0 = rbase + pr * 2, r1 = r0 + 1;
            uint2 h0v = make_uint2(0, 0), h1v = h0v, l0v = h0v, l1v = h0v;
            if (r0 < NNODES) {
                h0v = *(const uint2*)&ph[(size_t)r0 * D + f4 * 4];
                l0v = *(const uint2*)&pl[(size_t)r0 * D + f4 * 4];
            }
            if (r1 < NNODES) {
                h1v = *(const uint2*)&ph[(size_t)r1 * D + f4 * 4];
                l1v = *(const uint2*)&pl[(size_t)r1 * D + f4 * 4];
            }
            const ushort* h0s = (const ushort*)&h0v;
            const ushort* h1s = (const ushort*)&h1v;
            const ushort* l0s = (const ushort*)&l0v;
            const ushort* l1s = (const ushort*)&l1v;
            float fs[4];
#pragma unroll
            for (int j = 0; j < 4; j++) {
                fs[j] = __bfloat162float(__ushort_as_bfloat16(h0s[j]))
                      + __bfloat162float(__ushort_as_bfloat16(l0s[j]))
                      + __bfloat162float(__ushort_as_bfloat16(h1s[j]))
                      + __bfloat162float(__ushort_as_bfloat16(l1s[j]));
                int feat = f4 * 4 + j;
                uint32_t hp = (uint32_t)h0s[j] | ((uint32_t)h1s[j] << 16);
                uint32_t lp = (uint32_t)l0s[j] | ((uint32_t)l1s[j] << 16);
                uint32_t so = sw128((uint32_t)(feat * 128 + pr * 4));
                *(uint32_t*)(sm + so) = hp;
                *(uint32_t*)(sm + OFF_L + so) = lp;
            }
            cs0 += fs[0]; cs1 += fs[1]; cs2 += fs[2]; cs3 += fs[3];
        }
        __syncthreads();
        if (wid < MW) {
#pragma unroll
            for (int k16 = 0; k16 < 4; k16++) {
                int kb = k16 * 32;
                uint32_t ah[4], al[4];
                {
                    int r = wid * 16 + (lane & 15);
                    int cb = kb + ((lane & 16) ? 16 : 0);
                    uint32_t so = sw128((uint32_t)(r * 128 + cb));
                    ldsm4(ah, sb + so);
                    ldsm4(al, sb + OFF_L + so);
                }
#pragma unroll
                for (int bt = 0; bt < NT / 2; bt++) {
                    int n = bt * 16 + (lane & 7) + ((lane & 16) ? 8 : 0);
                    int cb = kb + ((lane & 8) ? 16 : 0);
                    uint32_t so = sw128((uint32_t)(n * 128 + cb));
                    uint32_t bh[4], bl[4];
                    ldsm4(bh, sb + so);
                    ldsm4(bl, sb + OFF_L + so);
#pragma unroll
                    for (int hh = 0; hh < 2; hh++) {
                        int nt = bt * 2 + hh;
                        mma_bf(acc[nt], ah, &bh[hh * 2]);
                        mma_bf(acc[nt], ah, &bl[hh * 2]);
                        mma_bf(acc[nt], al, &bh[hh * 2]);
                    }
                }
            }
        }
        __syncthreads();
    }
    if (wid < MW) {
        int mrow = wid * 16 + (lane >> 2);
#pragma unroll
        for (int nt = 0; nt < NT; nt++) {
            int c = nt * 8 + (lane & 3) * 2;
            atomicAdd(&g_G[mrow * D + c], acc[nt][0]);
            atomicAdd(&g_G[mrow * D + c + 1], acc[nt][1]);
            atomicAdd(&g_G[(mrow + 8) * D + c], acc[nt][2]);
            atomicAdd(&g_G[(mrow + 8) * D + c + 1], acc[nt][3]);
        }
    }
    atomicAdd(&g_csum[f4 * 4 + 0], cs0);
    atomicAdd(&g_csum[f4 * 4 + 1], cs1);
    atomicAdd(&g_csum[f4 * 4 + 2], cs2);
    atomicAdd(&g_csum[f4 * 4 + 3], cs3);
}

// ---------------- Gram via mma from fp32 (D=64, for h3/out) -----------------
template <int D>
__global__ __launch_bounds__(256) void k_gram_mma(const float* __restrict__ h) {
    __shared__ __align__(1024) uint8_t sm[2 * D * 128];
    const int OFF_L = D * 128;
    const int FG = D / 4;
    const int PAIRS = 256 / FG;
    const int NT = D / 8;
    const int MW = D / 16;
    uint32_t sb = smem_u32(sm);
    int tid = threadIdx.x, wid = tid >> 5, lane = tid & 31;
    int f4 = tid % FG;
    int rp0 = tid / FG;

    float acc[NT][4];
#pragma unroll
    for (int j = 0; j < NT; j++)
#pragma unroll
        for (int q = 0; q < 4; q++) acc[j][q] = 0.f;
    float cs0 = 0.f, cs1 = 0.f, cs2 = 0.f, cs3 = 0.f;

    const int NCHUNK = (NNODES + 63) / 64;
    for (int ch = blockIdx.x; ch < NCHUNK; ch += gridDim.x) {
        int rbase = ch * 64;
#pragma unroll
        for (int it = 0; it < 32 / PAIRS; it++) {
            int pr = rp0 + it * PAIRS;
            int r0 = rbase + pr * 2, r1 = r0 + 1;
            float4 v0 = make_float4(0.f, 0.f, 0.f, 0.f), v1 = v0;
            if (r0 < NNODES) v0 = *(const float4*)&h[(size_t)r0 * D + f4 * 4];
            if (r1 < NNODES) v1 = *(const float4*)&h[(size_t)r1 * D + f4 * 4];
            cs0 += v0.x + v1.x; cs1 += v0.y + v1.y;
            cs2 += v0.z + v1.z; cs3 += v0.w + v1.w;
            float a0[4] = {v0.x, v0.y, v0.z, v0.w};
            float a1[4] = {v1.x, v1.y, v1.z, v1.w};
#pragma unroll
            for (int j = 0; j < 4; j++) {
                int feat = f4 * 4 + j;
                __nv_bfloat16 h0, l0, h1, l1;
                split2b(a0[j], h0, l0);
                split2b(a1[j], h1, l1);
                uint32_t hp = (uint32_t)__bfloat16_as_ushort(h0)
                            | ((uint32_t)__bfloat16_as_ushort(h1) << 16);
                uint32_t lp = (uint32_t)__bfloat16_as_ushort(l0)
                            | ((uint32_t)__bfloat16_as_ushort(l1) << 16);
                uint32_t so = sw128((uint32_t)(feat * 128 + pr * 4));
                *(uint32_t*)(sm + so) = hp;
                *(uint32_t*)(sm + OFF_L + so) = lp;
            }
        }
        __syncthreads();
        if (wid < MW) {
#pragma unroll
            for (int k16 = 0; k16 < 4; k16++) {
                int kb = k16 * 32;
                uint32_t ah[4], al[4];
                {
                    int r = wid * 16 + (lane & 15);
                    int cb = kb + ((lane & 16) ? 16 : 0);
                    uint32_t so = sw128((uint32_t)(r * 128 + cb));
                    ldsm4(ah, sb + so);
                    ldsm4(al, sb + OFF_L + so);
                }
#pragma unroll
                for (int bt = 0; bt < NT / 2; bt++) {
                    int n = bt * 16 + (lane & 7) + ((lane & 16) ? 8 : 0);
                    int cb = kb + ((lane & 8) ? 16 : 0);
                    uint32_t so = sw128((uint32_t)(n * 128 + cb));
                    uint32_t bh[4], bl[4];
                    ldsm4(bh, sb + so);
                    ldsm4(bl, sb + OFF_L + so);
#pragma unroll
                    for (int hh = 0; hh < 2; hh++) {
                        int nt = bt * 2 + hh;
                        mma_bf(acc[nt], ah, &bh[hh * 2]);
                        mma_bf(acc[nt], ah, &bl[hh * 2]);
                        mma_bf(acc[nt], al, &bh[hh * 2]);
                    }
                }
            }
        }
        __syncthreads();
    }
    if (wid < MW) {
        int mrow = wid * 16 + (lane >> 2);
#pragma unroll
        for (int nt = 0; nt < NT; nt++) {
            int c = nt * 8 + (lane & 3) * 2;
            atomicAdd(&g_G[mrow * D + c], acc[nt][0]);
            atomicAdd(&g_G[mrow * D + c + 1], acc[nt][1]);
            atomicAdd(&g_G[(mrow + 8) * D + c], acc[nt][2]);
            atomicAdd(&g_G[(mrow + 8) * D + c + 1], acc[nt][3]);
        }
    }
    atomicAdd(&g_csum[f4 * 4 + 0], cs0);
    atomicAdd(&g_csum[f4 * 4 + 1], cs1);
    atomicAdd(&g_csum[f4 * 4 + 2], cs2);
    atomicAdd(&g_csum[f4 * 4 + 3], cs3);
}

// ---------------- correlation metric finalize (single block) ----------------
template <int D>
__global__ void k_finalize(float* __restrict__ dst) {
    __shared__ float sd[D];
    __shared__ float red[256];
    int tid = threadIdx.x;
    const float invN = 1.0f / (float)NNODES;
    if (tid < D) {
        float cjj = g_G[tid * D + tid] - g_csum[tid] * g_csum[tid] * invN;
        sd[tid] = sqrtf(fmaxf(cjj, 1e-12f));
    }
    __syncthreads();
    float sum = 0.f;
    for (int idx = tid; idx < D * D; idx += 256) {
        int j = idx / D, k = idx % D;
        if (k > j) {
            float cov = g_G[idx] - g_csum[j] * g_csum[k] * invN;
            sum += fabsf(cov / (sd[j] * sd[k]));
        }
    }
    red[tid] = sum;
    __syncthreads();
    for (int off = 128; off > 0; off >>= 1) {
        if (tid < off) red[tid] += red[tid + off];
        __syncthreads();
    }
    if (tid == 0) *dst = red[0] / (float)(D * (D - 1) / 2);
}

// ---------------- launch ----------------
extern "C" void kernel_launch(void* const* d_in, const int* in_sizes, int n_in,
                              void* d_out, int out_size) {
    const float* x  = (const float*)d_in[0];
    const int*   ei = (const int*)d_in[1];
    const float* W0 = (const float*)d_in[2];
    const float* W1 = (const float*)d_in[3];
    const float* W2 = (const float*)d_in[4];
    const float* W3 = (const float*)d_in[5];
    float* out = (float*)d_out;

    __half *tmp, *hf;
    __nv_bfloat16 *ph, *pl;
    cudaGetSymbolAddress((void**)&tmp, g_tmp);
    cudaGetSymbolAddress((void**)&hf, g_hf);
    cudaGetSymbolAddress((void**)&ph, g_ph);
    cudaGetSymbolAddress((void**)&pl, g_pl);
    __half *w0h, *w0l, *w1h, *w1l, *w2h, *w2l, *w3h, *w3l;
    cudaGetSymbolAddress((void**)&w0h, g_w0h); cudaGetSymbolAddress((void**)&w0l, g_w0l);
    cudaGetSymbolAddress((void**)&w1h, g_w1h); cudaGetSymbolAddress((void**)&w1l, g_w1l);
    cudaGetSymbolAddress((void**)&w2h, g_w2h); cudaGetSymbolAddress((void**)&w2l, g_w2l);
    cudaGetSymbolAddress((void**)&w3h, g_w3h); cudaGetSymbolAddress((void**)&w3l, g_w3l);
    int *cntp, *curp;
    float *Gp, *csp;
    cudaGetSymbolAddress((void**)&cntp, g_cnt);
    cudaGetSymbolAddress((void**)&curp, g_cursor);
    cudaGetSymbolAddress((void**)&Gp, g_G);
    cudaGetSymbolAddress((void**)&csp, g_csum);

    const int SM_BIG = 2 * 128 * 128 + 4 * HID * 128;   // 98304
    const int SM_SML = 2 * 128 * 128 + 4 * COUT * 128;  // 65536
    cudaFuncSetAttribute((const void*)k_tgemm512<FIN, HID, true, 1>,
                         cudaFuncAttributeMaxDynamicSharedMemorySize, SM_BIG);
    cudaFuncSetAttribute((const void*)k_tgemm512<HID, HID, false, 2>,
                         cudaFuncAttributeMaxDynamicSharedMemorySize, SM_BIG);
    cudaFuncSetAttribute((const void*)k_tgemm512<HID, COUT, false, 2>,
                         cudaFuncAttributeMaxDynamicSharedMemorySize, SM_SML);

    // side stream + events for fork/join inside graph capture (leaked, bounded)
    cudaStream_t s1;
    cudaStreamCreateWithFlags(&s1, cudaStreamNonBlocking);
    cudaEvent_t eFork1, ePre, eFork2, eCorr;
    cudaEventCreateWithFlags(&eFork1, cudaEventDisableTiming);
    cudaEventCreateWithFlags(&ePre,  cudaEventDisableTiming);
    cudaEventCreateWithFlags(&eFork2, cudaEventDisableTiming);
    cudaEventCreateWithFlags(&eCorr, cudaEventDisableTiming);

    const int TB = 256;
    const int nbE = (NEDGES + TB - 1) / TB;
    const int nbM = (NNODES + 127) / 128;
    const int nbA = (NNODES + 7) / 8;
    const int P3N = 2 * HID * HID + HID * COUT;

    // ---- fork: preprocessing on s1, L0 GEMM path on capture stream ----
    cudaEventRecord(eFork1, 0);
    cudaStreamWaitEvent(s1, eFork1, 0);

    k_prepW<FIN, HID><<<(FIN * HID + TB - 1) / TB, TB>>>(W0, w0h, w0l);
    cudaMemsetAsync(cntp, 0, NNODES * sizeof(int), s1);
    cudaMemsetAsync(curp, 0, NNODES * sizeof(int), s1);
    k_count<<<nbE, TB, 0, s1>>>(ei);
    k_tgemm512<FIN, HID, true, 1><<<nbM, 512, SM_BIG>>>(x, nullptr,
                                                        w0h, w0l, tmp);
    k_scan1<<<SCAN_NB, SCAN_TPB, 0, s1>>>();
    k_scan2<<<1, 64, 0, s1>>>();
    k_scan3<<<SCAN_NB, SCAN_TPB, 0, s1>>>();
    k_fill<<<nbE, TB, 0, s1>>>(ei);
    k_prepW3x<<<(P3N + TB - 1) / TB, TB, 0, s1>>>(W1, W2, W3);
    cudaEventRecord(ePre, s1);
    cudaStreamWaitEvent(0, ePre, 0);

    // layer 0 aggregation -> relu'd fp16 h0
    k_agg128s<false><<<nbA, TB>>>(tmp, hf, ph, pl);
    // layer 1
    k_tgemm512<HID, HID, false, 2><<<nbM, 512, SM_BIG>>>(nullptr, hf, w1h, w1l, tmp);
    k_agg128s<false><<<nbA, TB>>>(tmp, hf, ph, pl);
    // layer 2 (pre-relu h2 kept for corr_2)
    k_tgemm512<HID, HID, false, 2><<<nbM, 512, SM_BIG>>>(nullptr, hf, w2h, w2l, tmp);
    k_agg128s<true><<<nbA, TB>>>(tmp, hf, ph, pl);

    // ---- fork: corr_2 metric (s1) concurrent with layer-3 chain (s0) ----
    cudaEventRecord(eFork2, 0);
    cudaStreamWaitEvent(s1, eFork2, 0);
    cudaMemsetAsync(Gp, 0, HID * HID * sizeof(float), s1);
    cudaMemsetAsync(csp, 0, HID * sizeof(float), s1);
    k_gram_split<<<296, 256, 0, s1>>>(ph, pl);
    k_finalize<HID><<<1, 256, 0, s1>>>(out + NNODES * COUT);
    cudaEventRecord(eCorr, s1);

    // layer 3: relu(h2) @ W3 -> agg directly into d_out
    k_tgemm512<HID, COUT, false, 2><<<nbM, 512, SM_SML>>>(nullptr, hf, w3h, w3l, tmp);
    k_agg64h<<<nbA, TB>>>(tmp, out);

    // final corr on h3
    cudaStreamWaitEvent(0, eCorr, 0);
    cudaMemsetAsync(Gp, 0, HID * HID * sizeof(float), 0);
    cudaMemsetAsync(csp, 0, HID * sizeof(float), 0);
    k_gram_mma<COUT><<<296, 256>>>(out);
    k_finalize<COUT><<<1, 256>>>(out + NNODES * COUT + 1);
}

// round 13
// speedup vs baseline: 1.1816x; 1.0432x over previous
#include <cuda_runtime.h>
#include <cuda_bf16.h>
#include <cuda_fp16.h>
#include <math.h>
#include <stdint.h>

#define NNODES 100000
#define NEDGES 1600000
#define FIN 256
#define HID 128
#define COUT 64

#define SCAN_TPB 256
#define SCAN_ELEMS 8
#define SCAN_CHUNK (SCAN_TPB * SCAN_ELEMS)                 // 2048
#define SCAN_NB ((NNODES + SCAN_CHUNK - 1) / SCAN_CHUNK)   // 49

// ---------------- scratch (static __device__, no allocation) ----------------
__device__ __half g_tmp[NNODES * HID];          // messages (GEMM out), fp16
__device__ __half g_hf[NNODES * HID];           // relu'd h fp16 (GEMM A) / h3 fp16 copy
__device__ __half g_pf[NNODES * HID];           // pre-relu h2 fp16 (gram operand)
__device__ float g_dinv[NNODES];
__device__ int   g_cnt[NNODES];
__device__ int   g_cursor[NNODES];
__device__ int   g_rowptr[NNODES + 1];
__device__ int   g_col[NEDGES];
__device__ float g_w[NEDGES];
__device__ float g_G[HID * HID];
__device__ float g_csum[HID];
__device__ int   g_bsum[SCAN_NB];

// split-fp16 transposed weights: Wt[d][k] = W[k][d]
__device__ __half g_w0h[HID * FIN],  g_w0l[HID * FIN];
__device__ __half g_w1h[HID * HID],  g_w1l[HID * HID];
__device__ __half g_w2h[HID * HID],  g_w2l[HID * HID];
__device__ __half g_w3h[COUT * HID], g_w3l[COUT * HID];

// ---------------- helpers ----------------
__device__ __forceinline__ uint32_t smem_u32(const void* p) {
    uint32_t a;
    asm("{ .reg .u64 t; cvta.to.shared.u64 t, %1; cvt.u32.u64 %0, t; }"
        : "=r"(a) : "l"(p));
    return a;
}
__device__ __forceinline__ uint32_t sw128(uint32_t off) {
    return off ^ ((off >> 3) & 0x70);
}
__device__ __forceinline__ void ldsm4(uint32_t* r, uint32_t addr) {
    asm volatile("ldmatrix.sync.aligned.m8n8.x4.shared.b16 {%0,%1,%2,%3}, [%4];"
                 : "=r"(r[0]), "=r"(r[1]), "=r"(r[2]), "=r"(r[3]) : "r"(addr));
}
__device__ __forceinline__ void mma_h(float* c, const uint32_t* a,
                                      const uint32_t* b) {
    asm volatile(
        "mma.sync.aligned.m16n8k16.row.col.f32.f16.f16.f32 "
        "{%0,%1,%2,%3}, {%4,%5,%6,%7}, {%8,%9}, {%0,%1,%2,%3};"
        : "+f"(c[0]), "+f"(c[1]), "+f"(c[2]), "+f"(c[3])
        : "r"(a[0]), "r"(a[1]), "r"(a[2]), "r"(a[3]), "r"(b[0]), "r"(b[1]));
}
__device__ __forceinline__ void split2h(float f, __half& h, __half& l) {
    h = __float2half_rn(f);
    l = __float2half_rn(f - __half2float(h));
}
__device__ __forceinline__ void cpa16(uint32_t dst, const void* src, int nbytes) {
    asm volatile("cp.async.cg.shared.global [%0], [%1], 16, %2;"
                 :: "r"(dst), "l"(src), "r"(nbytes) : "memory");
}
__device__ __forceinline__ void cpa_commit() {
    asm volatile("cp.async.commit_group;" ::: "memory");
}
__device__ __forceinline__ void cpa_wait1() {
    asm volatile("cp.async.wait_group 1;" ::: "memory");
}
__device__ __forceinline__ void cpa_wait0() {
    asm volatile("cp.async.wait_group 0;" ::: "memory");
}

// ---------------- preprocessing ----------------
__global__ void k_count(const int* __restrict__ ei) {
    int e = blockIdx.x * blockDim.x + threadIdx.x;
    if (e < NEDGES) atomicAdd(&g_cnt[ei[e]], 1);
}

__global__ void k_scan1() {
    __shared__ int warp_s[SCAN_TPB / 32];
    int tid = threadIdx.x, blk = blockIdx.x;
    int base = blk * SCAN_CHUNK + tid * SCAN_ELEMS;
    int s = 0;
#pragma unroll
    for (int i = 0; i < SCAN_ELEMS; i++) {
        int idx = base + i;
        if (idx < NNODES) {
            int c = g_cnt[idx];
            s += c;
            g_dinv[idx] = rsqrtf((float)(c + 1));  // +1 self loop
        }
    }
    for (int o = 16; o > 0; o >>= 1) s += __shfl_down_sync(0xffffffffu, s, o);
    if ((tid & 31) == 0) warp_s[tid >> 5] = s;
    __syncthreads();
    if (tid < SCAN_TPB / 32) {
        int w = warp_s[tid];
        for (int o = (SCAN_TPB / 64); o > 0; o >>= 1)
            w += __shfl_down_sync(0xffu, w, o);
        if (tid == 0) g_bsum[blk] = w;
    }
}

__global__ void k_scan2() {
    __shared__ int sh[64];
    int tid = threadIdx.x;
    sh[tid] = (tid < SCAN_NB) ? g_bsum[tid] : 0;
    __syncthreads();
    for (int o = 1; o < 64; o <<= 1) {
        int v = (tid >= o) ? sh[tid - o] : 0;
        __syncthreads();
        sh[tid] += v;
        __syncthreads();
    }
    if (tid < SCAN_NB) g_bsum[tid] = (tid == 0) ? 0 : sh[tid - 1];
    if (tid == 0) g_rowptr[NNODES] = sh[SCAN_NB - 1];
}

__global__ void k_scan3() {
    __shared__ int tsum[SCAN_TPB];
    int tid = threadIdx.x, blk = blockIdx.x;
    int base = blk * SCAN_CHUNK + tid * SCAN_ELEMS;
    int c[SCAN_ELEMS];
    int s = 0;
#pragma unroll
    for (int i = 0; i < SCAN_ELEMS; i++) {
        int idx = base + i;
        c[i] = (idx < NNODES) ? g_cnt[idx] : 0;
        s += c[i];
    }
    tsum[tid] = s;
    __syncthreads();
    for (int o = 1; o < SCAN_TPB; o <<= 1) {
        int v = (tid >= o) ? tsum[tid - o] : 0;
        __syncthreads();
        tsum[tid] += v;
        __syncthreads();
    }
    int run = g_bsum[blk] + ((tid == 0) ? 0 : tsum[tid - 1]);
#pragma unroll
    for (int i = 0; i < SCAN_ELEMS; i++) {
        int idx = base + i;
        if (idx < NNODES) { g_rowptr[idx] = run; run += c[i]; }
    }
}

__global__ void k_fill(const int* __restrict__ ei) {
    int e = blockIdx.x * blockDim.x + threadIdx.x;
    if (e >= NEDGES) return;
    int r = ei[e];
    int c = ei[NEDGES + e];
    int pos = g_rowptr[r] + atomicAdd(&g_cursor[r], 1);
    g_col[pos] = c;
    g_w[pos] = g_dinv[r] * g_dinv[c];
}

// ---------------- weight prep: W[K,D] fp32 -> Wt hi/lo fp16 [D][K] ----------
template <int K, int D>
__global__ void k_prepW(const float* __restrict__ W,
                        __half* __restrict__ Wh, __half* __restrict__ Wl) {
    int i = blockIdx.x * blockDim.x + threadIdx.x;
    if (i >= K * D) return;
    int n = i / K, k = i % K;
    __half h, l;
    split2h(W[k * D + n], h, l);
    Wh[n * K + k] = h;
    Wl[n * K + k] = l;
}

__global__ void k_prepW3x(const float* __restrict__ W1,
                          const float* __restrict__ W2,
                          const float* __restrict__ W3) {
    int i = blockIdx.x * blockDim.x + threadIdx.x;
    const int S1 = HID * HID, S2 = 2 * HID * HID, S3 = 2 * HID * HID + HID * COUT;
    __half h, l;
    if (i < S1) {
        int n = i / HID, k = i % HID;
        split2h(W1[k * HID + n], h, l);
        g_w1h[n * HID + k] = h; g_w1l[n * HID + k] = l;
    } else if (i < S2) {
        int j = i - S1;
        int n = j / HID, k = j % HID;
        split2h(W2[k * HID + n], h, l);
        g_w2h[n * HID + k] = h; g_w2l[n * HID + k] = l;
    } else if (i < S3) {
        int j = i - S2;
        int n = j / HID, k = j % HID;
        split2h(W3[k * COUT + n], h, l);
        g_w3h[n * HID + k] = h; g_w3l[n * HID + k] = l;
    }
}

// ---------------- fp16-A / split-fp16-B GEMM --------------------------------
template <int K, int D, bool CONVERT, int MINB>
__global__ __launch_bounds__(512, MINB) void k_tgemm512(const float* __restrict__ Af,
                                                        const __half* __restrict__ Ah,
                                                        const __half* __restrict__ Bh,
                                                        const __half* __restrict__ Bl,
                                                        __half* __restrict__ C) {
    extern __shared__ __align__(1024) uint8_t smem[];
    const int CK = 64;
    const int NCH = K / CK;
    const int WN = D / 4;
    const int NT = WN / 8;
    const int STA = 128 * 128;
    const int SBB = D * 128;
    const bool SINGLE = (!CONVERT) && (NCH <= 2);
    const int NSTA = SINGLE ? NCH : 2;
    const int OFF_B = NSTA * STA;

    uint32_t sb = smem_u32(smem);
    int tid = threadIdx.x, wid = tid >> 5, lane = tid & 31;
    int wm = wid & 3, wn = wid >> 2;
    int row0 = wm * 32;
    int col0 = wn * WN;
    int grow = blockIdx.x * 128;

    float acc[2][NT][4];
#pragma unroll
    for (int i = 0; i < 2; i++)
#pragma unroll
        for (int j = 0; j < NT; j++)
#pragma unroll
            for (int q = 0; q < 4; q++) acc[i][j][q] = 0.f;

    float4 pf[4];

    auto a_async = [&](int s, int ch) {
        int kk = ch * CK;
#pragma unroll
        for (int i = 0; i < 2; i++) {
            int u = tid + i * 512;
            int m = u >> 3, g = u & 7;
            int r = grow + m;
            int rc = (r < NNODES) ? r : 0;
            int nb = (r < NNODES) ? 16 : 0;
            uint32_t so = sw128((uint32_t)(m * 128 + g * 16));
            cpa16(sb + s * STA + so, &Ah[(size_t)rc * K + kk + g * 8], nb);
        }
    };
    auto b_async = [&](int s, int ch) {
        int kk = ch * CK;
#pragma unroll
        for (int i = 0; i < (D * 8 + 511) / 512; i++) {
            int u = tid + i * 512;
            if (u < D * 8) {
                int n = u >> 3, g = u & 7;
                uint32_t so = sw128((uint32_t)(n * 128 + g * 16));
                cpa16(sb + OFF_B + (2 * s) * SBB + so, &Bh[n * K + kk + g * 8], 16);
                cpa16(sb + OFF_B + (2 * s + 1) * SBB + so, &Bl[n * K + kk + g * 8], 16);
            }
        }
    };
    auto a_ldregs = [&](int ch) {
        int kk = ch * CK;
#pragma unroll
        for (int i = 0; i < 2; i++) {
            int u = tid + i * 512;
            int m = u >> 3, g = u & 7;
            int r = grow + m;
            pf[2 * i] = make_float4(0.f, 0.f, 0.f, 0.f);
            pf[2 * i + 1] = pf[2 * i];
            if (r < NNODES) {
                const float* p = &Af[(size_t)r * K + kk + g * 8];
                pf[2 * i] = *(const float4*)p;
                pf[2 * i + 1] = *(const float4*)(p + 4);
            }
        }
    };
    auto a_cvtsts = [&](int s) {
#pragma unroll
        for (int i = 0; i < 2; i++) {
            int u = tid + i * 512;
            int m = u >> 3, g = u & 7;
            uint32_t hp[4];
            __half2 h0 = __floats2half2_rn(pf[2 * i].x, pf[2 * i].y);
            __half2 h1 = __floats2half2_rn(pf[2 * i].z, pf[2 * i].w);
            __half2 h2 = __floats2half2_rn(pf[2 * i + 1].x, pf[2 * i + 1].y);
            __half2 h3 = __floats2half2_rn(pf[2 * i + 1].z, pf[2 * i + 1].w);
            hp[0] = *(uint32_t*)&h0; hp[1] = *(uint32_t*)&h1;
            hp[2] = *(uint32_t*)&h2; hp[3] = *(uint32_t*)&h3;
            uint32_t so = sw128((uint32_t)(m * 128 + g * 16));
            *(uint4*)(smem + s * STA + so) = make_uint4(hp[0], hp[1], hp[2], hp[3]);
        }
    };
    auto mma_stage = [&](int stA, int stB) {
        uint32_t aB = sb + stA * STA;
        uint32_t bB0 = sb + OFF_B + (2 * stB) * SBB;
        uint32_t bB1 = sb + OFF_B + (2 * stB + 1) * SBB;
#pragma unroll
        for (int k16 = 0; k16 < CK / 16; k16++) {
            int kb = k16 * 32;
            uint32_t ah[2][4];
#pragma unroll
            for (int mt = 0; mt < 2; mt++) {
                int r = row0 + mt * 16 + (lane & 15);
                int cb = kb + ((lane & 16) ? 16 : 0);
                uint32_t so = sw128((uint32_t)(r * 128 + cb));
                ldsm4(ah[mt], aB + so);
            }
#pragma unroll
            for (int bt = 0; bt < NT / 2; bt++) {
                int n = col0 + bt * 16 + (lane & 7) + ((lane & 16) ? 8 : 0);
                int cb = kb + ((lane & 8) ? 16 : 0);
                uint32_t so = sw128((uint32_t)(n * 128 + cb));
                uint32_t bh[4], bl[4];
                ldsm4(bh, bB0 + so);
                ldsm4(bl, bB1 + so);
#pragma unroll
                for (int h = 0; h < 2; h++) {
                    int nt = bt * 2 + h;
#pragma unroll
                    for (int mt = 0; mt < 2; mt++) {
                        mma_h(acc[mt][nt], ah[mt], &bh[h * 2]);
                        mma_h(acc[mt][nt], ah[mt], &bl[h * 2]);
                    }
                }
            }
        }
    };

    if (SINGLE) {
#pragma unroll
        for (int s = 0; s < NCH; s++) { a_async(s, s); b_async(s, s); }
        cpa_commit();
        cpa_wait0();
        __syncthreads();
#pragma unroll
        for (int ch = 0; ch < NCH; ch++) mma_stage(ch, ch);
    } else {
        if (CONVERT) { a_ldregs(0); a_cvtsts(0); }
        else a_async(0, 0);
        b_async(0, 0);
        cpa_commit();
        for (int ch = 0; ch < NCH; ch++) {
            int cur = ch & 1, nxt = cur ^ 1;
            bool more = (ch + 1 < NCH);
            if (more) {
                if (CONVERT) a_ldregs(ch + 1);
                else a_async(nxt, ch + 1);
                b_async(nxt, ch + 1);
                cpa_commit();
            }
            if (more) cpa_wait1(); else cpa_wait0();
            __syncthreads();
            mma_stage(cur, cur);
            if (more && CONVERT) a_cvtsts(nxt);
            __syncthreads();
        }
    }

#pragma unroll
    for (int mt = 0; mt < 2; mt++) {
        int r0 = grow + row0 + mt * 16 + (lane >> 2);
        int r1 = r0 + 8;
#pragma unroll
        for (int nt = 0; nt < NT; nt++) {
            int cc = col0 + nt * 8 + (lane & 3) * 2;
            if (r0 < NNODES)
                *(__half2*)&C[(size_t)r0 * D + cc] =
                    __floats2half2_rn(acc[mt][nt][0], acc[mt][nt][1]);
            if (r1 < NNODES)
                *(__half2*)&C[(size_t)r1 * D + cc] =
                    __floats2half2_rn(acc[mt][nt][2], acc[mt][nt][3]);
        }
    }
}

// ---------------- sparse aggregation (fp16 gather, fp32 accumulate) --------
// h[i] = dinv^2*tmp[i] + sum w*tmp[col]; relu(h) -> hf (fp16);
// PRE: pre-relu h -> pfh (fp16, gram operand).
template <bool PRE>
__global__ void k_agg128s(const __half* __restrict__ tmp,
                          __half* __restrict__ hf,
                          __half* __restrict__ pfh) {
    int gw = (blockIdx.x * blockDim.x + threadIdx.x) >> 5;
    int lane = threadIdx.x & 31;
    if (gw >= NNODES) return;
    const uint2* __restrict__ t = (const uint2*)tmp;
    float di = g_dinv[gw];
    float s = di * di;
    uint2 u = t[gw * 32 + lane];
    float2 p0 = __half22float2(*(__half2*)&u.x);
    float2 p1 = __half22float2(*(__half2*)&u.y);
    float4 acc = make_float4(p0.x * s, p0.y * s, p1.x * s, p1.y * s);
    float4 acc2 = make_float4(0.f, 0.f, 0.f, 0.f);
    int e = g_rowptr[gw], en = g_rowptr[gw + 1];
    for (; e + 7 < en; e += 8) {
        int cidx[8];
        float wv[8];
        uint2 v[8];
#pragma unroll
        for (int j = 0; j < 8; j++) { cidx[j] = g_col[e + j]; wv[j] = g_w[e + j]; }
#pragma unroll
        for (int j = 0; j < 8; j++) v[j] = t[cidx[j] * 32 + lane];
#pragma unroll
        for (int j = 0; j < 8; j++) {
            float2 f0 = __half22float2(*(__half2*)&v[j].x);
            float2 f1 = __half22float2(*(__half2*)&v[j].y);
            if (j & 1) {
                acc2.x = fmaf(wv[j], f0.x, acc2.x); acc2.y = fmaf(wv[j], f0.y, acc2.y);
                acc2.z = fmaf(wv[j], f1.x, acc2.z); acc2.w = fmaf(wv[j], f1.y, acc2.w);
            } else {
                acc.x = fmaf(wv[j], f0.x, acc.x); acc.y = fmaf(wv[j], f0.y, acc.y);
                acc.z = fmaf(wv[j], f1.x, acc.z); acc.w = fmaf(wv[j], f1.y, acc.w);
            }
        }
    }
    for (; e + 1 < en; e += 2) {
        int c0 = g_col[e], c1 = g_col[e + 1];
        float w0 = g_w[e], w1 = g_w[e + 1];
        uint2 a = t[c0 * 32 + lane];
        uint2 b = t[c1 * 32 + lane];
        float2 a0 = __half22float2(*(__half2*)&a.x), a1 = __half22float2(*(__half2*)&a.y);
        float2 b0 = __half22float2(*(__half2*)&b.x), b1 = __half22float2(*(__half2*)&b.y);
        acc.x = fmaf(w0, a0.x, acc.x);   acc.y = fmaf(w0, a0.y, acc.y);
        acc.z = fmaf(w0, a1.x, acc.z);   acc.w = fmaf(w0, a1.y, acc.w);
        acc2.x = fmaf(w1, b0.x, acc2.x); acc2.y = fmaf(w1, b0.y, acc2.y);
        acc2.z = fmaf(w1, b1.x, acc2.z); acc2.w = fmaf(w1, b1.y, acc2.w);
    }
    if (e < en) {
        int c0 = g_col[e];
        float w0 = g_w[e];
        uint2 a = t[c0 * 32 + lane];
        float2 a0 = __half22float2(*(__half2*)&a.x);
        float2 a1 = __half22float2(*(__half2*)&a.y);
        acc.x = fmaf(w0, a0.x, acc.x); acc.y = fmaf(w0, a0.y, acc.y);
        acc.z = fmaf(w0, a1.x, acc.z); acc.w = fmaf(w0, a1.y, acc.w);
    }
    acc.x += acc2.x; acc.y += acc2.y; acc.z += acc2.z; acc.w += acc2.w;

    size_t base = (size_t)gw * HID + lane * 4;
    if (PRE) {
        __half2 q0 = __floats2half2_rn(acc.x, acc.y);
        __half2 q1 = __floats2half2_rn(acc.z, acc.w);
        *(uint2*)&pfh[base] = make_uint2(*(uint32_t*)&q0, *(uint32_t*)&q1);
    }
    __half2 r0 = __floats2half2_rn(fmaxf(acc.x, 0.f), fmaxf(acc.y, 0.f));
    __half2 r1 = __floats2half2_rn(fmaxf(acc.z, 0.f), fmaxf(acc.w, 0.f));
    *(uint2*)&hf[base] = make_uint2(*(uint32_t*)&r0, *(uint32_t*)&r1);
}

// D=64 aggregation into d_out (fp32) + fp16 copy for the gram
__global__ void k_agg64h(const __half* __restrict__ tmp, float* __restrict__ out,
                         __half* __restrict__ cpy) {
    int gw = (blockIdx.x * blockDim.x + threadIdx.x) >> 5;
    int lane = threadIdx.x & 31;
    if (gw >= NNODES) return;
    const uint32_t* __restrict__ t = (const uint32_t*)tmp;
    float di = g_dinv[gw];
    float s = di * di;
    uint32_t u = t[gw * 32 + lane];
    float2 p = __half22float2(*(__half2*)&u);
    float2 acc = make_float2(p.x * s, p.y * s);
    float2 acc2 = make_float2(0.f, 0.f);
    int e = g_rowptr[gw], en = g_rowptr[gw + 1];
    for (; e + 7 < en; e += 8) {
        int cidx[8];
        float wv[8];
        uint32_t v[8];
#pragma unroll
        for (int j = 0; j < 8; j++) { cidx[j] = g_col[e + j]; wv[j] = g_w[e + j]; }
#pragma unroll
        for (int j = 0; j < 8; j++) v[j] = t[cidx[j] * 32 + lane];
#pragma unroll
        for (int j = 0; j < 8; j++) {
            float2 f = __half22float2(*(__half2*)&v[j]);
            if (j & 1) {
                acc2.x = fmaf(wv[j], f.x, acc2.x); acc2.y = fmaf(wv[j], f.y, acc2.y);
            } else {
                acc.x = fmaf(wv[j], f.x, acc.x); acc.y = fmaf(wv[j], f.y, acc.y);
            }
        }
    }
    for (; e < en; e++) {
        int c0 = g_col[e];
        float w0 = g_w[e];
        uint32_t a = t[c0 * 32 + lane];
        float2 af = __half22float2(*(__half2*)&a);
        acc.x = fmaf(w0, af.x, acc.x); acc.y = fmaf(w0, af.y, acc.y);
    }
    acc.x += acc2.x; acc.y += acc2.y;
    ((float2*)out)[gw * 32 + lane] = acc;
    __half2 q = __floats2half2_rn(acc.x, acc.y);
    ((uint32_t*)cpy)[gw * 32 + lane] = *(uint32_t*)&q;
}

// ---------------- Gram via mma from fp16 h (single term) --------------------
// G = H^T H + column sums; H fp16 [N, D].
template <int D>
__global__ __launch_bounds__(256) void k_gram_h(const __half* __restrict__ hh) {
    __shared__ __align__(1024) uint8_t sm[D * 128];
    const int FG = D / 4;
    const int PAIRS = 256 / FG;
    const int NT = D / 8;
    const int MW = D / 16;
    uint32_t sb = smem_u32(sm);
    int tid = threadIdx.x, wid = tid >> 5, lane = tid & 31;
    int f4 = tid % FG;
    int rp0 = tid / FG;

    float acc[NT][4];
#pragma unroll
    for (int j = 0; j < NT; j++)
#pragma unroll
        for (int q = 0; q < 4; q++) acc[j][q] = 0.f;
    float cs0 = 0.f, cs1 = 0.f, cs2 = 0.f, cs3 = 0.f;

    const int NCHUNK = (NNODES + 63) / 64;
    for (int ch = blockIdx.x; ch < NCHUNK; ch += gridDim.x) {
        int rbase = ch * 64;
#pragma unroll
        for (int it = 0; it < 32 / PAIRS; it++) {
            int pr = rp0 + it * PAIRS;
            int r0 = rbase + pr * 2, r1 = r0 + 1;
            uint2 h0v = make_uint2(0, 0), h1v = h0v;
            if (r0 < NNODES) h0v = *(const uint2*)&hh[(size_t)r0 * D + f4 * 4];
            if (r1 < NNODES) h1v = *(const uint2*)&hh[(size_t)r1 * D + f4 * 4];
            const ushort* h0s = (const ushort*)&h0v;
            const ushort* h1s = (const ushort*)&h1v;
#pragma unroll
            for (int j = 0; j < 4; j++) {
                float f0 = __half2float(__ushort_as_half(h0s[j]));
                float f1 = __half2float(__ushort_as_half(h1s[j]));
                float fs = f0 + f1;
                if (j == 0) cs0 += fs;
                else if (j == 1) cs1 += fs;
                else if (j == 2) cs2 += fs;
                else cs3 += fs;
                int feat = f4 * 4 + j;
                uint32_t hp = (uint32_t)h0s[j] | ((uint32_t)h1s[j] << 16);
                uint32_t so = sw128((uint32_t)(feat * 128 + pr * 4));
                *(uint32_t*)(sm + so) = hp;
            }
        }
        __syncthreads();
        if (wid < MW) {
#pragma unroll
            for (int k16 = 0; k16 < 4; k16++) {
                int kb = k16 * 32;
                uint32_t av[4];
                {
                    int r = wid * 16 + (lane & 15);
                    int cb = kb + ((lane & 16) ? 16 : 0);
                    uint32_t so = sw128((uint32_t)(r * 128 + cb));
                    ldsm4(av, sb + so);
                }
#pragma unroll
                for (int bt = 0; bt < NT / 2; bt++) {
                    int n = bt * 16 + (lane & 7) + ((lane & 16) ? 8 : 0);
                    int cb = kb + ((lane & 8) ? 16 : 0);
                    uint32_t so = sw128((uint32_t)(n * 128 + cb));
                    uint32_t bv[4];
                    ldsm4(bv, sb + so);
#pragma unroll
                    for (int h2 = 0; h2 < 2; h2++) {
                        int nt = bt * 2 + h2;
                        mma_h(acc[nt], av, &bv[h2 * 2]);
                    }
                }
            }
        }
        __syncthreads();
    }
    if (wid < MW) {
        int mrow = wid * 16 + (lane >> 2);
#pragma unroll
        for (int nt = 0; nt < NT; nt++) {
            int c = nt * 8 + (lane & 3) * 2;
            atomicAdd(&g_G[mrow * D + c], acc[nt][0]);
            atomicAdd(&g_G[mrow * D + c + 1], acc[nt][1]);
            atomicAdd(&g_G[(mrow + 8) * D + c], acc[nt][2]);
            atomicAdd(&g_G[(mrow + 8) * D + c + 1], acc[nt][3]);
        }
    }
    atomicAdd(&g_csum[f4 * 4 + 0], cs0);
    atomicAdd(&g_csum[f4 * 4 + 1], cs1);
    atomicAdd(&g_csum[f4 * 4 + 2], cs2);
    atomicAdd(&g_csum[f4 * 4 + 3], cs3);
}

// ---------------- correlation metric finalize (single block) ----------------
template <int D>
__global__ void k_finalize(float* __restrict__ dst) {
    __shared__ float sd[D];
    __shared__ float red[256];
    int tid = threadIdx.x;
    const float invN = 1.0f / (float)NNODES;
    if (tid < D) {
        float cjj = g_G[tid * D + tid] - g_csum[tid] * g_csum[tid] * invN;
        sd[tid] = sqrtf(fmaxf(cjj, 1e-12f));
    }
    __syncthreads();
    float sum = 0.f;
    for (int idx = tid; idx < D * D; idx += 256) {
        int j = idx / D, k = idx % D;
        if (k > j) {
            float cov = g_G[idx] - g_csum[j] * g_csum[k] * invN;
            sum += fabsf(cov / (sd[j] * sd[k]));
        }
    }
    red[tid] = sum;
    __syncthreads();
    for (int off = 128; off > 0; off >>= 1) {
        if (tid < off) red[tid] += red[tid + off];
        __syncthreads();
    }
    if (tid == 0) *dst = red[0] / (float)(D * (D - 1) / 2);
}

// ---------------- launch ----------------
extern "C" void kernel_launch(void* const* d_in, const int* in_sizes, int n_in,
                              void* d_out, int out_size) {
    const float* x  = (const float*)d_in[0];
    const int*   ei = (const int*)d_in[1];
    const float* W0 = (const float*)d_in[2];
    const float* W1 = (const float*)d_in[3];
    const float* W2 = (const float*)d_in[4];
    const float* W3 = (const float*)d_in[5];
    float* out = (float*)d_out;

    __half *tmp, *hf, *pfh;
    cudaGetSymbolAddress((void**)&tmp, g_tmp);
    cudaGetSymbolAddress((void**)&hf, g_hf);
    cudaGetSymbolAddress((void**)&pfh, g_pf);
    __half *w0h, *w0l, *w1h, *w1l, *w2h, *w2l, *w3h, *w3l;
    cudaGetSymbolAddress((void**)&w0h, g_w0h); cudaGetSymbolAddress((void**)&w0l, g_w0l);
    cudaGetSymbolAddress((void**)&w1h, g_w1h); cudaGetSymbolAddress((void**)&w1l, g_w1l);
    cudaGetSymbolAddress((void**)&w2h, g_w2h); cudaGetSymbolAddress((void**)&w2l, g_w2l);
    cudaGetSymbolAddress((void**)&w3h, g_w3h); cudaGetSymbolAddress((void**)&w3l, g_w3l);
    int *cntp, *curp;
    float *Gp, *csp;
    cudaGetSymbolAddress((void**)&cntp, g_cnt);
    cudaGetSymbolAddress((void**)&curp, g_cursor);
    cudaGetSymbolAddress((void**)&Gp, g_G);
    cudaGetSymbolAddress((void**)&csp, g_csum);

    const int SM_BIG = 2 * 128 * 128 + 4 * HID * 128;   // 98304
    const int SM_SML = 2 * 128 * 128 + 4 * COUT * 128;  // 65536
    cudaFuncSetAttribute((const void*)k_tgemm512<FIN, HID, true, 1>,
                         cudaFuncAttributeMaxDynamicSharedMemorySize, SM_BIG);
    cudaFuncSetAttribute((const void*)k_tgemm512<HID, HID, false, 2>,
                         cudaFuncAttributeMaxDynamicSharedMemorySize, SM_BIG);
    cudaFuncSetAttribute((const void*)k_tgemm512<HID, COUT, false, 2>,
                         cudaFuncAttributeMaxDynamicSharedMemorySize, SM_SML);

    // side stream + events for fork/join inside graph capture (leaked, bounded)
    cudaStream_t s1;
    cudaStreamCreateWithFlags(&s1, cudaStreamNonBlocking);
    cudaEvent_t eFork1, ePre, eFork2, eCorr;
    cudaEventCreateWithFlags(&eFork1, cudaEventDisableTiming);
    cudaEventCreateWithFlags(&ePre,  cudaEventDisableTiming);
    cudaEventCreateWithFlags(&eFork2, cudaEventDisableTiming);
    cudaEventCreateWithFlags(&eCorr, cudaEventDisableTiming);

    const int TB = 256;
    const int nbE = (NEDGES + TB - 1) / TB;
    const int nbM = (NNODES + 127) / 128;
    const int nbA = (NNODES + 7) / 8;
    const int P3N = 2 * HID * HID + HID * COUT;

    // ---- fork: preprocessing on s1, L0 GEMM path on capture stream ----
    cudaEventRecord(eFork1, 0);
    cudaStreamWaitEvent(s1, eFork1, 0);

    k_prepW<FIN, HID><<<(FIN * HID + TB - 1) / TB, TB>>>(W0, w0h, w0l);
    cudaMemsetAsync(cntp, 0, NNODES * sizeof(int), s1);
    cudaMemsetAsync(curp, 0, NNODES * sizeof(int), s1);
    k_count<<<nbE, TB, 0, s1>>>(ei);
    k_tgemm512<FIN, HID, true, 1><<<nbM, 512, SM_BIG>>>(x, nullptr,
                                                        w0h, w0l, tmp);
    k_scan1<<<SCAN_NB, SCAN_TPB, 0, s1>>>();
    k_scan2<<<1, 64, 0, s1>>>();
    k_scan3<<<SCAN_NB, SCAN_TPB, 0, s1>>>();
    k_fill<<<nbE, TB, 0, s1>>>(ei);
    k_prepW3x<<<(P3N + TB - 1) / TB, TB, 0, s1>>>(W1, W2, W3);
    cudaEventRecord(ePre, s1);
    cudaStreamWaitEvent(0, ePre, 0);

    // layer 0 aggregation -> relu'd fp16 h0
    k_agg128s<false><<<nbA, TB>>>(tmp, hf, pfh);
    // layer 1
    k_tgemm512<HID, HID, false, 2><<<nbM, 512, SM_BIG>>>(nullptr, hf, w1h, w1l, tmp);
    k_agg128s<false><<<nbA, TB>>>(tmp, hf, pfh);
    // layer 2 (pre-relu h2 kept as fp16 for corr_2)
    k_tgemm512<HID, HID, false, 2><<<nbM, 512, SM_BIG>>>(nullptr, hf, w2h, w2l, tmp);
    k_agg128s<true><<<nbA, TB>>>(tmp, hf, pfh);

    // ---- fork: corr_2 metric (s1) concurrent with layer-3 chain (s0) ----
    cudaEventRecord(eFork2, 0);
    cudaStreamWaitEvent(s1, eFork2, 0);
    cudaMemsetAsync(Gp, 0, HID * HID * sizeof(float), s1);
    cudaMemsetAsync(csp, 0, HID * sizeof(float), s1);
    k_gram_h<HID><<<296, 256, 0, s1>>>(pfh);
    k_finalize<HID><<<1, 256, 0, s1>>>(out + NNODES * COUT);
    cudaEventRecord(eCorr, s1);

    // layer 3: relu(h2) @ W3 -> agg into d_out (+fp16 copy into dead hf)
    k_tgemm512<HID, COUT, false, 2><<<nbM, 512, SM_SML>>>(nullptr, hf, w3h, w3l, tmp);
    k_agg64h<<<nbA, TB>>>(tmp, out, hf);

    // final corr on h3 (fp16 copy in hf)
    cudaStreamWaitEvent(0, eCorr, 0);
    cudaMemsetAsync(Gp, 0, HID * HID * sizeof(float), 0);
    cudaMemsetAsync(csp, 0, HID * sizeof(float), 0);
    k_gram_h<COUT><<<296, 256>>>(hf);
    k_finalize<COUT><<<1, 256>>>(out + NNODES * COUT + 1);
}

// round 14
// speedup vs baseline: 1.2356x; 1.0456x over previous
#include <cuda_runtime.h>
#include <cuda_bf16.h>
#include <cuda_fp16.h>
#include <math.h>
#include <stdint.h>

#define NNODES 100000
#define NEDGES 1600000
#define FIN 256
#define HID 128
#define COUT 64

#define SCAN_TPB 256
#define SCAN_ELEMS 8
#define SCAN_CHUNK (SCAN_TPB * SCAN_ELEMS)                 // 2048
#define SCAN_NB ((NNODES + SCAN_CHUNK - 1) / SCAN_CHUNK)   // 49

// ---------------- scratch (static __device__, no allocation) ----------------
__device__ __half g_tmp[NNODES * HID];          // messages (GEMM out), fp16
__device__ __half g_hf[NNODES * HID];           // relu'd h fp16 (GEMM A) / h3 fp16 copy
__device__ __half g_pf[NNODES * HID];           // pre-relu h2 fp16 (gram operand)
__device__ float g_dinv[NNODES];
__device__ int   g_cnt[NNODES];
__device__ int   g_cursor[NNODES];
__device__ int   g_rowptr[NNODES + 1];
__device__ int   g_col[NEDGES];
__device__ float g_w[NEDGES];
__device__ float g_G[HID * HID];
__device__ float g_csum[HID];
__device__ float g_G2[COUT * COUT];
__device__ float g_csum2[COUT];
__device__ int   g_bsum[SCAN_NB];

// split-fp16 transposed weights: Wt[d][k] = W[k][d]
__device__ __half g_w0h[HID * FIN],  g_w0l[HID * FIN];
__device__ __half g_w1h[HID * HID],  g_w1l[HID * HID];
__device__ __half g_w2h[HID * HID],  g_w2l[HID * HID];
__device__ __half g_w3h[COUT * HID], g_w3l[COUT * HID];

// ---------------- helpers ----------------
__device__ __forceinline__ uint32_t smem_u32(const void* p) {
    uint32_t a;
    asm("{ .reg .u64 t; cvta.to.shared.u64 t, %1; cvt.u32.u64 %0, t; }"
        : "=r"(a) : "l"(p));
    return a;
}
__device__ __forceinline__ uint32_t sw128(uint32_t off) {
    return off ^ ((off >> 3) & 0x70);
}
__device__ __forceinline__ void ldsm4(uint32_t* r, uint32_t addr) {
    asm volatile("ldmatrix.sync.aligned.m8n8.x4.shared.b16 {%0,%1,%2,%3}, [%4];"
                 : "=r"(r[0]), "=r"(r[1]), "=r"(r[2]), "=r"(r[3]) : "r"(addr));
}
__device__ __forceinline__ void mma_h(float* c, const uint32_t* a,
                                      const uint32_t* b) {
    asm volatile(
        "mma.sync.aligned.m16n8k16.row.col.f32.f16.f16.f32 "
        "{%0,%1,%2,%3}, {%4,%5,%6,%7}, {%8,%9}, {%0,%1,%2,%3};"
        : "+f"(c[0]), "+f"(c[1]), "+f"(c[2]), "+f"(c[3])
        : "r"(a[0]), "r"(a[1]), "r"(a[2]), "r"(a[3]), "r"(b[0]), "r"(b[1]));
}
__device__ __forceinline__ void split2h(float f, __half& h, __half& l) {
    h = __float2half_rn(f);
    l = __float2half_rn(f - __half2float(h));
}
__device__ __forceinline__ void cpa16(uint32_t dst, const void* src, int nbytes) {
    asm volatile("cp.async.cg.shared.global [%0], [%1], 16, %2;"
                 :: "r"(dst), "l"(src), "r"(nbytes) : "memory");
}
__device__ __forceinline__ void cpa_commit() {
    asm volatile("cp.async.commit_group;" ::: "memory");
}
__device__ __forceinline__ void cpa_wait1() {
    asm volatile("cp.async.wait_group 1;" ::: "memory");
}
__device__ __forceinline__ void cpa_wait0() {
    asm volatile("cp.async.wait_group 0;" ::: "memory");
}

// ---------------- preprocessing ----------------
__global__ void k_count(const int* __restrict__ ei) {
    int e = blockIdx.x * blockDim.x + threadIdx.x;
    if (e < NEDGES) atomicAdd(&g_cnt[ei[e]], 1);
}

__global__ void k_scan1() {
    __shared__ int warp_s[SCAN_TPB / 32];
    int tid = threadIdx.x, blk = blockIdx.x;
    int base = blk * SCAN_CHUNK + tid * SCAN_ELEMS;
    int s = 0;
#pragma unroll
    for (int i = 0; i < SCAN_ELEMS; i++) {
        int idx = base + i;
        if (idx < NNODES) {
            int c = g_cnt[idx];
            s += c;
            g_dinv[idx] = rsqrtf((float)(c + 1));  // +1 self loop
        }
    }
    for (int o = 16; o > 0; o >>= 1) s += __shfl_down_sync(0xffffffffu, s, o);
    if ((tid & 31) == 0) warp_s[tid >> 5] = s;
    __syncthreads();
    if (tid < SCAN_TPB / 32) {
        int w = warp_s[tid];
        for (int o = (SCAN_TPB / 64); o > 0; o >>= 1)
            w += __shfl_down_sync(0xffu, w, o);
        if (tid == 0) g_bsum[blk] = w;
    }
}

__global__ void k_scan2() {
    __shared__ int sh[64];
    int tid = threadIdx.x;
    sh[tid] = (tid < SCAN_NB) ? g_bsum[tid] : 0;
    __syncthreads();
    for (int o = 1; o < 64; o <<= 1) {
        int v = (tid >= o) ? sh[tid - o] : 0;
        __syncthreads();
        sh[tid] += v;
        __syncthreads();
    }
    if (tid < SCAN_NB) g_bsum[tid] = (tid == 0) ? 0 : sh[tid - 1];
    if (tid == 0) g_rowptr[NNODES] = sh[SCAN_NB - 1];
}

__global__ void k_scan3() {
    __shared__ int tsum[SCAN_TPB];
    int tid = threadIdx.x, blk = blockIdx.x;
    int base = blk * SCAN_CHUNK + tid * SCAN_ELEMS;
    int c[SCAN_ELEMS];
    int s = 0;
#pragma unroll
    for (int i = 0; i < SCAN_ELEMS; i++) {
        int idx = base + i;
        c[i] = (idx < NNODES) ? g_cnt[idx] : 0;
        s += c[i];
    }
    tsum[tid] = s;
    __syncthreads();
    for (int o = 1; o < SCAN_TPB; o <<= 1) {
        int v = (tid >= o) ? tsum[tid - o] : 0;
        __syncthreads();
        tsum[tid] += v;
        __syncthreads();
    }
    int run = g_bsum[blk] + ((tid == 0) ? 0 : tsum[tid - 1]);
#pragma unroll
    for (int i = 0; i < SCAN_ELEMS; i++) {
        int idx = base + i;
        if (idx < NNODES) { g_rowptr[idx] = run; run += c[i]; }
    }
}

__global__ void k_fill(const int* __restrict__ ei) {
    int e = blockIdx.x * blockDim.x + threadIdx.x;
    if (e >= NEDGES) return;
    int r = ei[e];
    int c = ei[NEDGES + e];
    int pos = g_rowptr[r] + atomicAdd(&g_cursor[r], 1);
    g_col[pos] = c;
    g_w[pos] = g_dinv[r] * g_dinv[c];
}

// ---------------- weight prep: W[K,D] fp32 -> Wt hi/lo fp16 [D][K] ----------
template <int K, int D>
__global__ void k_prepW(const float* __restrict__ W,
                        __half* __restrict__ Wh, __half* __restrict__ Wl) {
    int i = blockIdx.x * blockDim.x + threadIdx.x;
    if (i >= K * D) return;
    int n = i / K, k = i % K;
    __half h, l;
    split2h(W[k * D + n], h, l);
    Wh[n * K + k] = h;
    Wl[n * K + k] = l;
}

__global__ void k_prepW3x(const float* __restrict__ W1,
                          const float* __restrict__ W2,
                          const float* __restrict__ W3) {
    int i = blockIdx.x * blockDim.x + threadIdx.x;
    const int S1 = HID * HID, S2 = 2 * HID * HID, S3 = 2 * HID * HID + HID * COUT;
    __half h, l;
    if (i < S1) {
        int n = i / HID, k = i % HID;
        split2h(W1[k * HID + n], h, l);
        g_w1h[n * HID + k] = h; g_w1l[n * HID + k] = l;
    } else if (i < S2) {
        int j = i - S1;
        int n = j / HID, k = j % HID;
        split2h(W2[k * HID + n], h, l);
        g_w2h[n * HID + k] = h; g_w2l[n * HID + k] = l;
    } else if (i < S3) {
        int j = i - S2;
        int n = j / HID, k = j % HID;
        split2h(W3[k * COUT + n], h, l);
        g_w3h[n * HID + k] = h; g_w3l[n * HID + k] = l;
    }
}

// ---------------- fp16-A / split-fp16-B GEMM --------------------------------
// K<=128 non-convert: SINGLE-SHOT. CONVERT (K=256, layer 0): 2-stage B via
// cp.async; A converted fp32->fp16 via plain LDG+cvt+STS after the MMA (the
// sibling CTA at MINB=2 hides the exposed LDG latency).
template <int K, int D, bool CONVERT, int MINB>
__global__ __launch_bounds__(512, MINB) void k_tgemm512(const float* __restrict__ Af,
                                                        const __half* __restrict__ Ah,
                                                        const __half* __restrict__ Bh,
                                                        const __half* __restrict__ Bl,
                                                        __half* __restrict__ C) {
    extern __shared__ __align__(1024) uint8_t smem[];
    const int CK = 64;
    const int NCH = K / CK;
    const int WN = D / 4;
    const int NT = WN / 8;
    const int STA = 128 * 128;
    const int SBB = D * 128;
    const bool SINGLE = (!CONVERT) && (NCH <= 2);
    const int NSTA = SINGLE ? NCH : 2;
    const int OFF_B = NSTA * STA;

    uint32_t sb = smem_u32(smem);
    int tid = threadIdx.x, wid = tid >> 5, lane = tid & 31;
    int wm = wid & 3, wn = wid >> 2;
    int row0 = wm * 32;
    int col0 = wn * WN;
    int grow = blockIdx.x * 128;

    float acc[2][NT][4];
#pragma unroll
    for (int i = 0; i < 2; i++)
#pragma unroll
        for (int j = 0; j < NT; j++)
#pragma unroll
            for (int q = 0; q < 4; q++) acc[i][j][q] = 0.f;

    auto a_async = [&](int s, int ch) {
        int kk = ch * CK;
#pragma unroll
        for (int i = 0; i < 2; i++) {
            int u = tid + i * 512;
            int m = u >> 3, g = u & 7;
            int r = grow + m;
            int rc = (r < NNODES) ? r : 0;
            int nb = (r < NNODES) ? 16 : 0;
            uint32_t so = sw128((uint32_t)(m * 128 + g * 16));
            cpa16(sb + s * STA + so, &Ah[(size_t)rc * K + kk + g * 8], nb);
        }
    };
    auto b_async = [&](int s, int ch) {
        int kk = ch * CK;
#pragma unroll
        for (int i = 0; i < (D * 8 + 511) / 512; i++) {
            int u = tid + i * 512;
            if (u < D * 8) {
                int n = u >> 3, g = u & 7;
                uint32_t so = sw128((uint32_t)(n * 128 + g * 16));
                cpa16(sb + OFF_B + (2 * s) * SBB + so, &Bh[n * K + kk + g * 8], 16);
                cpa16(sb + OFF_B + (2 * s + 1) * SBB + so, &Bl[n * K + kk + g * 8], 16);
            }
        }
    };
    // direct fp32 load -> fp16 convert -> STS (no persistent registers)
    auto a_direct = [&](int s, int ch) {
        int kk = ch * CK;
#pragma unroll
        for (int i = 0; i < 2; i++) {
            int u = tid + i * 512;
            int m = u >> 3, g = u & 7;
            int r = grow + m;
            float4 v0 = make_float4(0.f, 0.f, 0.f, 0.f), v1 = v0;
            if (r < NNODES) {
                const float* p = &Af[(size_t)r * K + kk + g * 8];
                v0 = *(const float4*)p;
                v1 = *(const float4*)(p + 4);
            }
            __half2 h0 = __floats2half2_rn(v0.x, v0.y);
            __half2 h1 = __floats2half2_rn(v0.z, v0.w);
            __half2 h2 = __floats2half2_rn(v1.x, v1.y);
            __half2 h3 = __floats2half2_rn(v1.z, v1.w);
            uint32_t so = sw128((uint32_t)(m * 128 + g * 16));
            *(uint4*)(smem + s * STA + so) =
                make_uint4(*(uint32_t*)&h0, *(uint32_t*)&h1,
                           *(uint32_t*)&h2, *(uint32_t*)&h3);
        }
    };
    auto mma_stage = [&](int stA, int stB) {
        uint32_t aB = sb + stA * STA;
        uint32_t bB0 = sb + OFF_B + (2 * stB) * SBB;
        uint32_t bB1 = sb + OFF_B + (2 * stB + 1) * SBB;
#pragma unroll
        for (int k16 = 0; k16 < CK / 16; k16++) {
            int kb = k16 * 32;
            uint32_t ah[2][4];
#pragma unroll
            for (int mt = 0; mt < 2; mt++) {
                int r = row0 + mt * 16 + (lane & 15);
                int cb = kb + ((lane & 16) ? 16 : 0);
                uint32_t so = sw128((uint32_t)(r * 128 + cb));
                ldsm4(ah[mt], aB + so);
            }
#pragma unroll
            for (int bt = 0; bt < NT / 2; bt++) {
                int n = col0 + bt * 16 + (lane & 7) + ((lane & 16) ? 8 : 0);
                int cb = kb + ((lane & 8) ? 16 : 0);
                uint32_t so = sw128((uint32_t)(n * 128 + cb));
                uint32_t bh[4], bl[4];
                ldsm4(bh, bB0 + so);
                ldsm4(bl, bB1 + so);
#pragma unroll
                for (int h = 0; h < 2; h++) {
                    int nt = bt * 2 + h;
#pragma unroll
                    for (int mt = 0; mt < 2; mt++) {
                        mma_h(acc[mt][nt], ah[mt], &bh[h * 2]);
                        mma_h(acc[mt][nt], ah[mt], &bl[h * 2]);
                    }
                }
            }
        }
    };

    if (SINGLE) {
#pragma unroll
        for (int s = 0; s < NCH; s++) { a_async(s, s); b_async(s, s); }
        cpa_commit();
        cpa_wait0();
        __syncthreads();
#pragma unroll
        for (int ch = 0; ch < NCH; ch++) mma_stage(ch, ch);
    } else {
        // CONVERT path: B double-buffered via cp.async, A converted directly.
        a_direct(0, 0);
        b_async(0, 0);
        cpa_commit();
        for (int ch = 0; ch < NCH; ch++) {
            int cur = ch & 1, nxt = cur ^ 1;
            bool more = (ch + 1 < NCH);
            if (more) {
                b_async(nxt, ch + 1);
                cpa_commit();
            }
            if (more) cpa_wait1(); else cpa_wait0();
            __syncthreads();
            mma_stage(cur, cur);
            if (more) a_direct(nxt, ch + 1);
            __syncthreads();
        }
    }

#pragma unroll
    for (int mt = 0; mt < 2; mt++) {
        int r0 = grow + row0 + mt * 16 + (lane >> 2);
        int r1 = r0 + 8;
#pragma unroll
        for (int nt = 0; nt < NT; nt++) {
            int cc = col0 + nt * 8 + (lane & 3) * 2;
            if (r0 < NNODES)
                *(__half2*)&C[(size_t)r0 * D + cc] =
                    __floats2half2_rn(acc[mt][nt][0], acc[mt][nt][1]);
            if (r1 < NNODES)
                *(__half2*)&C[(size_t)r1 * D + cc] =
                    __floats2half2_rn(acc[mt][nt][2], acc[mt][nt][3]);
        }
    }
}

// ---------------- sparse aggregation (fp16 gather, fp32 accumulate) --------
template <bool PRE>
__global__ void k_agg128s(const __half* __restrict__ tmp,
                          __half* __restrict__ hf,
                          __half* __restrict__ pfh) {
    int gw = (blockIdx.x * blockDim.x + threadIdx.x) >> 5;
    int lane = threadIdx.x & 31;
    if (gw >= NNODES) return;
    const uint2* __restrict__ t = (const uint2*)tmp;
    float di = g_dinv[gw];
    float s = di * di;
    uint2 u = t[gw * 32 + lane];
    float2 p0 = __half22float2(*(__half2*)&u.x);
    float2 p1 = __half22float2(*(__half2*)&u.y);
    float4 acc = make_float4(p0.x * s, p0.y * s, p1.x * s, p1.y * s);
    float4 acc2 = make_float4(0.f, 0.f, 0.f, 0.f);
    int e = g_rowptr[gw], en = g_rowptr[gw + 1];
    for (; e + 7 < en; e += 8) {
        int cidx[8];
        float wv[8];
        uint2 v[8];
#pragma unroll
        for (int j = 0; j < 8; j++) { cidx[j] = g_col[e + j]; wv[j] = g_w[e + j]; }
#pragma unroll
        for (int j = 0; j < 8; j++) v[j] = t[cidx[j] * 32 + lane];
#pragma unroll
        for (int j = 0; j < 8; j++) {
            float2 f0 = __half22float2(*(__half2*)&v[j].x);
            float2 f1 = __half22float2(*(__half2*)&v[j].y);
            if (j & 1) {
                acc2.x = fmaf(wv[j], f0.x, acc2.x); acc2.y = fmaf(wv[j], f0.y, acc2.y);
                acc2.z = fmaf(wv[j], f1.x, acc2.z); acc2.w = fmaf(wv[j], f1.y, acc2.w);
            } else {
                acc.x = fmaf(wv[j], f0.x, acc.x); acc.y = fmaf(wv[j], f0.y, acc.y);
                acc.z = fmaf(wv[j], f1.x, acc.z); acc.w = fmaf(wv[j], f1.y, acc.w);
            }
        }
    }
    for (; e + 1 < en; e += 2) {
        int c0 = g_col[e], c1 = g_col[e + 1];
        float w0 = g_w[e], w1 = g_w[e + 1];
        uint2 a = t[c0 * 32 + lane];
        uint2 b = t[c1 * 32 + lane];
        float2 a0 = __half22float2(*(__half2*)&a.x), a1 = __half22float2(*(__half2*)&a.y);
        float2 b0 = __half22float2(*(__half2*)&b.x), b1 = __half22float2(*(__half2*)&b.y);
        acc.x = fmaf(w0, a0.x, acc.x);   acc.y = fmaf(w0, a0.y, acc.y);
        acc.z = fmaf(w0, a1.x, acc.z);   acc.w = fmaf(w0, a1.y, acc.w);
        acc2.x = fmaf(w1, b0.x, acc2.x); acc2.y = fmaf(w1, b0.y, acc2.y);
        acc2.z = fmaf(w1, b1.x, acc2.z); acc2.w = fmaf(w1, b1.y, acc2.w);
    }
    if (e < en) {
        int c0 = g_col[e];
        float w0 = g_w[e];
        uint2 a = t[c0 * 32 + lane];
        float2 a0 = __half22float2(*(__half2*)&a.x);
        float2 a1 = __half22float2(*(__half2*)&a.y);
        acc.x = fmaf(w0, a0.x, acc.x); acc.y = fmaf(w0, a0.y, acc.y);
        acc.z = fmaf(w0, a1.x, acc.z); acc.w = fmaf(w0, a1.y, acc.w);
    }
    acc.x += acc2.x; acc.y += acc2.y; acc.z += acc2.z; acc.w += acc2.w;

    size_t base = (size_t)gw * HID + lane * 4;
    if (PRE) {
        __half2 q0 = __floats2half2_rn(acc.x, acc.y);
        __half2 q1 = __floats2half2_rn(acc.z, acc.w);
        *(uint2*)&pfh[base] = make_uint2(*(uint32_t*)&q0, *(uint32_t*)&q1);
    }
    __half2 r0 = __floats2half2_rn(fmaxf(acc.x, 0.f), fmaxf(acc.y, 0.f));
    __half2 r1 = __floats2half2_rn(fmaxf(acc.z, 0.f), fmaxf(acc.w, 0.f));
    *(uint2*)&hf[base] = make_uint2(*(uint32_t*)&r0, *(uint32_t*)&r1);
}

// D=64 aggregation into d_out (fp32) + fp16 copy for the gram
__global__ void k_agg64h(const __half* __restrict__ tmp, float* __restrict__ out,
                         __half* __restrict__ cpy) {
    int gw = (blockIdx.x * blockDim.x + threadIdx.x) >> 5;
    int lane = threadIdx.x & 31;
    if (gw >= NNODES) return;
    const uint32_t* __restrict__ t = (const uint32_t*)tmp;
    float di = g_dinv[gw];
    float s = di * di;
    uint32_t u = t[gw * 32 + lane];
    float2 p = __half22float2(*(__half2*)&u);
    float2 acc = make_float2(p.x * s, p.y * s);
    float2 acc2 = make_float2(0.f, 0.f);
    int e = g_rowptr[gw], en = g_rowptr[gw + 1];
    for (; e + 7 < en; e += 8) {
        int cidx[8];
        float wv[8];
        uint32_t v[8];
#pragma unroll
        for (int j = 0; j < 8; j++) { cidx[j] = g_col[e + j]; wv[j] = g_w[e + j]; }
#pragma unroll
        for (int j = 0; j < 8; j++) v[j] = t[cidx[j] * 32 + lane];
#pragma unroll
        for (int j = 0; j < 8; j++) {
            float2 f = __half22float2(*(__half2*)&v[j]);
            if (j & 1) {
                acc2.x = fmaf(wv[j], f.x, acc2.x); acc2.y = fmaf(wv[j], f.y, acc2.y);
            } else {
                acc.x = fmaf(wv[j], f.x, acc.x); acc.y = fmaf(wv[j], f.y, acc.y);
            }
        }
    }
    for (; e < en; e++) {
        int c0 = g_col[e];
        float w0 = g_w[e];
        uint32_t a = t[c0 * 32 + lane];
        float2 af = __half22float2(*(__half2*)&a);
        acc.x = fmaf(w0, af.x, acc.x); acc.y = fmaf(w0, af.y, acc.y);
    }
    acc.x += acc2.x; acc.y += acc2.y;
    ((float2*)out)[gw * 32 + lane] = acc;
    __half2 q = __floats2half2_rn(acc.x, acc.y);
    ((uint32_t*)cpy)[gw * 32 + lane] = *(uint32_t*)&q;
}

// ---------------- Gram via mma from fp16 h (single term) --------------------
template <int D>
__global__ __launch_bounds__(256) void k_gram_h(const __half* __restrict__ hh,
                                                float* __restrict__ G,
                                                float* __restrict__ cs) {
    __shared__ __align__(1024) uint8_t sm[D * 128];
    const int FG = D / 4;
    const int PAIRS = 256 / FG;
    const int NT = D / 8;
    const int MW = D / 16;
    uint32_t sb = smem_u32(sm);
    int tid = threadIdx.x, wid = tid >> 5, lane = tid & 31;
    int f4 = tid % FG;
    int rp0 = tid / FG;

    float acc[NT][4];
#pragma unroll
    for (int j = 0; j < NT; j++)
#pragma unroll
        for (int q = 0; q < 4; q++) acc[j][q] = 0.f;
    float cs0 = 0.f, cs1 = 0.f, cs2 = 0.f, cs3 = 0.f;

    const int NCHUNK = (NNODES + 63) / 64;
    for (int ch = blockIdx.x; ch < NCHUNK; ch += gridDim.x) {
        int rbase = ch * 64;
#pragma unroll
        for (int it = 0; it < 32 / PAIRS; it++) {
            int pr = rp0 + it * PAIRS;
            int r0 = rbase + pr * 2, r1 = r0 + 1;
            uint2 h0v = make_uint2(0, 0), h1v = h0v;
            if (r0 < NNODES) h0v = *(const uint2*)&hh[(size_t)r0 * D + f4 * 4];
            if (r1 < NNODES) h1v = *(const uint2*)&hh[(size_t)r1 * D + f4 * 4];
            const ushort* h0s = (const ushort*)&h0v;
            const ushort* h1s = (const ushort*)&h1v;
#pragma unroll
            for (int j = 0; j < 4; j++) {
                float f0 = __half2float(__ushort_as_half(h0s[j]));
                float f1 = __half2float(__ushort_as_half(h1s[j]));
                float fs = f0 + f1;
                if (j == 0) cs0 += fs;
                else if (j == 1) cs1 += fs;
                else if (j == 2) cs2 += fs;
                else cs3 += fs;
                int feat = f4 * 4 + j;
                uint32_t hp = (uint32_t)h0s[j] | ((uint32_t)h1s[j] << 16);
                uint32_t so = sw128((uint32_t)(feat * 128 + pr * 4));
                *(uint32_t*)(sm + so) = hp;
            }
        }
        __syncthreads();
        if (wid < MW) {
#pragma unroll
            for (int k16 = 0; k16 < 4; k16++) {
                int kb = k16 * 32;
                uint32_t av[4];
                {
                    int r = wid * 16 + (lane & 15);
                    int cb = kb + ((lane & 16) ? 16 : 0);
                    uint32_t so = sw128((uint32_t)(r * 128 + cb));
                    ldsm4(av, sb + so);
                }
#pragma unroll
                for (int bt = 0; bt < NT / 2; bt++) {
                    int n = bt * 16 + (lane & 7) + ((lane & 16) ? 8 : 0);
                    int cb = kb + ((lane & 8) ? 16 : 0);
                    uint32_t so = sw128((uint32_t)(n * 128 + cb));
                    uint32_t bv[4];
                    ldsm4(bv, sb + so);
#pragma unroll
                    for (int h2 = 0; h2 < 2; h2++) {
                        int nt = bt * 2 + h2;
                        mma_h(acc[nt], av, &bv[h2 * 2]);
                    }
                }
            }
        }
        __syncthreads();
    }
    if (wid < MW) {
        int mrow = wid * 16 + (lane >> 2);
#pragma unroll
        for (int nt = 0; nt < NT; nt++) {
            int c = nt * 8 + (lane & 3) * 2;
            atomicAdd(&G[mrow * D + c], acc[nt][0]);
            atomicAdd(&G[mrow * D + c + 1], acc[nt][1]);
            atomicAdd(&G[(mrow + 8) * D + c], acc[nt][2]);
            atomicAdd(&G[(mrow + 8) * D + c + 1], acc[nt][3]);
        }
    }
    atomicAdd(&cs[f4 * 4 + 0], cs0);
    atomicAdd(&cs[f4 * 4 + 1], cs1);
    atomicAdd(&cs[f4 * 4 + 2], cs2);
    atomicAdd(&cs[f4 * 4 + 3], cs3);
}

// ---------------- correlation metric finalize (single block) ----------------
template <int D>
__global__ void k_finalize(const float* __restrict__ G,
                           const float* __restrict__ cs,
                           float* __restrict__ dst) {
    __shared__ float sd[D];
    __shared__ float red[256];
    int tid = threadIdx.x;
    const float invN = 1.0f / (float)NNODES;
    if (tid < D) {
        float cjj = G[tid * D + tid] - cs[tid] * cs[tid] * invN;
        sd[tid] = sqrtf(fmaxf(cjj, 1e-12f));
    }
    __syncthreads();
    float sum = 0.f;
    for (int idx = tid; idx < D * D; idx += 256) {
        int j = idx / D, k = idx % D;
        if (k > j) {
            float cov = G[idx] - cs[j] * cs[k] * invN;
            sum += fabsf(cov / (sd[j] * sd[k]));
        }
    }
    red[tid] = sum;
    __syncthreads();
    for (int off = 128; off > 0; off >>= 1) {
        if (tid < off) red[tid] += red[tid + off];
        __syncthreads();
    }
    if (tid == 0) *dst = red[0] / (float)(D * (D - 1) / 2);
}

// ---------------- launch ----------------
extern "C" void kernel_launch(void* const* d_in, const int* in_sizes, int n_in,
                              void* d_out, int out_size) {
    const float* x  = (const float*)d_in[0];
    const int*   ei = (const int*)d_in[1];
    const float* W0 = (const float*)d_in[2];
    const float* W1 = (const float*)d_in[3];
    const float* W2 = (const float*)d_in[4];
    const float* W3 = (const float*)d_in[5];
    float* out = (float*)d_out;

    __half *tmp, *hf, *pfh;
    cudaGetSymbolAddress((void**)&tmp, g_tmp);
    cudaGetSymbolAddress((void**)&hf, g_hf);
    cudaGetSymbolAddress((void**)&pfh, g_pf);
    __half *w0h, *w0l, *w1h, *w1l, *w2h, *w2l, *w3h, *w3l;
    cudaGetSymbolAddress((void**)&w0h, g_w0h); cudaGetSymbolAddress((void**)&w0l, g_w0l);
    cudaGetSymbolAddress((void**)&w1h, g_w1h); cudaGetSymbolAddress((void**)&w1l, g_w1l);
    cudaGetSymbolAddress((void**)&w2h, g_w2h); cudaGetSymbolAddress((void**)&w2l, g_w2l);
    cudaGetSymbolAddress((void**)&w3h, g_w3h); cudaGetSymbolAddress((void**)&w3l, g_w3l);
    int *cntp, *curp;
    float *Gp, *csp, *G2p, *cs2p;
    cudaGetSymbolAddress((void**)&cntp, g_cnt);
    cudaGetSymbolAddress((void**)&curp, g_cursor);
    cudaGetSymbolAddress((void**)&Gp, g_G);
    cudaGetSymbolAddress((void**)&csp, g_csum);
    cudaGetSymbolAddress((void**)&G2p, g_G2);
    cudaGetSymbolAddress((void**)&cs2p, g_csum2);

    const int SM_BIG = 2 * 128 * 128 + 4 * HID * 128;   // 98304
    const int SM_SML = 2 * 128 * 128 + 4 * COUT * 128;  // 65536
    cudaFuncSetAttribute((const void*)k_tgemm512<FIN, HID, true, 2>,
                         cudaFuncAttributeMaxDynamicSharedMemorySize, SM_BIG);
    cudaFuncSetAttribute((const void*)k_tgemm512<HID, HID, false, 2>,
                         cudaFuncAttributeMaxDynamicSharedMemorySize, SM_BIG);
    cudaFuncSetAttribute((const void*)k_tgemm512<HID, COUT, false, 2>,
                         cudaFuncAttributeMaxDynamicSharedMemorySize, SM_SML);

    // side stream + events for fork/join inside graph capture (leaked, bounded)
    cudaStream_t s1;
    cudaStreamCreateWithFlags(&s1, cudaStreamNonBlocking);
    cudaEvent_t eFork1, ePre, eFork2, eCorr;
    cudaEventCreateWithFlags(&eFork1, cudaEventDisableTiming);
    cudaEventCreateWithFlags(&ePre,  cudaEventDisableTiming);
    cudaEventCreateWithFlags(&eFork2, cudaEventDisableTiming);
    cudaEventCreateWithFlags(&eCorr, cudaEventDisableTiming);

    const int TB = 256;
    const int nbE = (NEDGES + TB - 1) / TB;
    const int nbM = (NNODES + 127) / 128;
    const int nbA = (NNODES + 7) / 8;
    const int P3N = 2 * HID * HID + HID * COUT;

    // ---- fork: preprocessing on s1, L0 GEMM path on capture stream ----
    cudaEventRecord(eFork1, 0);
    cudaStreamWaitEvent(s1, eFork1, 0);

    // zero final-gram buffers early (tiny, off critical path)
    cudaMemsetAsync(G2p, 0, COUT * COUT * sizeof(float), 0);
    cudaMemsetAsync(cs2p, 0, COUT * sizeof(float), 0);
    k_prepW<FIN, HID><<<(FIN * HID + TB - 1) / TB, TB>>>(W0, w0h, w0l);
    cudaMemsetAsync(cntp, 0, NNODES * sizeof(int), s1);
    cudaMemsetAsync(curp, 0, NNODES * sizeof(int), s1);
    k_count<<<nbE, TB, 0, s1>>>(ei);
    k_tgemm512<FIN, HID, true, 2><<<nbM, 512, SM_BIG>>>(x, nullptr,
                                                        w0h, w0l, tmp);
    k_scan1<<<SCAN_NB, SCAN_TPB, 0, s1>>>();
    k_scan2<<<1, 64, 0, s1>>>();
    k_scan3<<<SCAN_NB, SCAN_TPB, 0, s1>>>();
    k_fill<<<nbE, TB, 0, s1>>>(ei);
    k_prepW3x<<<(P3N + TB - 1) / TB, TB, 0, s1>>>(W1, W2, W3);
    cudaEventRecord(ePre, s1);
    cudaStreamWaitEvent(0, ePre, 0);

    // layer 0 aggregation -> relu'd fp16 h0
    k_agg128s<false><<<nbA, TB>>>(tmp, hf, pfh);
    // layer 1
    k_tgemm512<HID, HID, false, 2><<<nbM, 512, SM_BIG>>>(nullptr, hf, w1h, w1l, tmp);
    k_agg128s<false><<<nbA, TB>>>(tmp, hf, pfh);
    // layer 2 (pre-relu h2 kept as fp16 for corr_2)
    k_tgemm512<HID, HID, false, 2><<<nbM, 512, SM_BIG>>>(nullptr, hf, w2h, w2l, tmp);
    k_agg128s<true><<<nbA, TB>>>(tmp, hf, pfh);

    // ---- fork: corr_2 metric (s1, uses g_G) concurrent with layer-3 (s0) ----
    cudaEventRecord(eFork2, 0);
    cudaStreamWaitEvent(s1, eFork2, 0);
    cudaMemsetAsync(Gp, 0, HID * HID * sizeof(float), s1);
    cudaMemsetAsync(csp, 0, HID * sizeof(float), s1);
    k_gram_h<HID><<<296, 256, 0, s1>>>(pfh, Gp, csp);
    k_finalize<HID><<<1, 256, 0, s1>>>(Gp, csp, out + NNODES * COUT);
    cudaEventRecord(eCorr, s1);

    // layer 3: relu(h2) @ W3 -> agg into d_out (+fp16 copy into dead hf)
    k_tgemm512<HID, COUT, false, 2><<<nbM, 512, SM_SML>>>(nullptr, hf, w3h, w3l, tmp);
    k_agg64h<<<nbA, TB>>>(tmp, out, hf);

    // final corr on h3 (uses independent g_G2 — no wait on corr_2)
    k_gram_h<COUT><<<296, 256>>>(hf, G2p, cs2p);
    k_finalize<COUT><<<1, 256>>>(G2p, cs2p, out + NNODES * COUT + 1);

    // join s1 back into the capture stream (required for valid capture)
    cudaStreamWaitEvent(0, eCorr, 0);
}